// round 2
// baseline (speedup 1.0000x reference)
#include <cuda_runtime.h>
#include <cuda_bf16.h>
#include <math.h>

#define BSZ 8
#define CH 256
#define HH 64
#define WW 64
#define NN 4096          // HH*WW
#define GH 16
#define NG 256           // GH*GH
#define M_FINE (BSZ*NN)  // 32768
#define M_GLOB (BSZ*NG)  // 2048
#define NCHUNK 64
#define NCHUNK_G 8

// ---------------- scratch (device globals; no allocation allowed) ----------------
__device__ float d_SEQ [M_FINE*CH];
__device__ float d_U   [M_FINE*CH];
__device__ float d_GA  [M_FINE*CH];
__device__ float d_GB  [M_FINE*CH];
__device__ float d_GO  [M_FINE*CH];
__device__ float d_YF  [M_FINE*CH];
__device__ float d_YB  [M_FINE*CH];
__device__ float d_Y   [M_FINE*CH];
__device__ float d_YG  [M_FINE*CH];
__device__ float d_T0  [M_FINE*CH];

__device__ float d_PF  [NN*CH];
__device__ float d_PG  [NG*CH];
__device__ float d_XG  [BSZ*CH*NG];
__device__ float d_SEQG[M_GLOB*CH];
__device__ float d_UG  [M_GLOB*CH];
__device__ float d_AG  [M_GLOB*CH];
__device__ float d_BG  [M_GLOB*CH];
__device__ float d_OG  [M_GLOB*CH];
__device__ float d_YGS [M_GLOB*CH];
__device__ float d_YGB [M_GLOB*CH];

__device__ float d_PART[BSZ*32*CH];
__device__ float d_CBAR[BSZ*CH];
__device__ float d_GBF [BSZ*CH];
__device__ float d_GBW [BSZ*CH];
__device__ float d_GBO [BSZ*CH];

__device__ float d_AF [BSZ*NCHUNK*CH];
__device__ float d_BF [BSZ*NCHUNK*CH];
__device__ float d_ABc[BSZ*NCHUNK*CH];
__device__ float d_BBc[BSZ*NCHUNK*CH];
__device__ float d_SF [BSZ*NCHUNK*CH];
__device__ float d_SB [BSZ*NCHUNK*CH];

// ---------------- kernels ----------------

// in[b][CC][NR] -> out[b][NR][CC]
__global__ void k_transpose(const float* __restrict__ in, float* __restrict__ out,
                            int CC, int NR) {
    __shared__ float tile[32][33];
    int b = blockIdx.z;
    int n0 = blockIdx.x * 32, c0 = blockIdx.y * 32;
    const float* ip = in + (size_t)b * CC * NR;
    float* op = out + (size_t)b * CC * NR;
    for (int i = threadIdx.y; i < 32; i += 8)
        tile[i][threadIdx.x] = ip[(size_t)(c0 + i) * NR + n0 + threadIdx.x];
    __syncthreads();
    for (int i = threadIdx.y; i < 32; i += 8)
        op[(size_t)(n0 + i) * CC + c0 + threadIdx.x] = tile[threadIdx.x][i];
}

// jax.image.resize linear taps (antialias=True, translation=0, renormalized at edges)
__device__ __forceinline__ int resize_taps(int i, int IS, int OS, int* jj, float* ww) {
    float inv = (float)IS / (float)OS;
    float dil = inv > 1.f ? inv : 1.f;
    float s = (i + 0.5f) * inv - 0.5f;
    int lo = (int)floorf(s - dil);
    int hi = (int)ceilf(s + dil);
    int n = 0; float tot = 0.f;
    for (int j = lo; j <= hi; j++) {
        if (j < 0 || j >= IS) continue;
        float w = 1.f - fabsf(s - (float)j) / dil;
        if (w <= 0.f) continue;
        jj[n] = j; ww[n] = w; tot += w; n++;
    }
    float r = 1.f / tot;
    for (int t = 0; t < n; t++) ww[t] *= r;
    return n;
}

// pos[CH][32][32] -> out[OH*OW][CH]
__global__ void k_pos_embed(const float* __restrict__ pos, float* __restrict__ out,
                            int OH, int OW) {
    int c = threadIdx.x;
    int n = blockIdx.x;
    int h = n / OW, w = n % OW;
    int jy[8], jx[8]; float wy[8], wx[8];
    int ny = resize_taps(h, 32, OH, jy, wy);
    int nx = resize_taps(w, 32, OW, jx, wx);
    float acc = 0.f;
    for (int a = 0; a < ny; a++)
        for (int b2 = 0; b2 < nx; b2++)
            acc += wy[a] * wx[b2] * pos[c * 1024 + jy[a] * 32 + jx[b2]];
    out[(size_t)n * CH + c] = acc;
}

__global__ void k_add_pos(float* __restrict__ u, const float* __restrict__ pf,
                          int M, int rows) {
    int i = blockIdx.x * blockDim.x + threadIdx.x;
    if (i < M * CH) {
        int m = i / CH; int c = i - m * CH;
        u[i] += pf[(size_t)(m % rows) * CH + c];
    }
}

// partial column sums: u[b][rowsTotal][CH] -> part[b][nch][CH]
__global__ void k_colsum(const float* __restrict__ u, float* __restrict__ part,
                         int rowsTotal, int rowsPerBlock, int nch) {
    int b = blockIdx.y, c = threadIdx.x, chn = blockIdx.x;
    const float* p = u + ((size_t)b * rowsTotal + (size_t)chn * rowsPerBlock) * CH + c;
    float s = 0.f;
    for (int r = 0; r < rowsPerBlock; r++) s += p[(size_t)r * CH];
    part[((size_t)b * nch + chn) * CH + c] = s;
}

__global__ void k_ln_ctx(const float* __restrict__ part, int nch, float invN,
                         const float* __restrict__ g, const float* __restrict__ be,
                         float* __restrict__ cbar) {
    __shared__ float red[256];
    int b = blockIdx.x, c = threadIdx.x;
    float v = 0.f;
    for (int chn = 0; chn < nch; chn++) v += part[((size_t)b * nch + chn) * CH + c];
    v *= invN;
    red[c] = v; __syncthreads();
    for (int s = 128; s > 0; s >>= 1) { if (c < s) red[c] += red[c + s]; __syncthreads(); }
    float m = red[0] / CH; __syncthreads();
    float d = v - m;
    red[c] = d * d; __syncthreads();
    for (int s = 128; s > 0; s >>= 1) { if (c < s) red[c] += red[c + s]; __syncthreads(); }
    float var = red[0] / CH;
    cbar[b * CH + c] = d * rsqrtf(var + 1e-5f) * g[c] + be[c];
}

// out[b][j] = bias[j] + sum_c cbar[b][c] * Wlow[c][j]
__global__ void k_gate_bias(const float* __restrict__ cbar, const float* __restrict__ Wlow,
                            const float* __restrict__ bias, float* __restrict__ out) {
    __shared__ float cs[256];
    int b = blockIdx.x, j = threadIdx.x;
    cs[j] = cbar[b * CH + j];
    __syncthreads();
    float s = bias[j];
    for (int c = 0; c < CH; c++) s += cs[c] * Wlow[c * CH + j];
    out[b * CH + j] = s;
}

// C[M,256] (+)= A[M,256] @ B[256,256] (+bias_n[n]) (+bias_bn[m/rpb][n])
__global__ void __launch_bounds__(256)
k_gemm(const float* __restrict__ A, const float* __restrict__ Bw,
       const float* __restrict__ bias_n, const float* __restrict__ bias_bn,
       float* __restrict__ Cmat, int rowsPerBatch, int accum) {
    __shared__ float As[16][64];
    __shared__ float Bs[16][64];
    int tid = threadIdx.x;
    int tx = tid & 15, ty = tid >> 4;
    int m0 = blockIdx.y * 64, n0 = blockIdx.x * 64;
    float acc[4][4] = {};
    const float* Ap = A + (size_t)m0 * 256;
    for (int k0 = 0; k0 < 256; k0 += 16) {
#pragma unroll
        for (int i = 0; i < 4; i++) {
            int f = tid + i * 256;
            int m = f >> 4, k = f & 15;
            As[k][m] = Ap[(size_t)m * 256 + k0 + k];
        }
#pragma unroll
        for (int i = 0; i < 4; i++) {
            int f = tid + i * 256;
            int k = f >> 6, n = f & 63;
            Bs[k][n] = Bw[(size_t)(k0 + k) * 256 + n0 + n];
        }
        __syncthreads();
#pragma unroll
        for (int k = 0; k < 16; k++) {
            float4 av = *(const float4*)&As[k][ty * 4];
            float4 bv = *(const float4*)&Bs[k][tx * 4];
            float aa[4] = {av.x, av.y, av.z, av.w};
            float bb[4] = {bv.x, bv.y, bv.z, bv.w};
#pragma unroll
            for (int i = 0; i < 4; i++)
#pragma unroll
                for (int j = 0; j < 4; j++) acc[i][j] = fmaf(aa[i], bb[j], acc[i][j]);
        }
        __syncthreads();
    }
#pragma unroll
    for (int i = 0; i < 4; i++) {
        int m = m0 + ty * 4 + i;
        int bb = m / rowsPerBatch;
        int n = n0 + tx * 4;
        float4 v = make_float4(acc[i][0], acc[i][1], acc[i][2], acc[i][3]);
        if (bias_n) {
            v.x += bias_n[n]; v.y += bias_n[n + 1]; v.z += bias_n[n + 2]; v.w += bias_n[n + 3];
        }
        if (bias_bn) {
            const float* bp = bias_bn + bb * 256 + n;
            v.x += bp[0]; v.y += bp[1]; v.z += bp[2]; v.w += bp[3];
        }
        float4* cp = (float4*)(Cmat + (size_t)m * 256 + n);
        if (accum) {
            float4 o = *cp;
            v.x += o.x; v.y += o.y; v.z += o.z; v.w += o.w;
        }
        *cp = v;
    }
}

__device__ __forceinline__ float sigf(float x) { return 1.f / (1.f + expf(-x)); }

// GA=F-logit, GB=W-logit, GO=O-logit -> a, b, o in place
__global__ void k_gates(float* __restrict__ GA, float* __restrict__ GB,
                        float* __restrict__ GO, const float* __restrict__ U, int total) {
    int i = blockIdx.x * blockDim.x + threadIdx.x;
    if (i >= total) return;
    float F = GA[i], Wv = GB[i], Ov = GO[i], u = U[i];
    float a = 1.f / (1.f + expf(F));     // exp(-softplus(F)) == sigmoid(-F)
    float sF = 1.f / (1.f + expf(-F));   // 1 - a
    GA[i] = a;
    GB[i] = sF * sigf(Wv) * u;
    GO[i] = sigf(Ov);
}

__global__ void k_scan_pass1(const float* __restrict__ GA, const float* __restrict__ GB,
                             float* __restrict__ AF, float* __restrict__ BF,
                             float* __restrict__ ABc, float* __restrict__ BBc,
                             int rows, int nchunk) {
    int b = blockIdx.y, chn = blockIdx.x, c = threadIdx.x;
    int L = rows / nchunk;
    size_t base = ((size_t)b * rows + (size_t)chn * L) * CH + c;
    float Af = 1.f, Bf = 0.f;
    for (int i = 0; i < L; i++) {
        float a = GA[base + (size_t)i * CH], bb = GB[base + (size_t)i * CH];
        Af *= a; Bf = a * Bf + bb;
    }
    float Ab = 1.f, Bb = 0.f;
    for (int i = L - 1; i >= 0; i--) {
        float a = GA[base + (size_t)i * CH], bb = GB[base + (size_t)i * CH];
        Ab *= a; Bb = a * Bb + bb;
    }
    size_t co = ((size_t)b * nchunk + chn) * CH + c;
    AF[co] = Af; BF[co] = Bf; ABc[co] = Ab; BBc[co] = Bb;
}

__global__ void k_scan_pass2(const float* __restrict__ AF, const float* __restrict__ BF,
                             const float* __restrict__ ABc, const float* __restrict__ BBc,
                             float* __restrict__ SF, float* __restrict__ SB, int nchunk) {
    int b = blockIdx.x, c = threadIdx.x;
    float s = 0.f;
    for (int chn = 0; chn < nchunk; chn++) {
        size_t o = ((size_t)b * nchunk + chn) * CH + c;
        SF[o] = s; s = AF[o] * s + BF[o];
    }
    float sb = 0.f;
    for (int chn = nchunk - 1; chn >= 0; chn--) {
        size_t o = ((size_t)b * nchunk + chn) * CH + c;
        SB[o] = sb; sb = ABc[o] * sb + BBc[o];
    }
}

__global__ void k_scan_pass3(const float* __restrict__ GA, const float* __restrict__ GB,
                             const float* __restrict__ GO, const float* __restrict__ U,
                             const float* __restrict__ SF, const float* __restrict__ SB,
                             float* __restrict__ YF, float* __restrict__ YB,
                             int rows, int nchunk) {
    int b = blockIdx.y, chn = blockIdx.x, c = threadIdx.x;
    int L = rows / nchunk;
    size_t base = ((size_t)b * rows + (size_t)chn * L) * CH + c;
    size_t co = ((size_t)b * nchunk + chn) * CH + c;
    float s = SF[co];
    for (int i = 0; i < L; i++) {
        size_t o = base + (size_t)i * CH;
        float a = GA[o], bb = GB[o], ov = GO[o], u = U[o];
        s = a * s + bb;
        YF[o] = ov * s + (1.f - ov) * u;
    }
    float sb = SB[co];
    for (int i = L - 1; i >= 0; i--) {
        size_t o = base + (size_t)i * CH;
        float a = GA[o], bb = GB[o], ov = GO[o], u = U[o];
        sb = a * sb + bb;
        YB[o] = ov * sb + (1.f - ov) * u;
    }
}

__global__ void k_combine_rho(const float* __restrict__ T, const float* __restrict__ YF,
                              const float* __restrict__ YB, float* __restrict__ Y, int total) {
    int i = blockIdx.x * blockDim.x + threadIdx.x;
    if (i >= total) return;
    float r = sigf(T[i]);
    Y[i] = r * YF[i] + (1.f - r) * YB[i];
}

__global__ void k_combine_lam(const float* __restrict__ T, const float* __restrict__ Y,
                              const float* __restrict__ YG, float* __restrict__ Z, int total) {
    int i = blockIdx.x * blockDim.x + threadIdx.x;
    if (i >= total) return;
    Z[i] = Y[i] + sigf(T[i]) * YG[i];
}

__global__ void k_combine_eta(const float* __restrict__ T, const float* __restrict__ V,
                              const float* __restrict__ Z, float* __restrict__ Uo, int total) {
    int i = blockIdx.x * blockDim.x + threadIdx.x;
    if (i >= total) return;
    float e = sigf(T[i]);
    Uo[i] = e * V[i] + (1.f - e) * Z[i];
}

// x[b][c][64][64] -> xg[b][c][16][16] (exact 4x4 avg)
__global__ void k_pool(const float* __restrict__ x, float* __restrict__ xg) {
    int i = blockIdx.x * blockDim.x + threadIdx.x;
    if (i >= BSZ * CH * NG) return;
    int gx = i % GH; int gy = (i / GH) % GH; int bc = i / NG;
    const float* p = x + (size_t)bc * NN + (gy * 4) * 64 + gx * 4;
    float s = 0.f;
#pragma unroll
    for (int dy = 0; dy < 4; dy++)
#pragma unroll
        for (int dx = 0; dx < 4; dx++) s += p[dy * 64 + dx];
    xg[i] = s * 0.0625f;
}

// yg[b][256tok][CH] (16x16) -> out[b][4096tok][CH] (64x64), bilinear scale 4, clamped
__global__ void k_upsample(const float* __restrict__ yg, float* __restrict__ out) {
    int c = threadIdx.x;
    int n = blockIdx.x;
    int b = blockIdx.y;
    int h = n >> 6, w = n & 63;
    float sy = (h + 0.5f) * 0.25f - 0.5f;
    float sx = (w + 0.5f) * 0.25f - 0.5f;
    int y0 = (int)floorf(sy); float fy = sy - y0;
    int x0 = (int)floorf(sx); float fx = sx - x0;
    int y0c = min(max(y0, 0), 15), y1c = min(max(y0 + 1, 0), 15);
    int x0c = min(max(x0, 0), 15), x1c = min(max(x0 + 1, 0), 15);
    const float* p = yg + (size_t)b * NG * CH + c;
    float v00 = p[(size_t)(y0c * 16 + x0c) * CH];
    float v01 = p[(size_t)(y0c * 16 + x1c) * CH];
    float v10 = p[(size_t)(y1c * 16 + x0c) * CH];
    float v11 = p[(size_t)(y1c * 16 + x1c) * CH];
    out[((size_t)b * NN + n) * CH + c] =
        (1.f - fy) * ((1.f - fx) * v00 + fx * v01) + fy * ((1.f - fx) * v10 + fx * v11);
}

// depthwise 3x3 SAME: x[b][c][64][64] -> out[b][c][n]
__global__ void k_dwconv(const float* __restrict__ x, const float* __restrict__ wt,
                         const float* __restrict__ bs, float* __restrict__ out) {
    int i = blockIdx.x * blockDim.x + threadIdx.x;
    if (i >= BSZ * CH * NN) return;
    int wp = i & 63;
    int h = (i >> 6) & 63;
    int cc = (i >> 12) & 255;
    const float* xp = x + (size_t)(i - wp - h * 64);
    const float* kp = wt + cc * 9;
    float s = bs[cc];
#pragma unroll
    for (int dy = -1; dy <= 1; dy++) {
        int yy = h + dy; if (yy < 0 || yy >= 64) continue;
#pragma unroll
        for (int dx = -1; dx <= 1; dx++) {
            int xx = wp + dx; if (xx < 0 || xx >= 64) continue;
            s += xp[yy * 64 + xx] * kp[(dy + 1) * 3 + (dx + 1)];
        }
    }
    out[i] = s;
}

// out[b][c][n] = x[b][c][n] + P[b][n][c]
__global__ void k_final(const float* __restrict__ x, const float* __restrict__ P,
                        float* __restrict__ out) {
    __shared__ float tile[32][33];
    int b = blockIdx.z;
    int n0 = blockIdx.x * 32, c0 = blockIdx.y * 32;
    const float* pp = P + (size_t)b * NN * CH;
    for (int i = threadIdx.y; i < 32; i += 8)
        tile[i][threadIdx.x] = pp[(size_t)(n0 + i) * CH + c0 + threadIdx.x];
    __syncthreads();
    const float* xp = x + (size_t)b * CH * NN;
    float* op = out + (size_t)b * CH * NN;
    for (int i = threadIdx.y; i < 32; i += 8)
        op[(size_t)(c0 + i) * NN + n0 + threadIdx.x] =
            xp[(size_t)(c0 + i) * NN + n0 + threadIdx.x] + tile[threadIdx.x][i];
}

// ---------------- host orchestration ----------------
static float* gsym(const void* sym) {
    void* p = nullptr;
    cudaGetSymbolAddress(&p, sym);
    return (float*)p;
}

extern "C" void kernel_launch(void* const* d_in, const int* in_sizes, int n_in,
                              void* d_out, int out_size) {
    const float* x    = (const float*)d_in[0];
    const float* Wt   = (const float*)d_in[1];
    const float* bt   = (const float*)d_in[2];
    const float* posf = (const float*)d_in[3];
    const float* posg = (const float*)d_in[4];
    const float* lng  = (const float*)d_in[5];
    const float* lnb  = (const float*)d_in[6];
    const float* Wf   = (const float*)d_in[7];
    const float* bf   = (const float*)d_in[8];
    const float* Ww_  = (const float*)d_in[9];
    const float* bw   = (const float*)d_in[10];
    const float* Wo   = (const float*)d_in[11];
    const float* bo   = (const float*)d_in[12];
    const float* Wr   = (const float*)d_in[13];
    const float* br   = (const float*)d_in[14];
    const float* Wgi  = (const float*)d_in[15];
    const float* bgi  = (const float*)d_in[16];
    const float* dww  = (const float*)d_in[17];
    const float* dwb  = (const float*)d_in[18];
    const float* Wl   = (const float*)d_in[19];
    const float* bl   = (const float*)d_in[20];
    const float* Wlf  = (const float*)d_in[21];
    const float* blf  = (const float*)d_in[22];
    const float* Wout = (const float*)d_in[23];
    const float* bout = (const float*)d_in[24];
    float* out = (float*)d_out;

    float *SEQ = gsym(d_SEQ), *U = gsym(d_U), *GA = gsym(d_GA), *GB = gsym(d_GB),
          *GO = gsym(d_GO), *YF = gsym(d_YF), *YB = gsym(d_YB), *Y = gsym(d_Y),
          *YG = gsym(d_YG), *T0 = gsym(d_T0);
    float *PF = gsym(d_PF), *PG = gsym(d_PG), *XG = gsym(d_XG), *SEQG = gsym(d_SEQG),
          *UG = gsym(d_UG), *AG = gsym(d_AG), *BG = gsym(d_BG), *OG = gsym(d_OG),
          *YGS = gsym(d_YGS), *YGB = gsym(d_YGB);
    float *PART = gsym(d_PART), *CBAR = gsym(d_CBAR), *GBF = gsym(d_GBF),
          *GBW = gsym(d_GBW), *GBO = gsym(d_GBO);
    float *AF = gsym(d_AF), *BF = gsym(d_BF), *ABc = gsym(d_ABc), *BBc = gsym(d_BBc),
          *SF = gsym(d_SF), *SB = gsym(d_SB);

    const int TF = M_FINE * CH;   // 8388608
    const int TG = M_GLOB * CH;   // 524288
    dim3 tb(32, 8);
    int eb = (TF + 255) / 256;
    int ebg = (TG + 255) / 256;

    // ---- fine sequence ----
    k_transpose<<<dim3(NN / 32, CH / 32, BSZ), tb>>>(x, SEQ, CH, NN);
    k_pos_embed<<<NN, 256>>>(posf, PF, HH, WW);
    k_pos_embed<<<NG, 256>>>(posg, PG, GH, GH);

    k_gemm<<<dim3(4, M_FINE / 64), 256>>>(SEQ, Wt, bt, nullptr, U, NN, 0);
    k_add_pos<<<eb, 256>>>(U, PF, M_FINE, NN);

    // context + gate biases (z = [u, cbar] split)
    k_colsum<<<dim3(32, BSZ), 256>>>(U, PART, NN, 128, 32);
    k_ln_ctx<<<BSZ, 256>>>(PART, 32, 1.f / NN, lng, lnb, CBAR);
    k_gate_bias<<<BSZ, 256>>>(CBAR, Wf + 256 * 256, bf, GBF);
    k_gate_bias<<<BSZ, 256>>>(CBAR, Ww_ + 256 * 256, bw, GBW);
    k_gate_bias<<<BSZ, 256>>>(CBAR, Wo + 256 * 256, bo, GBO);

    // gates (shared between fwd & bwd branches)
    k_gemm<<<dim3(4, M_FINE / 64), 256>>>(U, Wf, nullptr, GBF, GA, NN, 0);
    k_gemm<<<dim3(4, M_FINE / 64), 256>>>(U, Ww_, nullptr, GBW, GB, NN, 0);
    k_gemm<<<dim3(4, M_FINE / 64), 256>>>(U, Wo, nullptr, GBO, GO, NN, 0);
    k_gates<<<eb, 256>>>(GA, GB, GO, U, TF);

    // bidirectional chunked scan
    k_scan_pass1<<<dim3(NCHUNK, BSZ), 256>>>(GA, GB, AF, BF, ABc, BBc, NN, NCHUNK);
    k_scan_pass2<<<BSZ, 256>>>(AF, BF, ABc, BBc, SF, SB, NCHUNK);
    k_scan_pass3<<<dim3(NCHUNK, BSZ), 256>>>(GA, GB, GO, U, SF, SB, YF, YB, NN, NCHUNK);

    // rho mix
    k_gemm<<<dim3(4, M_FINE / 64), 256>>>(U, Wr, br, nullptr, T0, NN, 0);
    k_gemm<<<dim3(4, M_FINE / 64), 256>>>(YF, Wr + 256 * 256, nullptr, nullptr, T0, NN, 1);
    k_gemm<<<dim3(4, M_FINE / 64), 256>>>(YB, Wr + 512 * 256, nullptr, nullptr, T0, NN, 1);
    k_combine_rho<<<eb, 256>>>(T0, YF, YB, Y, TF);

    // ---- global branch ----
    k_pool<<<(BSZ * CH * NG + 255) / 256, 256>>>(x, XG);
    k_transpose<<<dim3(NG / 32, CH / 32, BSZ), tb>>>(XG, SEQG, CH, NG);
    k_gemm<<<dim3(4, M_GLOB / 64), 256>>>(SEQG, Wt, bt, nullptr, UG, NG, 0);
    k_add_pos<<<ebg, 256>>>(UG, PG, M_GLOB, NG);

    k_colsum<<<dim3(2, BSZ), 256>>>(UG, PART, NG, 128, 2);
    k_ln_ctx<<<BSZ, 256>>>(PART, 2, 1.f / NG, lng, lnb, CBAR);
    k_gate_bias<<<BSZ, 256>>>(CBAR, Wf + 256 * 256, bf, GBF);
    k_gate_bias<<<BSZ, 256>>>(CBAR, Ww_ + 256 * 256, bw, GBW);
    k_gate_bias<<<BSZ, 256>>>(CBAR, Wo + 256 * 256, bo, GBO);

    k_gemm<<<dim3(4, M_GLOB / 64), 256>>>(UG, Wf, nullptr, GBF, AG, NG, 0);
    k_gemm<<<dim3(4, M_GLOB / 64), 256>>>(UG, Ww_, nullptr, GBW, BG, NG, 0);
    k_gemm<<<dim3(4, M_GLOB / 64), 256>>>(UG, Wo, nullptr, GBO, OG, NG, 0);
    k_gates<<<ebg, 256>>>(AG, BG, OG, UG, TG);

    k_scan_pass1<<<dim3(NCHUNK_G, BSZ), 256>>>(AG, BG, AF, BF, ABc, BBc, NG, NCHUNK_G);
    k_scan_pass2<<<BSZ, 256>>>(AF, BF, ABc, BBc, SF, SB, NCHUNK_G);
    k_scan_pass3<<<dim3(NCHUNK_G, BSZ), 256>>>(AG, BG, OG, UG, SF, SB, YGS, YGB, NG, NCHUNK_G);

    k_upsample<<<dim3(NN, BSZ), 256>>>(YGS, YG);

    // lam mix: z = y + sig(.)*y_g  (write Z into YF, now free)
    k_gemm<<<dim3(4, M_FINE / 64), 256>>>(Y, Wgi, bgi, nullptr, T0, NN, 0);
    k_gemm<<<dim3(4, M_FINE / 64), 256>>>(YG, Wgi + 256 * 256, nullptr, nullptr, T0, NN, 1);
    k_gemm<<<dim3(4, M_FINE / 64), 256>>>(U, Wgi + 512 * 256, nullptr, nullptr, T0, NN, 1);
    k_combine_lam<<<eb, 256>>>(T0, Y, YG, YF, TF);

    // ---- local depthwise conv branch ----
    k_dwconv<<<(BSZ * CH * NN + 255) / 256, 256>>>(x, dww, dwb, SEQ);      // SEQ = conv map
    k_transpose<<<dim3(NN / 32, CH / 32, BSZ), tb>>>(SEQ, YB, CH, NN);     // YB = conv seq
    k_gemm<<<dim3(4, M_FINE / 64), 256>>>(YB, Wl, bl, nullptr, GA, NN, 0); // GA = v

    k_gemm<<<dim3(4, M_FINE / 64), 256>>>(GA, Wlf, blf, nullptr, T0, NN, 0);
    k_gemm<<<dim3(4, M_FINE / 64), 256>>>(YF, Wlf + 256 * 256, nullptr, nullptr, T0, NN, 1);
    k_combine_eta<<<eb, 256>>>(T0, GA, YF, GB, TF);                        // GB = u_out

    // output projection + residual
    k_gemm<<<dim3(4, M_FINE / 64), 256>>>(GB, Wout, bout, nullptr, T0, NN, 0);
    k_final<<<dim3(NN / 32, CH / 32, BSZ), tb>>>(x, T0, out);
}

// round 5
// speedup vs baseline: 2.6051x; 2.6051x over previous
#include <cuda_runtime.h>
#include <cuda_bf16.h>
#include <math.h>
#include <stdint.h>

#define BSZ 8
#define CH 256
#define HH 64
#define WW 64
#define NN 4096          // HH*WW
#define GH 16
#define NG 256           // GH*GH
#define M_FINE (BSZ*NN)  // 32768
#define M_GLOB (BSZ*NG)  // 2048
#define NCHUNK 64
#define NCHUNK_G 8

// ---------------- scratch (device globals; no allocation allowed) ----------------
__device__ float d_SEQ [M_FINE*CH];
__device__ float d_U   [M_FINE*CH];
__device__ float d_GA  [M_FINE*CH];
__device__ float d_GB  [M_FINE*CH];
__device__ float d_GO  [M_FINE*CH];
__device__ float d_YF  [M_FINE*CH];
__device__ float d_YB  [M_FINE*CH];
__device__ float d_Y   [M_FINE*CH];
__device__ float d_YG  [M_FINE*CH];
__device__ float d_T0  [M_FINE*CH];

__device__ float d_PF  [NN*CH];
__device__ float d_PG  [NG*CH];
__device__ float d_XG  [BSZ*CH*NG];
__device__ float d_SEQG[M_GLOB*CH];
__device__ float d_UG  [M_GLOB*CH];
__device__ float d_AG  [M_GLOB*CH];
__device__ float d_BG  [M_GLOB*CH];
__device__ float d_OG  [M_GLOB*CH];
__device__ float d_YGS [M_GLOB*CH];
__device__ float d_YGB [M_GLOB*CH];

__device__ float d_PART[BSZ*32*CH];
__device__ float d_CBAR[BSZ*CH];
__device__ float d_GBF [BSZ*CH];
__device__ float d_GBW [BSZ*CH];
__device__ float d_GBO [BSZ*CH];

__device__ float d_AF [BSZ*NCHUNK*CH];
__device__ float d_BF [BSZ*NCHUNK*CH];
__device__ float d_ABc[BSZ*NCHUNK*CH];
__device__ float d_BBc[BSZ*NCHUNK*CH];
__device__ float d_SF [BSZ*NCHUNK*CH];
__device__ float d_SB [BSZ*NCHUNK*CH];

// ---------------- HMMA helpers ----------------
__device__ __forceinline__ uint32_t smem_u32(const void* p) {
    uint32_t a;
    asm("{ .reg .u64 t; cvta.to.shared.u64 t, %1; cvt.u32.u64 %0, t; }" : "=r"(a) : "l"(p));
    return a;
}
#define LDSM_X4(r0, r1, r2, r3, addr) \
    asm volatile("ldmatrix.sync.aligned.m8n8.x4.shared.b16 {%0,%1,%2,%3}, [%4];" \
                 : "=r"(r0), "=r"(r1), "=r"(r2), "=r"(r3) : "r"(addr))
#define LDSM_X4_T(r0, r1, r2, r3, addr) \
    asm volatile("ldmatrix.sync.aligned.m8n8.x4.trans.shared.b16 {%0,%1,%2,%3}, [%4];" \
                 : "=r"(r0), "=r"(r1), "=r"(r2), "=r"(r3) : "r"(addr))
#define MMA16816(d, a, b0, b1) \
    asm volatile("mma.sync.aligned.m16n8k16.row.col.f32.bf16.bf16.f32 " \
                 "{%0,%1,%2,%3}, {%4,%5,%6,%7}, {%8,%9}, {%0,%1,%2,%3};" \
                 : "+f"((d)[0]), "+f"((d)[1]), "+f"((d)[2]), "+f"((d)[3]) \
                 : "r"((a)[0]), "r"((a)[1]), "r"((a)[2]), "r"((a)[3]), "r"(b0), "r"(b1))

__device__ __forceinline__ uint4 cvt8_bf16(float4 x, float4 y) {
    __nv_bfloat162 p0 = __floats2bfloat162_rn(x.x, x.y);
    __nv_bfloat162 p1 = __floats2bfloat162_rn(x.z, x.w);
    __nv_bfloat162 p2 = __floats2bfloat162_rn(y.x, y.y);
    __nv_bfloat162 p3 = __floats2bfloat162_rn(y.z, y.w);
    return make_uint4(*(uint32_t*)&p0, *(uint32_t*)&p1, *(uint32_t*)&p2, *(uint32_t*)&p3);
}

// ---------------- HMMA GEMM: C[M,256] (+)= A[M,256] @ W[256,256] ----------------
// grid = (2, M/128), 256 threads. CTA tile 128x128, BK=32, double-buffered.
__global__ void __launch_bounds__(256, 1)
k_gemm_mma(const float* __restrict__ A, const float* __restrict__ Bw,
           const float* __restrict__ bias_n, const float* __restrict__ bias_bn,
           float* __restrict__ Cmat, int rowsPerBatch, int accum) {
    // layout: per buffer 16KB: A 8KB (128 rows x 64B) at +0, B 8KB (32 rows x 256B) at +8192.
    __shared__ __align__(16) uint8_t sm[32768];
    uint32_t smBase = smem_u32(sm);

    int tid = threadIdx.x;
    int wid = tid >> 5, lane = tid & 31;
    int wm = wid >> 2, wn = wid & 3;            // warp grid 2 x 4
    int m0 = blockIdx.y * 128, n0 = blockIdx.x * 128;

    // global load indices (per thread: 2 A units + 2 B units; unit = 8 floats -> 16B bf16)
    int mA = tid >> 2, cA = tid & 3;            // A: rows mA, mA+64; chunk cA
    int kB = tid >> 4, cB = tid & 15;           // B: rows kB, kB+16; chunk cB
    const float* Ag = A + (size_t)m0 * 256 + (size_t)mA * 256 + cA * 8;
    const float* Bg = Bw + (size_t)kB * 256 + n0 + cB * 8;

    // SMEM byte offsets (relative to sm) — swizzled
    uint32_t offA0 = (uint32_t)(mA * 64 + ((cA ^ ((mA >> 1) & 3)) << 4));
    uint32_t offA1 = offA0 + 64u * 64u;         // row+64: same swizzle term (64>>1 ≡ 0 mod 4)
    uint32_t offB0 = 8192u + (uint32_t)(kB * 256 + ((cB ^ (kB & 7)) << 4));
    uint32_t offB1 = offB0 + 16u * 256u;        // row+16: same swizzle term (16 ≡ 0 mod 8)

    // ldmatrix lane address components
    int lr = lane & 7, lh = (lane >> 3) & 1, lq = lane >> 4;
    int arow_base = wm * 64 + lh * 8 + lr;      // + mi*16
    int brow_base = lh * 8 + lr;                // + k16*16

    float acc[4][4][4] = {};
    float4 ra[4], rb[4];

    // prefetch step 0
    {
        const float4* a0 = (const float4*)(Ag);
        const float4* a1 = (const float4*)(Ag + 64 * 256);
        ra[0] = a0[0]; ra[1] = a0[1]; ra[2] = a1[0]; ra[3] = a1[1];
        const float4* b0 = (const float4*)(Bg);
        const float4* b1 = (const float4*)(Bg + 16 * 256);
        rb[0] = b0[0]; rb[1] = b0[1]; rb[2] = b1[0]; rb[3] = b1[1];
    }

    uint32_t bo = 0;
#pragma unroll 1
    for (int s = 0; s < 8; s++) {
        *(uint4*)(sm + bo + offA0) = cvt8_bf16(ra[0], ra[1]);
        *(uint4*)(sm + bo + offA1) = cvt8_bf16(ra[2], ra[3]);
        *(uint4*)(sm + bo + offB0) = cvt8_bf16(rb[0], rb[1]);
        *(uint4*)(sm + bo + offB1) = cvt8_bf16(rb[2], rb[3]);
        __syncthreads();
        if (s < 7) {
            int k0 = (s + 1) * 32;
            const float4* a0 = (const float4*)(Ag + k0);
            const float4* a1 = (const float4*)(Ag + 64 * 256 + k0);
            ra[0] = a0[0]; ra[1] = a0[1]; ra[2] = a1[0]; ra[3] = a1[1];
            const float4* b0 = (const float4*)(Bg + (size_t)k0 * 256);
            const float4* b1 = (const float4*)(Bg + (size_t)(k0 + 16) * 256);
            rb[0] = b0[0]; rb[1] = b0[1]; rb[2] = b1[0]; rb[3] = b1[1];
        }
        // compute on current buffer
#pragma unroll
        for (int k16 = 0; k16 < 2; k16++) {
            uint32_t afr[4][4];
#pragma unroll
            for (int mi = 0; mi < 4; mi++) {
                int row = arow_base + mi * 16;
                int c = k16 * 2 + lq;
                uint32_t addr = smBase + bo + (uint32_t)(row * 64 + ((c ^ ((row >> 1) & 3)) << 4));
                LDSM_X4(afr[mi][0], afr[mi][1], afr[mi][2], afr[mi][3], addr);
            }
            uint32_t bfr[2][4];
#pragma unroll
            for (int g = 0; g < 2; g++) {
                int rowk = k16 * 16 + brow_base;
                int c = wn * 4 + g * 2 + lq;
                uint32_t addr = smBase + bo + 8192u + (uint32_t)(rowk * 256 + ((c ^ (rowk & 7)) << 4));
                LDSM_X4_T(bfr[g][0], bfr[g][1], bfr[g][2], bfr[g][3], addr);
            }
#pragma unroll
            for (int mi = 0; mi < 4; mi++)
#pragma unroll
                for (int j = 0; j < 4; j++)
                    MMA16816(acc[mi][j], afr[mi], bfr[j >> 1][(j & 1) * 2], bfr[j >> 1][(j & 1) * 2 + 1]);
        }
        bo ^= 16384u;
        if (s < 7) __syncthreads();
    }

    // epilogue
    int gid = lane >> 2, tig = lane & 3;
    int batch = m0 / rowsPerBatch;
#pragma unroll
    for (int mi = 0; mi < 4; mi++) {
#pragma unroll
        for (int j = 0; j < 4; j++) {
            int row = m0 + wm * 64 + mi * 16 + gid;
            int col = n0 + wn * 32 + j * 8 + tig * 2;
            float b0 = 0.f, b1 = 0.f;
            if (bias_n) { b0 += bias_n[col]; b1 += bias_n[col + 1]; }
            if (bias_bn) { b0 += bias_bn[batch * 256 + col]; b1 += bias_bn[batch * 256 + col + 1]; }
            float* p0 = Cmat + (size_t)row * 256 + col;
            float* p1 = Cmat + (size_t)(row + 8) * 256 + col;
            float v0 = acc[mi][j][0] + b0, v1 = acc[mi][j][1] + b1;
            float v2 = acc[mi][j][2] + b0, v3 = acc[mi][j][3] + b1;
            if (accum) { v0 += p0[0]; v1 += p0[1]; v2 += p1[0]; v3 += p1[1]; }
            p0[0] = v0; p0[1] = v1;
            p1[0] = v2; p1[1] = v3;
        }
    }
}

// ---------------- other kernels (unchanged from R2 passing version) ----------------

__global__ void k_transpose(const float* __restrict__ in, float* __restrict__ out,
                            int CC, int NR) {
    __shared__ float tile[32][33];
    int b = blockIdx.z;
    int n0 = blockIdx.x * 32, c0 = blockIdx.y * 32;
    const float* ip = in + (size_t)b * CC * NR;
    float* op = out + (size_t)b * CC * NR;
    for (int i = threadIdx.y; i < 32; i += 8)
        tile[i][threadIdx.x] = ip[(size_t)(c0 + i) * NR + n0 + threadIdx.x];
    __syncthreads();
    for (int i = threadIdx.y; i < 32; i += 8)
        op[(size_t)(n0 + i) * CC + c0 + threadIdx.x] = tile[threadIdx.x][i];
}

__device__ __forceinline__ int resize_taps(int i, int IS, int OS, int* jj, float* ww) {
    float inv = (float)IS / (float)OS;
    float dil = inv > 1.f ? inv : 1.f;
    float s = (i + 0.5f) * inv - 0.5f;
    int lo = (int)floorf(s - dil);
    int hi = (int)ceilf(s + dil);
    int n = 0; float tot = 0.f;
    for (int j = lo; j <= hi; j++) {
        if (j < 0 || j >= IS) continue;
        float w = 1.f - fabsf(s - (float)j) / dil;
        if (w <= 0.f) continue;
        jj[n] = j; ww[n] = w; tot += w; n++;
    }
    float r = 1.f / tot;
    for (int t = 0; t < n; t++) ww[t] *= r;
    return n;
}

__global__ void k_pos_embed(const float* __restrict__ pos, float* __restrict__ out,
                            int OH, int OW) {
    int c = threadIdx.x;
    int n = blockIdx.x;
    int h = n / OW, w = n % OW;
    int jy[8], jx[8]; float wy[8], wx[8];
    int ny = resize_taps(h, 32, OH, jy, wy);
    int nx = resize_taps(w, 32, OW, jx, wx);
    float acc = 0.f;
    for (int a = 0; a < ny; a++)
        for (int b2 = 0; b2 < nx; b2++)
            acc += wy[a] * wx[b2] * pos[c * 1024 + jy[a] * 32 + jx[b2]];
    out[(size_t)n * CH + c] = acc;
}

__global__ void k_add_pos(float* __restrict__ u, const float* __restrict__ pf,
                          int M, int rows) {
    int i = blockIdx.x * blockDim.x + threadIdx.x;
    if (i < M * CH) {
        int m = i / CH; int c = i - m * CH;
        u[i] += pf[(size_t)(m % rows) * CH + c];
    }
}

__global__ void k_colsum(const float* __restrict__ u, float* __restrict__ part,
                         int rowsTotal, int rowsPerBlock, int nch) {
    int b = blockIdx.y, c = threadIdx.x, chn = blockIdx.x;
    const float* p = u + ((size_t)b * rowsTotal + (size_t)chn * rowsPerBlock) * CH + c;
    float s = 0.f;
    for (int r = 0; r < rowsPerBlock; r++) s += p[(size_t)r * CH];
    part[((size_t)b * nch + chn) * CH + c] = s;
}

__global__ void k_ln_ctx(const float* __restrict__ part, int nch, float invN,
                         const float* __restrict__ g, const float* __restrict__ be,
                         float* __restrict__ cbar) {
    __shared__ float red[256];
    int b = blockIdx.x, c = threadIdx.x;
    float v = 0.f;
    for (int chn = 0; chn < nch; chn++) v += part[((size_t)b * nch + chn) * CH + c];
    v *= invN;
    red[c] = v; __syncthreads();
    for (int s = 128; s > 0; s >>= 1) { if (c < s) red[c] += red[c + s]; __syncthreads(); }
    float m = red[0] / CH; __syncthreads();
    float d = v - m;
    red[c] = d * d; __syncthreads();
    for (int s = 128; s > 0; s >>= 1) { if (c < s) red[c] += red[c + s]; __syncthreads(); }
    float var = red[0] / CH;
    cbar[b * CH + c] = d * rsqrtf(var + 1e-5f) * g[c] + be[c];
}

__global__ void k_gate_bias(const float* __restrict__ cbar, const float* __restrict__ Wlow,
                            const float* __restrict__ bias, float* __restrict__ out) {
    __shared__ float cs[256];
    int b = blockIdx.x, j = threadIdx.x;
    cs[j] = cbar[b * CH + j];
    __syncthreads();
    float s = bias[j];
    for (int c = 0; c < CH; c++) s += cs[c] * Wlow[c * CH + j];
    out[b * CH + j] = s;
}

__device__ __forceinline__ float sigf(float x) { return 1.f / (1.f + expf(-x)); }

__global__ void k_gates(float* __restrict__ GA, float* __restrict__ GB,
                        float* __restrict__ GO, const float* __restrict__ U, int total) {
    int i = blockIdx.x * blockDim.x + threadIdx.x;
    if (i >= total) return;
    float F = GA[i], Wv = GB[i], Ov = GO[i], u = U[i];
    float a = 1.f / (1.f + expf(F));
    float sF = 1.f / (1.f + expf(-F));
    GA[i] = a;
    GB[i] = sF * sigf(Wv) * u;
    GO[i] = sigf(Ov);
}

__global__ void k_scan_pass1(const float* __restrict__ GA, const float* __restrict__ GB,
                             float* __restrict__ AF, float* __restrict__ BF,
                             float* __restrict__ ABc, float* __restrict__ BBc,
                             int rows, int nchunk) {
    int b = blockIdx.y, chn = blockIdx.x, c = threadIdx.x;
    int L = rows / nchunk;
    size_t base = ((size_t)b * rows + (size_t)chn * L) * CH + c;
    float Af = 1.f, Bf = 0.f;
    for (int i = 0; i < L; i++) {
        float a = GA[base + (size_t)i * CH], bb = GB[base + (size_t)i * CH];
        Af *= a; Bf = a * Bf + bb;
    }
    float Ab = 1.f, Bb = 0.f;
    for (int i = L - 1; i >= 0; i--) {
        float a = GA[base + (size_t)i * CH], bb = GB[base + (size_t)i * CH];
        Ab *= a; Bb = a * Bb + bb;
    }
    size_t co = ((size_t)b * nchunk + chn) * CH + c;
    AF[co] = Af; BF[co] = Bf; ABc[co] = Ab; BBc[co] = Bb;
}

__global__ void k_scan_pass2(const float* __restrict__ AF, const float* __restrict__ BF,
                             const float* __restrict__ ABc, const float* __restrict__ BBc,
                             float* __restrict__ SF, float* __restrict__ SB, int nchunk) {
    int b = blockIdx.x, c = threadIdx.x;
    float s = 0.f;
    for (int chn = 0; chn < nchunk; chn++) {
        size_t o = ((size_t)b * nchunk + chn) * CH + c;
        SF[o] = s; s = AF[o] * s + BF[o];
    }
    float sb = 0.f;
    for (int chn = nchunk - 1; chn >= 0; chn--) {
        size_t o = ((size_t)b * nchunk + chn) * CH + c;
        SB[o] = sb; sb = ABc[o] * sb + BBc[o];
    }
}

__global__ void k_scan_pass3(const float* __restrict__ GA, const float* __restrict__ GB,
                             const float* __restrict__ GO, const float* __restrict__ U,
                             const float* __restrict__ SF, const float* __restrict__ SB,
                             float* __restrict__ YF, float* __restrict__ YB,
                             int rows, int nchunk) {
    int b = blockIdx.y, chn = blockIdx.x, c = threadIdx.x;
    int L = rows / nchunk;
    size_t base = ((size_t)b * rows + (size_t)chn * L) * CH + c;
    size_t co = ((size_t)b * nchunk + chn) * CH + c;
    float s = SF[co];
    for (int i = 0; i < L; i++) {
        size_t o = base + (size_t)i * CH;
        float a = GA[o], bb = GB[o], ov = GO[o], u = U[o];
        s = a * s + bb;
        YF[o] = ov * s + (1.f - ov) * u;
    }
    float sb = SB[co];
    for (int i = L - 1; i >= 0; i--) {
        size_t o = base + (size_t)i * CH;
        float a = GA[o], bb = GB[o], ov = GO[o], u = U[o];
        sb = a * sb + bb;
        YB[o] = ov * sb + (1.f - ov) * u;
    }
}

__global__ void k_combine_rho(const float* __restrict__ T, const float* __restrict__ YF,
                              const float* __restrict__ YB, float* __restrict__ Y, int total) {
    int i = blockIdx.x * blockDim.x + threadIdx.x;
    if (i >= total) return;
    float r = sigf(T[i]);
    Y[i] = r * YF[i] + (1.f - r) * YB[i];
}

__global__ void k_combine_lam(const float* __restrict__ T, const float* __restrict__ Y,
                              const float* __restrict__ YG, float* __restrict__ Z, int total) {
    int i = blockIdx.x * blockDim.x + threadIdx.x;
    if (i >= total) return;
    Z[i] = Y[i] + sigf(T[i]) * YG[i];
}

__global__ void k_combine_eta(const float* __restrict__ T, const float* __restrict__ V,
                              const float* __restrict__ Z, float* __restrict__ Uo, int total) {
    int i = blockIdx.x * blockDim.x + threadIdx.x;
    if (i >= total) return;
    float e = sigf(T[i]);
    Uo[i] = e * V[i] + (1.f - e) * Z[i];
}

__global__ void k_pool(const float* __restrict__ x, float* __restrict__ xg) {
    int i = blockIdx.x * blockDim.x + threadIdx.x;
    if (i >= BSZ * CH * NG) return;
    int gx = i % GH; int gy = (i / GH) % GH; int bc = i / NG;
    const float* p = x + (size_t)bc * NN + (gy * 4) * 64 + gx * 4;
    float s = 0.f;
#pragma unroll
    for (int dy = 0; dy < 4; dy++)
#pragma unroll
        for (int dx = 0; dx < 4; dx++) s += p[dy * 64 + dx];
    xg[i] = s * 0.0625f;
}

__global__ void k_upsample(const float* __restrict__ yg, float* __restrict__ out) {
    int c = threadIdx.x;
    int n = blockIdx.x;
    int b = blockIdx.y;
    int h = n >> 6, w = n & 63;
    float sy = (h + 0.5f) * 0.25f - 0.5f;
    float sx = (w + 0.5f) * 0.25f - 0.5f;
    int y0 = (int)floorf(sy); float fy = sy - y0;
    int x0 = (int)floorf(sx); float fx = sx - x0;
    int y0c = min(max(y0, 0), 15), y1c = min(max(y0 + 1, 0), 15);
    int x0c = min(max(x0, 0), 15), x1c = min(max(x0 + 1, 0), 15);
    const float* p = yg + (size_t)b * NG * CH + c;
    float v00 = p[(size_t)(y0c * 16 + x0c) * CH];
    float v01 = p[(size_t)(y0c * 16 + x1c) * CH];
    float v10 = p[(size_t)(y1c * 16 + x0c) * CH];
    float v11 = p[(size_t)(y1c * 16 + x1c) * CH];
    out[((size_t)b * NN + n) * CH + c] =
        (1.f - fy) * ((1.f - fx) * v00 + fx * v01) + fy * ((1.f - fx) * v10 + fx * v11);
}

__global__ void k_dwconv(const float* __restrict__ x, const float* __restrict__ wt,
                         const float* __restrict__ bs, float* __restrict__ out) {
    int i = blockIdx.x * blockDim.x + threadIdx.x;
    if (i >= BSZ * CH * NN) return;
    int wp = i & 63;
    int h = (i >> 6) & 63;
    int cc = (i >> 12) & 255;
    const float* xp = x + (size_t)(i - wp - h * 64);
    const float* kp = wt + cc * 9;
    float s = bs[cc];
#pragma unroll
    for (int dy = -1; dy <= 1; dy++) {
        int yy = h + dy; if (yy < 0 || yy >= 64) continue;
#pragma unroll
        for (int dx = -1; dx <= 1; dx++) {
            int xx = wp + dx; if (xx < 0 || xx >= 64) continue;
            s += xp[yy * 64 + xx] * kp[(dy + 1) * 3 + (dx + 1)];
        }
    }
    out[i] = s;
}

__global__ void k_final(const float* __restrict__ x, const float* __restrict__ P,
                        float* __restrict__ out) {
    __shared__ float tile[32][33];
    int b = blockIdx.z;
    int n0 = blockIdx.x * 32, c0 = blockIdx.y * 32;
    const float* pp = P + (size_t)b * NN * CH;
    for (int i = threadIdx.y; i < 32; i += 8)
        tile[i][threadIdx.x] = pp[(size_t)(n0 + i) * CH + c0 + threadIdx.x];
    __syncthreads();
    const float* xp = x + (size_t)b * CH * NN;
    float* op = out + (size_t)b * CH * NN;
    for (int i = threadIdx.y; i < 32; i += 8)
        op[(size_t)(c0 + i) * NN + n0 + threadIdx.x] =
            xp[(size_t)(c0 + i) * NN + n0 + threadIdx.x] + tile[threadIdx.x][i];
}

// ---------------- host orchestration ----------------
static float* gsym(const void* sym) {
    void* p = nullptr;
    cudaGetSymbolAddress(&p, sym);
    return (float*)p;
}

#define GEMM_FINE(Aa, Bb, bn, bbn, Cc, acc) \
    k_gemm_mma<<<dim3(2, M_FINE / 128), 256>>>(Aa, Bb, bn, bbn, Cc, NN, acc)
#define GEMM_GLOB(Aa, Bb, bn, bbn, Cc, acc) \
    k_gemm_mma<<<dim3(2, M_GLOB / 128), 256>>>(Aa, Bb, bn, bbn, Cc, NG, acc)

extern "C" void kernel_launch(void* const* d_in, const int* in_sizes, int n_in,
                              void* d_out, int out_size) {
    const float* x    = (const float*)d_in[0];
    const float* Wt   = (const float*)d_in[1];
    const float* bt   = (const float*)d_in[2];
    const float* posf = (const float*)d_in[3];
    const float* posg = (const float*)d_in[4];
    const float* lng  = (const float*)d_in[5];
    const float* lnb  = (const float*)d_in[6];
    const float* Wf   = (const float*)d_in[7];
    const float* bf   = (const float*)d_in[8];
    const float* Ww_  = (const float*)d_in[9];
    const float* bw   = (const float*)d_in[10];
    const float* Wo   = (const float*)d_in[11];
    const float* bo   = (const float*)d_in[12];
    const float* Wr   = (const float*)d_in[13];
    const float* br   = (const float*)d_in[14];
    const float* Wgi  = (const float*)d_in[15];
    const float* bgi  = (const float*)d_in[16];
    const float* dww  = (const float*)d_in[17];
    const float* dwb  = (const float*)d_in[18];
    const float* Wl   = (const float*)d_in[19];
    const float* bl   = (const float*)d_in[20];
    const float* Wlf  = (const float*)d_in[21];
    const float* blf  = (const float*)d_in[22];
    const float* Wout = (const float*)d_in[23];
    const float* bout = (const float*)d_in[24];
    float* out = (float*)d_out;

    float *SEQ = gsym(d_SEQ), *U = gsym(d_U), *GA = gsym(d_GA), *GB = gsym(d_GB),
          *GO = gsym(d_GO), *YF = gsym(d_YF), *YB = gsym(d_YB), *Y = gsym(d_Y),
          *YG = gsym(d_YG), *T0 = gsym(d_T0);
    float *PF = gsym(d_PF), *PG = gsym(d_PG), *XG = gsym(d_XG), *SEQG = gsym(d_SEQG),
          *UG = gsym(d_UG), *AG = gsym(d_AG), *BG = gsym(d_BG), *OG = gsym(d_OG),
          *YGS = gsym(d_YGS);
    float *PART = gsym(d_PART), *CBAR = gsym(d_CBAR), *GBF = gsym(d_GBF),
          *GBW = gsym(d_GBW), *GBO = gsym(d_GBO);
    float *AF = gsym(d_AF), *BF = gsym(d_BF), *ABc = gsym(d_ABc), *BBc = gsym(d_BBc),
          *SF = gsym(d_SF), *SB = gsym(d_SB);

    const int TF = M_FINE * CH;
    const int TG = M_GLOB * CH;
    dim3 tb(32, 8);
    int eb = (TF + 255) / 256;
    int ebg = (TG + 255) / 256;

    // ---- fine sequence ----
    k_transpose<<<dim3(NN / 32, CH / 32, BSZ), tb>>>(x, SEQ, CH, NN);
    k_pos_embed<<<NN, 256>>>(posf, PF, HH, WW);
    k_pos_embed<<<NG, 256>>>(posg, PG, GH, GH);

    GEMM_FINE(SEQ, Wt, bt, nullptr, U, 0);
    k_add_pos<<<eb, 256>>>(U, PF, M_FINE, NN);

    // context + gate biases
    k_colsum<<<dim3(32, BSZ), 256>>>(U, PART, NN, 128, 32);
    k_ln_ctx<<<BSZ, 256>>>(PART, 32, 1.f / NN, lng, lnb, CBAR);
    k_gate_bias<<<BSZ, 256>>>(CBAR, Wf + 256 * 256, bf, GBF);
    k_gate_bias<<<BSZ, 256>>>(CBAR, Ww_ + 256 * 256, bw, GBW);
    k_gate_bias<<<BSZ, 256>>>(CBAR, Wo + 256 * 256, bo, GBO);

    // gates (shared between fwd & bwd branches)
    GEMM_FINE(U, Wf, nullptr, GBF, GA, 0);
    GEMM_FINE(U, Ww_, nullptr, GBW, GB, 0);
    GEMM_FINE(U, Wo, nullptr, GBO, GO, 0);
    k_gates<<<eb, 256>>>(GA, GB, GO, U, TF);

    // bidirectional chunked scan
    k_scan_pass1<<<dim3(NCHUNK, BSZ), 256>>>(GA, GB, AF, BF, ABc, BBc, NN, NCHUNK);
    k_scan_pass2<<<BSZ, 256>>>(AF, BF, ABc, BBc, SF, SB, NCHUNK);
    k_scan_pass3<<<dim3(NCHUNK, BSZ), 256>>>(GA, GB, GO, U, SF, SB, YF, YB, NN, NCHUNK);

    // rho mix
    GEMM_FINE(U, Wr, br, nullptr, T0, 0);
    GEMM_FINE(YF, Wr + 256 * 256, nullptr, nullptr, T0, 1);
    GEMM_FINE(YB, Wr + 512 * 256, nullptr, nullptr, T0, 1);
    k_combine_rho<<<eb, 256>>>(T0, YF, YB, Y, TF);

    // ---- global branch ----
    k_pool<<<(BSZ * CH * NG + 255) / 256, 256>>>(x, XG);
    k_transpose<<<dim3(NG / 32, CH / 32, BSZ), tb>>>(XG, SEQG, CH, NG);
    GEMM_GLOB(SEQG, Wt, bt, nullptr, UG, 0);
    k_add_pos<<<ebg, 256>>>(UG, PG, M_GLOB, NG);

    k_colsum<<<dim3(2, BSZ), 256>>>(UG, PART, NG, 128, 2);
    k_ln_ctx<<<BSZ, 256>>>(PART, 2, 1.f / NG, lng, lnb, CBAR);
    k_gate_bias<<<BSZ, 256>>>(CBAR, Wf + 256 * 256, bf, GBF);
    k_gate_bias<<<BSZ, 256>>>(CBAR, Ww_ + 256 * 256, bw, GBW);
    k_gate_bias<<<BSZ, 256>>>(CBAR, Wo + 256 * 256, bo, GBO);

    GEMM_GLOB(UG, Wf, nullptr, GBF, AG, 0);
    GEMM_GLOB(UG, Ww_, nullptr, GBW, BG, 0);
    GEMM_GLOB(UG, Wo, nullptr, GBO, OG, 0);
    k_gates<<<ebg, 256>>>(AG, BG, OG, UG, TG);

    k_scan_pass1<<<dim3(NCHUNK_G, BSZ), 256>>>(AG, BG, AF, BF, ABc, BBc, NG, NCHUNK_G);
    k_scan_pass2<<<BSZ, 256>>>(AF, BF, ABc, BBc, SF, SB, NCHUNK_G);
    k_scan_pass3<<<dim3(NCHUNK_G, BSZ), 256>>>(AG, BG, OG, UG, SF, SB, YGS, gsym(d_YGB), NG, NCHUNK_G);

    k_upsample<<<dim3(NN, BSZ), 256>>>(YGS, YG);

    // lam mix
    GEMM_FINE(Y, Wgi, bgi, nullptr, T0, 0);
    GEMM_FINE(YG, Wgi + 256 * 256, nullptr, nullptr, T0, 1);
    GEMM_FINE(U, Wgi + 512 * 256, nullptr, nullptr, T0, 1);
    k_combine_lam<<<eb, 256>>>(T0, Y, YG, YF, TF);   // YF := z

    // ---- local depthwise conv branch ----
    k_dwconv<<<(BSZ * CH * NN + 255) / 256, 256>>>(x, dww, dwb, SEQ);
    k_transpose<<<dim3(NN / 32, CH / 32, BSZ), tb>>>(SEQ, YB, CH, NN);
    GEMM_FINE(YB, Wl, bl, nullptr, GA, 0);           // GA := v

    GEMM_FINE(GA, Wlf, blf, nullptr, T0, 0);
    GEMM_FINE(YF, Wlf + 256 * 256, nullptr, nullptr, T0, 1);
    k_combine_eta<<<eb, 256>>>(T0, GA, YF, GB, TF);  // GB := u_out

    // output projection + residual
    GEMM_FINE(GB, Wout, bout, nullptr, T0, 0);
    k_final<<<dim3(NN / 32, CH / 32, BSZ), tb>>>(x, T0, out);
}

// round 6
// speedup vs baseline: 3.1774x; 1.2197x over previous
#include <cuda_runtime.h>
#include <cuda_bf16.h>
#include <math.h>
#include <stdint.h>

#define BSZ 8
#define CH 256
#define HH 64
#define WW 64
#define NN 4096          // HH*WW
#define GH 16
#define NG 256           // GH*GH
#define M_FINE (BSZ*NN)  // 32768
#define M_GLOB (BSZ*NG)  // 2048
#define NCHUNK 64
#define NCHUNK_G 8

// ---------------- scratch (device globals; no allocation allowed) ----------------
__device__ float d_SEQ [M_FINE*CH];
__device__ float d_U   [M_FINE*CH];
__device__ float d_GA  [M_FINE*CH];
__device__ float d_GB  [M_FINE*CH];   // holds g (fine), later u_out
__device__ float d_GO  [M_FINE*CH];
__device__ float d_YF  [M_FINE*CH];
__device__ float d_YB  [M_FINE*CH];
__device__ float d_Y   [M_FINE*CH];
__device__ float d_YG  [M_FINE*CH];
__device__ float d_T0  [M_FINE*CH];

__device__ float d_PF  [NN*CH];
__device__ float d_PG  [NG*CH];
__device__ float d_XG  [BSZ*CH*NG];
__device__ float d_SEQG[M_GLOB*CH];
__device__ float d_UG  [M_GLOB*CH];
__device__ float d_AG  [M_GLOB*CH];
__device__ float d_BG  [M_GLOB*CH];
__device__ float d_OG  [M_GLOB*CH];
__device__ float d_YGS [M_GLOB*CH];
__device__ float d_YGB [M_GLOB*CH];

__device__ float d_PART[BSZ*32*CH];
__device__ float d_CBAR[BSZ*CH];
__device__ float d_GBF [BSZ*CH];
__device__ float d_GBW [BSZ*CH];
__device__ float d_GBO [BSZ*CH];

__device__ float d_AF [BSZ*NCHUNK*CH];
__device__ float d_BF [BSZ*NCHUNK*CH];
__device__ float d_ABc[BSZ*NCHUNK*CH];
__device__ float d_BBc[BSZ*NCHUNK*CH];
__device__ float d_SF [BSZ*NCHUNK*CH];
__device__ float d_SB [BSZ*NCHUNK*CH];

// ---------------- HMMA helpers ----------------
__device__ __forceinline__ uint32_t smem_u32(const void* p) {
    uint32_t a;
    asm("{ .reg .u64 t; cvta.to.shared.u64 t, %1; cvt.u32.u64 %0, t; }" : "=r"(a) : "l"(p));
    return a;
}
#define LDSM_X4(r0, r1, r2, r3, addr) \
    asm volatile("ldmatrix.sync.aligned.m8n8.x4.shared.b16 {%0,%1,%2,%3}, [%4];" \
                 : "=r"(r0), "=r"(r1), "=r"(r2), "=r"(r3) : "r"(addr))
#define LDSM_X4_T(r0, r1, r2, r3, addr) \
    asm volatile("ldmatrix.sync.aligned.m8n8.x4.trans.shared.b16 {%0,%1,%2,%3}, [%4];" \
                 : "=r"(r0), "=r"(r1), "=r"(r2), "=r"(r3) : "r"(addr))
#define MMA16816(d, a, b0, b1) \
    asm volatile("mma.sync.aligned.m16n8k16.row.col.f32.bf16.bf16.f32 " \
                 "{%0,%1,%2,%3}, {%4,%5,%6,%7}, {%8,%9}, {%0,%1,%2,%3};" \
                 : "+f"((d)[0]), "+f"((d)[1]), "+f"((d)[2]), "+f"((d)[3]) \
                 : "r"((a)[0]), "r"((a)[1]), "r"((a)[2]), "r"((a)[3]), "r"(b0), "r"(b1))

__device__ __forceinline__ uint4 cvt8_bf16(float4 x, float4 y) {
    __nv_bfloat162 p0 = __floats2bfloat162_rn(x.x, x.y);
    __nv_bfloat162 p1 = __floats2bfloat162_rn(x.z, x.w);
    __nv_bfloat162 p2 = __floats2bfloat162_rn(y.x, y.y);
    __nv_bfloat162 p3 = __floats2bfloat162_rn(y.z, y.w);
    return make_uint4(*(uint32_t*)&p0, *(uint32_t*)&p1, *(uint32_t*)&p2, *(uint32_t*)&p3);
}
__device__ __forceinline__ float sigf(float x) { return 1.f / (1.f + expf(-x)); }

// ---------------- shared HMMA mainloop ----------------
// Computes acc = [sum over nA segments] A_j[128,256] @ B_seg[256,128]
// B is [nA*256, 256] row-major; segment s uses rows s*32..s*32+31.
__device__ __forceinline__ void mma_loop(
    const float* __restrict__ A0, const float* __restrict__ A1, const float* __restrict__ A2,
    const float* __restrict__ Bw, int nA, int m0, int n0,
    uint8_t* sm, uint32_t smBase, float (*acc)[4][4]) {
    int tid = threadIdx.x;
    int wid = tid >> 5, lane = tid & 31;
    int wm = wid >> 2, wn = wid & 3;            // warp grid 2 x 4
    int mA = tid >> 2, cA = tid & 3;
    int kB = tid >> 4, cB = tid & 15;

    uint32_t offA0 = (uint32_t)(mA * 64 + ((cA ^ ((mA >> 1) & 3)) << 4));
    uint32_t offA1 = offA0 + 4096u;
    uint32_t offB0 = 8192u + (uint32_t)(kB * 256 + ((cB ^ (kB & 7)) << 4));
    uint32_t offB1 = offB0 + 4096u;

    int lr = lane & 7, lh = (lane >> 3) & 1, lq = lane >> 4;
    int arow_base = wm * 64 + lh * 8 + lr;
    int brow_base = lh * 8 + lr;

    int totalS = nA * 8;
    float4 ra[4], rb[4];

    // prefetch step 0
    {
        const float* p = A0 + (size_t)(m0 + mA) * 256 + cA * 8;
        ra[0] = ((const float4*)p)[0]; ra[1] = ((const float4*)p)[1];
        const float* q = p + 64 * 256;
        ra[2] = ((const float4*)q)[0]; ra[3] = ((const float4*)q)[1];
        const float* r = Bw + (size_t)kB * 256 + n0 + cB * 8;
        rb[0] = ((const float4*)r)[0]; rb[1] = ((const float4*)r)[1];
        const float* t = r + 16 * 256;
        rb[2] = ((const float4*)t)[0]; rb[3] = ((const float4*)t)[1];
    }

    uint32_t bo = 0;
#pragma unroll 1
    for (int s = 0; s < totalS; s++) {
        *(uint4*)(sm + bo + offA0) = cvt8_bf16(ra[0], ra[1]);
        *(uint4*)(sm + bo + offA1) = cvt8_bf16(ra[2], ra[3]);
        *(uint4*)(sm + bo + offB0) = cvt8_bf16(rb[0], rb[1]);
        *(uint4*)(sm + bo + offB1) = cvt8_bf16(rb[2], rb[3]);
        __syncthreads();
        if (s < totalS - 1) {
            int sn = s + 1;
            const float* Aj = (sn >> 3) == 0 ? A0 : ((sn >> 3) == 1 ? A1 : A2);
            const float* p = Aj + (size_t)(m0 + mA) * 256 + ((sn & 7) * 32) + cA * 8;
            ra[0] = ((const float4*)p)[0]; ra[1] = ((const float4*)p)[1];
            const float* q = p + 64 * 256;
            ra[2] = ((const float4*)q)[0]; ra[3] = ((const float4*)q)[1];
            const float* r = Bw + (size_t)(sn * 32 + kB) * 256 + n0 + cB * 8;
            rb[0] = ((const float4*)r)[0]; rb[1] = ((const float4*)r)[1];
            const float* t = r + 16 * 256;
            rb[2] = ((const float4*)t)[0]; rb[3] = ((const float4*)t)[1];
        }
#pragma unroll
        for (int k16 = 0; k16 < 2; k16++) {
            uint32_t afr[4][4];
#pragma unroll
            for (int mi = 0; mi < 4; mi++) {
                int row = arow_base + mi * 16;
                int c = k16 * 2 + lq;
                uint32_t addr = smBase + bo + (uint32_t)(row * 64 + ((c ^ ((row >> 1) & 3)) << 4));
                LDSM_X4(afr[mi][0], afr[mi][1], afr[mi][2], afr[mi][3], addr);
            }
            uint32_t bfr[2][4];
#pragma unroll
            for (int g = 0; g < 2; g++) {
                int rowk = k16 * 16 + brow_base;
                int c = wn * 4 + g * 2 + lq;
                uint32_t addr = smBase + bo + 8192u + (uint32_t)(rowk * 256 + ((c ^ (rowk & 7)) << 4));
                LDSM_X4_T(bfr[g][0], bfr[g][1], bfr[g][2], bfr[g][3], addr);
            }
#pragma unroll
            for (int mi = 0; mi < 4; mi++)
#pragma unroll
                for (int j = 0; j < 4; j++)
                    MMA16816(acc[mi][j], afr[mi], bfr[j >> 1][(j & 1) * 2], bfr[j >> 1][(j & 1) * 2 + 1]);
        }
        bo ^= 16384u;
        if (s < totalS - 1) __syncthreads();
    }
}

// ---------------- fused GEMM: C = epi( concat(A0..A_{nA-1}) @ Bw + bias [+pos] ) ----
// mode 0: C = t (+pos)            mode 1: r=sig(t); C = r*E0 + (1-r)*E1
// mode 2: C = E0 + sig(t)*E1
__global__ void __launch_bounds__(256, 1)
k_gemm_f(const float* __restrict__ A0, const float* __restrict__ A1,
         const float* __restrict__ A2, const float* __restrict__ Bw,
         const float* __restrict__ bias, const float* __restrict__ E0,
         const float* __restrict__ E1, const float* __restrict__ pos,
         float* __restrict__ C, int nA, int mode, int posRows) {
    __shared__ __align__(16) uint8_t sm[32768];
    uint32_t smBase = smem_u32(sm);
    int m0 = blockIdx.y * 128, n0 = blockIdx.x * 128;

    float acc[4][4][4] = {};
    mma_loop(A0, A1, A2, Bw, nA, m0, n0, sm, smBase, acc);

    int lane = threadIdx.x & 31, wid = threadIdx.x >> 5;
    int wm = wid >> 2, wn = wid & 3;
    int gid = lane >> 2, tig = lane & 3;
#pragma unroll
    for (int mi = 0; mi < 4; mi++) {
#pragma unroll
        for (int j = 0; j < 4; j++) {
            int row = m0 + wm * 64 + mi * 16 + gid;
            int col = n0 + wn * 32 + j * 8 + tig * 2;
            float t0 = acc[mi][j][0], t1 = acc[mi][j][1];
            float t2 = acc[mi][j][2], t3 = acc[mi][j][3];
            float bb0 = 0.f, bb1 = 0.f;
            if (bias) { bb0 = bias[col]; bb1 = bias[col + 1]; }
            t0 += bb0; t1 += bb1; t2 += bb0; t3 += bb1;
            size_t o0 = (size_t)row * 256 + col;
            size_t o1 = (size_t)(row + 8) * 256 + col;
            float v0, v1, v2, v3;
            if (mode == 0) {
                if (pos) {
                    const float* p0 = pos + (size_t)(row % posRows) * 256 + col;
                    const float* p1 = pos + (size_t)((row + 8) % posRows) * 256 + col;
                    t0 += p0[0]; t1 += p0[1]; t2 += p1[0]; t3 += p1[1];
                }
                v0 = t0; v1 = t1; v2 = t2; v3 = t3;
            } else {
                float e0 = E0[o0], e1 = E0[o0 + 1], e2 = E0[o1], e3 = E0[o1 + 1];
                float f0 = E1[o0], f1 = E1[o0 + 1], f2 = E1[o1], f3 = E1[o1 + 1];
                if (mode == 1) {
                    float r0 = sigf(t0), r1 = sigf(t1), r2 = sigf(t2), r3 = sigf(t3);
                    v0 = r0 * e0 + (1.f - r0) * f0; v1 = r1 * e1 + (1.f - r1) * f1;
                    v2 = r2 * e2 + (1.f - r2) * f2; v3 = r3 * e3 + (1.f - r3) * f3;
                } else {
                    v0 = e0 + sigf(t0) * f0; v1 = e1 + sigf(t1) * f1;
                    v2 = e2 + sigf(t2) * f2; v3 = e3 + sigf(t3) * f3;
                }
            }
            C[o0] = v0; C[o0 + 1] = v1;
            C[o1] = v2; C[o1 + 1] = v3;
        }
    }
}

// ---------------- fused gates GEMM: 3 outputs share A (L2 reuse) ----------------
// grid (6, M/128): j = bx>>1 selects weight/output, bx&1 selects N-half.
// C0 = sigmoid(-(A@W0 + G0)), C1 = sigmoid(A@W1 + G1), C2 = sigmoid(A@W2 + G2)
__global__ void __launch_bounds__(256, 1)
k_gates3(const float* __restrict__ A, const float* __restrict__ W0,
         const float* __restrict__ W1, const float* __restrict__ W2,
         const float* __restrict__ G0, const float* __restrict__ G1,
         const float* __restrict__ G2, float* __restrict__ C0,
         float* __restrict__ C1, float* __restrict__ C2, int rowsPerBatch) {
    __shared__ __align__(16) uint8_t sm[32768];
    uint32_t smBase = smem_u32(sm);
    int j3 = blockIdx.x >> 1;
    int n0 = (blockIdx.x & 1) * 128;
    int m0 = blockIdx.y * 128;
    const float* Bw = j3 == 0 ? W0 : (j3 == 1 ? W1 : W2);
    const float* Gb = j3 == 0 ? G0 : (j3 == 1 ? G1 : G2);
    float* C = j3 == 0 ? C0 : (j3 == 1 ? C1 : C2);

    float acc[4][4][4] = {};
    mma_loop(A, A, A, Bw, 1, m0, n0, sm, smBase, acc);

    int lane = threadIdx.x & 31, wid = threadIdx.x >> 5;
    int wm = wid >> 2, wn = wid & 3;
    int gid = lane >> 2, tig = lane & 3;
    int batch = m0 / rowsPerBatch;
    float sgn = (j3 == 0) ? -1.f : 1.f;
#pragma unroll
    for (int mi = 0; mi < 4; mi++) {
#pragma unroll
        for (int j = 0; j < 4; j++) {
            int row = m0 + wm * 64 + mi * 16 + gid;
            int col = n0 + wn * 32 + j * 8 + tig * 2;
            float bb0 = Gb[batch * 256 + col], bb1 = Gb[batch * 256 + col + 1];
            float v0 = sigf(sgn * (acc[mi][j][0] + bb0));
            float v1 = sigf(sgn * (acc[mi][j][1] + bb1));
            float v2 = sigf(sgn * (acc[mi][j][2] + bb0));
            float v3 = sigf(sgn * (acc[mi][j][3] + bb1));
            size_t o0 = (size_t)row * 256 + col;
            size_t o1 = (size_t)(row + 8) * 256 + col;
            C[o0] = v0; C[o0 + 1] = v1;
            C[o1] = v2; C[o1 + 1] = v3;
        }
    }
}

// ---------------- elementwise / scan kernels ----------------

__global__ void k_transpose(const float* __restrict__ in, float* __restrict__ out,
                            int CC, int NR) {
    __shared__ float tile[32][33];
    int b = blockIdx.z;
    int n0 = blockIdx.x * 32, c0 = blockIdx.y * 32;
    const float* ip = in + (size_t)b * CC * NR;
    float* op = out + (size_t)b * CC * NR;
    for (int i = threadIdx.y; i < 32; i += 8)
        tile[i][threadIdx.x] = ip[(size_t)(c0 + i) * NR + n0 + threadIdx.x];
    __syncthreads();
    for (int i = threadIdx.y; i < 32; i += 8)
        op[(size_t)(n0 + i) * CC + c0 + threadIdx.x] = tile[threadIdx.x][i];
}

__device__ __forceinline__ int resize_taps(int i, int IS, int OS, int* jj, float* ww) {
    float inv = (float)IS / (float)OS;
    float dil = inv > 1.f ? inv : 1.f;
    float s = (i + 0.5f) * inv - 0.5f;
    int lo = (int)floorf(s - dil);
    int hi = (int)ceilf(s + dil);
    int n = 0; float tot = 0.f;
    for (int j = lo; j <= hi; j++) {
        if (j < 0 || j >= IS) continue;
        float w = 1.f - fabsf(s - (float)j) / dil;
        if (w <= 0.f) continue;
        jj[n] = j; ww[n] = w; tot += w; n++;
    }
    float r = 1.f / tot;
    for (int t = 0; t < n; t++) ww[t] *= r;
    return n;
}

__global__ void k_pos_embed(const float* __restrict__ pos, float* __restrict__ out,
                            int OH, int OW) {
    int c = threadIdx.x;
    int n = blockIdx.x;
    int h = n / OW, w = n % OW;
    int jy[8], jx[8]; float wy[8], wx[8];
    int ny = resize_taps(h, 32, OH, jy, wy);
    int nx = resize_taps(w, 32, OW, jx, wx);
    float acc = 0.f;
    for (int a = 0; a < ny; a++)
        for (int b2 = 0; b2 < nx; b2++)
            acc += wy[a] * wx[b2] * pos[c * 1024 + jy[a] * 32 + jx[b2]];
    out[(size_t)n * CH + c] = acc;
}

__global__ void k_colsum(const float* __restrict__ u, float* __restrict__ part,
                         int rowsTotal, int rowsPerBlock, int nch) {
    int b = blockIdx.y, c = threadIdx.x, chn = blockIdx.x;
    const float* p = u + ((size_t)b * rowsTotal + (size_t)chn * rowsPerBlock) * CH + c;
    float s = 0.f;
    for (int r = 0; r < rowsPerBlock; r++) s += p[(size_t)r * CH];
    part[((size_t)b * nch + chn) * CH + c] = s;
}

__global__ void k_ln_ctx(const float* __restrict__ part, int nch, float invN,
                         const float* __restrict__ g, const float* __restrict__ be,
                         float* __restrict__ cbar) {
    __shared__ float red[256];
    int b = blockIdx.x, c = threadIdx.x;
    float v = 0.f;
    for (int chn = 0; chn < nch; chn++) v += part[((size_t)b * nch + chn) * CH + c];
    v *= invN;
    red[c] = v; __syncthreads();
    for (int s = 128; s > 0; s >>= 1) { if (c < s) red[c] += red[c + s]; __syncthreads(); }
    float m = red[0] / CH; __syncthreads();
    float d = v - m;
    red[c] = d * d; __syncthreads();
    for (int s = 128; s > 0; s >>= 1) { if (c < s) red[c] += red[c + s]; __syncthreads(); }
    float var = red[0] / CH;
    cbar[b * CH + c] = d * rsqrtf(var + 1e-5f) * g[c] + be[c];
}

__global__ void k_gate_bias(const float* __restrict__ cbar, const float* __restrict__ Wlow,
                            const float* __restrict__ bias, float* __restrict__ out) {
    __shared__ float cs[256];
    int b = blockIdx.x, j = threadIdx.x;
    cs[j] = cbar[b * CH + j];
    __syncthreads();
    float s = bias[j];
    for (int c = 0; c < CH; c++) s += cs[c] * Wlow[c * CH + j];
    out[b * CH + j] = s;
}

// scan pass1: b computed inline from a, g, u
__global__ void k_scan_pass1(const float* __restrict__ GA, const float* __restrict__ GW,
                             const float* __restrict__ U,
                             float* __restrict__ AF, float* __restrict__ BF,
                             float* __restrict__ ABc, float* __restrict__ BBc,
                             int rows, int nchunk) {
    int b = blockIdx.y, chn = blockIdx.x, c = threadIdx.x;
    int L = rows / nchunk;
    size_t base = ((size_t)b * rows + (size_t)chn * L) * CH + c;
    float Af = 1.f, Bf = 0.f;
    for (int i = 0; i < L; i++) {
        size_t o = base + (size_t)i * CH;
        float a = GA[o];
        float bb = (1.f - a) * GW[o] * U[o];
        Af *= a; Bf = a * Bf + bb;
    }
    float Ab = 1.f, Bb = 0.f;
    for (int i = L - 1; i >= 0; i--) {
        size_t o = base + (size_t)i * CH;
        float a = GA[o];
        float bb = (1.f - a) * GW[o] * U[o];
        Ab *= a; Bb = a * Bb + bb;
    }
    size_t co = ((size_t)b * nchunk + chn) * CH + c;
    AF[co] = Af; BF[co] = Bf; ABc[co] = Ab; BBc[co] = Bb;
}

__global__ void k_scan_pass2(const float* __restrict__ AF, const float* __restrict__ BF,
                             const float* __restrict__ ABc, const float* __restrict__ BBc,
                             float* __restrict__ SF, float* __restrict__ SB, int nchunk) {
    int b = blockIdx.x, c = threadIdx.x;
    float s = 0.f;
    for (int chn = 0; chn < nchunk; chn++) {
        size_t o = ((size_t)b * nchunk + chn) * CH + c;
        SF[o] = s; s = AF[o] * s + BF[o];
    }
    float sb = 0.f;
    for (int chn = nchunk - 1; chn >= 0; chn--) {
        size_t o = ((size_t)b * nchunk + chn) * CH + c;
        SB[o] = sb; sb = ABc[o] * sb + BBc[o];
    }
}

__global__ void k_scan_pass3(const float* __restrict__ GA, const float* __restrict__ GW,
                             const float* __restrict__ GO, const float* __restrict__ U,
                             const float* __restrict__ SF, const float* __restrict__ SB,
                             float* __restrict__ YF, float* __restrict__ YB,
                             int rows, int nchunk) {
    int b = blockIdx.y, chn = blockIdx.x, c = threadIdx.x;
    int L = rows / nchunk;
    size_t base = ((size_t)b * rows + (size_t)chn * L) * CH + c;
    size_t co = ((size_t)b * nchunk + chn) * CH + c;
    float s = SF[co];
    for (int i = 0; i < L; i++) {
        size_t o = base + (size_t)i * CH;
        float a = GA[o], u = U[o], ov = GO[o];
        float bb = (1.f - a) * GW[o] * u;
        s = a * s + bb;
        YF[o] = ov * s + (1.f - ov) * u;
    }
    float sb = SB[co];
    for (int i = L - 1; i >= 0; i--) {
        size_t o = base + (size_t)i * CH;
        float a = GA[o], u = U[o], ov = GO[o];
        float bb = (1.f - a) * GW[o] * u;
        sb = a * sb + bb;
        YB[o] = ov * sb + (1.f - ov) * u;
    }
}

__global__ void k_pool(const float* __restrict__ x, float* __restrict__ xg) {
    int i = blockIdx.x * blockDim.x + threadIdx.x;
    if (i >= BSZ * CH * NG) return;
    int gx = i % GH; int gy = (i / GH) % GH; int bc = i / NG;
    const float* p = x + (size_t)bc * NN + (gy * 4) * 64 + gx * 4;
    float s = 0.f;
#pragma unroll
    for (int dy = 0; dy < 4; dy++)
#pragma unroll
        for (int dx = 0; dx < 4; dx++) s += p[dy * 64 + dx];
    xg[i] = s * 0.0625f;
}

__global__ void k_upsample(const float* __restrict__ yg, float* __restrict__ out) {
    int c = threadIdx.x;
    int n = blockIdx.x;
    int b = blockIdx.y;
    int h = n >> 6, w = n & 63;
    float sy = (h + 0.5f) * 0.25f - 0.5f;
    float sx = (w + 0.5f) * 0.25f - 0.5f;
    int y0 = (int)floorf(sy); float fy = sy - y0;
    int x0 = (int)floorf(sx); float fx = sx - x0;
    int y0c = min(max(y0, 0), 15), y1c = min(max(y0 + 1, 0), 15);
    int x0c = min(max(x0, 0), 15), x1c = min(max(x0 + 1, 0), 15);
    const float* p = yg + (size_t)b * NG * CH + c;
    float v00 = p[(size_t)(y0c * 16 + x0c) * CH];
    float v01 = p[(size_t)(y0c * 16 + x1c) * CH];
    float v10 = p[(size_t)(y1c * 16 + x0c) * CH];
    float v11 = p[(size_t)(y1c * 16 + x1c) * CH];
    out[((size_t)b * NN + n) * CH + c] =
        (1.f - fy) * ((1.f - fx) * v00 + fx * v01) + fy * ((1.f - fx) * v10 + fx * v11);
}

__global__ void k_dwconv(const float* __restrict__ x, const float* __restrict__ wt,
                         const float* __restrict__ bs, float* __restrict__ out) {
    int i = blockIdx.x * blockDim.x + threadIdx.x;
    if (i >= BSZ * CH * NN) return;
    int wp = i & 63;
    int h = (i >> 6) & 63;
    int cc = (i >> 12) & 255;
    const float* xp = x + (size_t)(i - wp - h * 64);
    const float* kp = wt + cc * 9;
    float s = bs[cc];
#pragma unroll
    for (int dy = -1; dy <= 1; dy++) {
        int yy = h + dy; if (yy < 0 || yy >= 64) continue;
#pragma unroll
        for (int dx = -1; dx <= 1; dx++) {
            int xx = wp + dx; if (xx < 0 || xx >= 64) continue;
            s += xp[yy * 64 + xx] * kp[(dy + 1) * 3 + (dx + 1)];
        }
    }
    out[i] = s;
}

__global__ void k_final(const float* __restrict__ x, const float* __restrict__ P,
                        float* __restrict__ out) {
    __shared__ float tile[32][33];
    int b = blockIdx.z;
    int n0 = blockIdx.x * 32, c0 = blockIdx.y * 32;
    const float* pp = P + (size_t)b * NN * CH;
    for (int i = threadIdx.y; i < 32; i += 8)
        tile[i][threadIdx.x] = pp[(size_t)(n0 + i) * CH + c0 + threadIdx.x];
    __syncthreads();
    const float* xp = x + (size_t)b * CH * NN;
    float* op = out + (size_t)b * CH * NN;
    for (int i = threadIdx.y; i < 32; i += 8)
        op[(size_t)(c0 + i) * NN + n0 + threadIdx.x] =
            xp[(size_t)(c0 + i) * NN + n0 + threadIdx.x] + tile[threadIdx.x][i];
}

// ---------------- host orchestration ----------------
static float* gsym(const void* sym) {
    void* p = nullptr;
    cudaGetSymbolAddress(&p, sym);
    return (float*)p;
}

extern "C" void kernel_launch(void* const* d_in, const int* in_sizes, int n_in,
                              void* d_out, int out_size) {
    const float* x    = (const float*)d_in[0];
    const float* Wt   = (const float*)d_in[1];
    const float* bt   = (const float*)d_in[2];
    const float* posf = (const float*)d_in[3];
    const float* posg = (const float*)d_in[4];
    const float* lng  = (const float*)d_in[5];
    const float* lnb  = (const float*)d_in[6];
    const float* Wf   = (const float*)d_in[7];
    const float* bf   = (const float*)d_in[8];
    const float* Ww_  = (const float*)d_in[9];
    const float* bw   = (const float*)d_in[10];
    const float* Wo   = (const float*)d_in[11];
    const float* bo   = (const float*)d_in[12];
    const float* Wr   = (const float*)d_in[13];
    const float* br   = (const float*)d_in[14];
    const float* Wgi  = (const float*)d_in[15];
    const float* bgi  = (const float*)d_in[16];
    const float* dww  = (const float*)d_in[17];
    const float* dwb  = (const float*)d_in[18];
    const float* Wl   = (const float*)d_in[19];
    const float* bl   = (const float*)d_in[20];
    const float* Wlf  = (const float*)d_in[21];
    const float* blf  = (const float*)d_in[22];
    const float* Wout = (const float*)d_in[23];
    const float* bout = (const float*)d_in[24];
    float* out = (float*)d_out;

    float *SEQ = gsym(d_SEQ), *U = gsym(d_U), *GA = gsym(d_GA), *GW = gsym(d_GB),
          *GO = gsym(d_GO), *YF = gsym(d_YF), *YB = gsym(d_YB), *Y = gsym(d_Y),
          *YG = gsym(d_YG), *T0 = gsym(d_T0);
    float *PF = gsym(d_PF), *PG = gsym(d_PG), *XG = gsym(d_XG), *SEQG = gsym(d_SEQG),
          *UG = gsym(d_UG), *AG = gsym(d_AG), *BG = gsym(d_BG), *OG = gsym(d_OG),
          *YGS = gsym(d_YGS), *YGB = gsym(d_YGB);
    float *PART = gsym(d_PART), *CBAR = gsym(d_CBAR), *GBF = gsym(d_GBF),
          *GBW = gsym(d_GBW), *GBO = gsym(d_GBO);
    float *AF = gsym(d_AF), *BF = gsym(d_BF), *ABc = gsym(d_ABc), *BBc = gsym(d_BBc),
          *SF = gsym(d_SF), *SB = gsym(d_SB);

    dim3 tb(32, 8);
    dim3 gF(2, M_FINE / 128);   // fine GEMM
    dim3 gG(2, M_GLOB / 128);   // glob GEMM
    dim3 gF3(6, M_FINE / 128);  // fine gates
    dim3 gG3(6, M_GLOB / 128);  // glob gates

    // ---- fine sequence ----
    k_transpose<<<dim3(NN / 32, CH / 32, BSZ), tb>>>(x, SEQ, CH, NN);
    k_pos_embed<<<NN, 256>>>(posf, PF, HH, WW);
    k_pos_embed<<<NG, 256>>>(posg, PG, GH, GH);

    // u = seq @ Wt + bt + pos
    k_gemm_f<<<gF, 256>>>(SEQ, nullptr, nullptr, Wt, bt, nullptr, nullptr, PF, U, 1, 0, NN);

    // context + gate biases
    k_colsum<<<dim3(32, BSZ), 256>>>(U, PART, NN, 128, 32);
    k_ln_ctx<<<BSZ, 256>>>(PART, 32, 1.f / NN, lng, lnb, CBAR);
    k_gate_bias<<<BSZ, 256>>>(CBAR, Wf + 256 * 256, bf, GBF);
    k_gate_bias<<<BSZ, 256>>>(CBAR, Ww_ + 256 * 256, bw, GBW);
    k_gate_bias<<<BSZ, 256>>>(CBAR, Wo + 256 * 256, bo, GBO);

    // gates: a, g, o (b computed inline in scans)
    k_gates3<<<gF3, 256>>>(U, Wf, Ww_, Wo, GBF, GBW, GBO, GA, GW, GO, NN);

    // bidirectional chunked scan
    k_scan_pass1<<<dim3(NCHUNK, BSZ), 256>>>(GA, GW, U, AF, BF, ABc, BBc, NN, NCHUNK);
    k_scan_pass2<<<BSZ, 256>>>(AF, BF, ABc, BBc, SF, SB, NCHUNK);
    k_scan_pass3<<<dim3(NCHUNK, BSZ), 256>>>(GA, GW, GO, U, SF, SB, YF, YB, NN, NCHUNK);

    // rho mix fused: Y = sig(t)*YF + (1-sig)*YB, t = [U,YF,YB]@Wr + br
    k_gemm_f<<<gF, 256>>>(U, YF, YB, Wr, br, YF, YB, nullptr, Y, 3, 1, NN);

    // ---- global branch ----
    k_pool<<<(BSZ * CH * NG + 255) / 256, 256>>>(x, XG);
    k_transpose<<<dim3(NG / 32, CH / 32, BSZ), tb>>>(XG, SEQG, CH, NG);
    k_gemm_f<<<gG, 256>>>(SEQG, nullptr, nullptr, Wt, bt, nullptr, nullptr, PG, UG, 1, 0, NG);

    k_colsum<<<dim3(2, BSZ), 256>>>(UG, PART, NG, 128, 2);
    k_ln_ctx<<<BSZ, 256>>>(PART, 2, 1.f / NG, lng, lnb, CBAR);
    k_gate_bias<<<BSZ, 256>>>(CBAR, Wf + 256 * 256, bf, GBF);
    k_gate_bias<<<BSZ, 256>>>(CBAR, Ww_ + 256 * 256, bw, GBW);
    k_gate_bias<<<BSZ, 256>>>(CBAR, Wo + 256 * 256, bo, GBO);

    k_gates3<<<gG3, 256>>>(UG, Wf, Ww_, Wo, GBF, GBW, GBO, AG, BG, OG, NG);

    k_scan_pass1<<<dim3(NCHUNK_G, BSZ), 256>>>(AG, BG, UG, AF, BF, ABc, BBc, NG, NCHUNK_G);
    k_scan_pass2<<<BSZ, 256>>>(AF, BF, ABc, BBc, SF, SB, NCHUNK_G);
    k_scan_pass3<<<dim3(NCHUNK_G, BSZ), 256>>>(AG, BG, OG, UG, SF, SB, YGS, YGB, NG, NCHUNK_G);

    k_upsample<<<dim3(NN, BSZ), 256>>>(YGS, YG);

    // lam fused: T0 := z = Y + sig(t)*YG, t = [Y,YG,U]@Wgi + bgi
    k_gemm_f<<<gF, 256>>>(Y, YG, U, Wgi, bgi, Y, YG, nullptr, T0, 3, 2, NN);

    // ---- local depthwise conv branch ----
    k_dwconv<<<(BSZ * CH * NN + 255) / 256, 256>>>(x, dww, dwb, SEQ);
    k_transpose<<<dim3(NN / 32, CH / 32, BSZ), tb>>>(SEQ, YF, CH, NN);
    // v = convseq @ Wl + bl  -> GA
    k_gemm_f<<<gF, 256>>>(YF, nullptr, nullptr, Wl, bl, nullptr, nullptr, nullptr, GA, 1, 0, NN);
    // eta fused: u_out = sig(t)*v + (1-sig)*z, t = [v,z]@Wlf + blf  -> GW buffer
    k_gemm_f<<<gF, 256>>>(GA, T0, nullptr, Wlf, blf, GA, T0, nullptr, GW, 2, 1, NN);
    // out projection -> U (free), then residual transpose
    k_gemm_f<<<gF, 256>>>(GW, nullptr, nullptr, Wout, bout, nullptr, nullptr, nullptr, U, 1, 0, NN);
    k_final<<<dim3(NN / 32, CH / 32, BSZ), tb>>>(x, U, out);
}

// round 7
// speedup vs baseline: 3.2950x; 1.0370x over previous
#include <cuda_runtime.h>
#include <cuda_bf16.h>
#include <math.h>
#include <stdint.h>

#define BSZ 8
#define CH 256
#define HH 64
#define WW 64
#define NN 4096          // HH*WW
#define GH 16
#define NG 256           // GH*GH
#define M_FINE (BSZ*NN)  // 32768
#define M_GLOB (BSZ*NG)  // 2048
#define NCHUNK 64
#define NCHUNK_G 8

// ---------------- scratch (device globals; no allocation allowed) ----------------
__device__ float d_SEQ [M_FINE*CH];
__device__ float d_U   [M_FINE*CH];
__device__ float d_GA  [M_FINE*CH];
__device__ float d_GB  [M_FINE*CH];   // holds g (fine), later u_out
__device__ float d_GO  [M_FINE*CH];
__device__ float d_YF  [M_FINE*CH];
__device__ float d_YB  [M_FINE*CH];
__device__ float d_Y   [M_FINE*CH];
__device__ float d_YG  [M_FINE*CH];
__device__ float d_T0  [M_FINE*CH];

__device__ float d_PF  [NN*CH];
__device__ float d_PG  [NG*CH];
__device__ float d_XG  [BSZ*CH*NG];
__device__ float d_SEQG[M_GLOB*CH];
__device__ float d_UG  [M_GLOB*CH];
__device__ float d_AG  [M_GLOB*CH];
__device__ float d_BG  [M_GLOB*CH];
__device__ float d_OG  [M_GLOB*CH];
__device__ float d_YGS [M_GLOB*CH];
__device__ float d_YGB [M_GLOB*CH];

__device__ float d_PART[BSZ*32*CH];
__device__ float d_CBAR[BSZ*CH];
__device__ float d_GBF [BSZ*CH];
__device__ float d_GBW [BSZ*CH];
__device__ float d_GBO [BSZ*CH];

__device__ float d_AF [BSZ*NCHUNK*CH];
__device__ float d_BF [BSZ*NCHUNK*CH];
__device__ float d_ABc[BSZ*NCHUNK*CH];
__device__ float d_BBc[BSZ*NCHUNK*CH];
__device__ float d_SF [BSZ*NCHUNK*CH];
__device__ float d_SB [BSZ*NCHUNK*CH];

// ---------------- HMMA helpers ----------------
__device__ __forceinline__ uint32_t smem_u32(const void* p) {
    uint32_t a;
    asm("{ .reg .u64 t; cvta.to.shared.u64 t, %1; cvt.u32.u64 %0, t; }" : "=r"(a) : "l"(p));
    return a;
}
#define LDSM_X4(r0, r1, r2, r3, addr) \
    asm volatile("ldmatrix.sync.aligned.m8n8.x4.shared.b16 {%0,%1,%2,%3}, [%4];" \
                 : "=r"(r0), "=r"(r1), "=r"(r2), "=r"(r3) : "r"(addr))
#define LDSM_X4_T(r0, r1, r2, r3, addr) \
    asm volatile("ldmatrix.sync.aligned.m8n8.x4.trans.shared.b16 {%0,%1,%2,%3}, [%4];" \
                 : "=r"(r0), "=r"(r1), "=r"(r2), "=r"(r3) : "r"(addr))
#define MMA16816(d, a, b0, b1) \
    asm volatile("mma.sync.aligned.m16n8k16.row.col.f32.bf16.bf16.f32 " \
                 "{%0,%1,%2,%3}, {%4,%5,%6,%7}, {%8,%9}, {%0,%1,%2,%3};" \
                 : "+f"((d)[0]), "+f"((d)[1]), "+f"((d)[2]), "+f"((d)[3]) \
                 : "r"((a)[0]), "r"((a)[1]), "r"((a)[2]), "r"((a)[3]), "r"(b0), "r"(b1))

__device__ __forceinline__ uint4 cvt8_bf16(float4 x, float4 y) {
    __nv_bfloat162 p0 = __floats2bfloat162_rn(x.x, x.y);
    __nv_bfloat162 p1 = __floats2bfloat162_rn(x.z, x.w);
    __nv_bfloat162 p2 = __floats2bfloat162_rn(y.x, y.y);
    __nv_bfloat162 p3 = __floats2bfloat162_rn(y.z, y.w);
    return make_uint4(*(uint32_t*)&p0, *(uint32_t*)&p1, *(uint32_t*)&p2, *(uint32_t*)&p3);
}
__device__ __forceinline__ float sigf(float x) { return 1.f / (1.f + expf(-x)); }

// ---------------- shared HMMA mainloop (CTA tile 64x128, 8 warps) ----------------
// acc = [sum over nA segments] A_j[64rows,256] @ B_seg[256,128]
// B is [nA*256, 256] row-major; step s uses rows s*32..s*32+31, cols n0..n0+127.
// smem per buffer 12KB: A 4KB (64x64B) @0, B 8KB (32x256B) @4096. double-buffered.
__device__ __forceinline__ void mma_loop(
    const float* __restrict__ A0, const float* __restrict__ A1, const float* __restrict__ A2,
    const float* __restrict__ Bw, int nA, int m0, int n0,
    uint8_t* sm, uint32_t smBase, float (*acc)[4][4]) {
    int tid = threadIdx.x;
    int wid = tid >> 5, lane = tid & 31;
    int wm = wid >> 2, wn = wid & 3;            // warp grid 2 x 4, warp tile 32x32
    int mA = tid >> 2, cA = tid & 3;            // A: row mA (0..63), chunk cA
    int kB = tid >> 4, cB = tid & 15;           // B: rows kB, kB+16; chunk cB

    uint32_t offA0 = (uint32_t)(mA * 64 + ((cA ^ ((mA >> 1) & 3)) << 4));
    uint32_t offB0 = 4096u + (uint32_t)(kB * 256 + ((cB ^ (kB & 7)) << 4));
    uint32_t offB1 = offB0 + 4096u;

    int lr = lane & 7, lh = (lane >> 3) & 1, lq = lane >> 4;
    int arow_base = wm * 32 + lh * 8 + lr;      // + mi*16, mi 0..1
    int brow_base = lh * 8 + lr;

    int totalS = nA * 8;
    float4 ra[2], rb[4];

    // prefetch step 0
    {
        const float* p = A0 + (size_t)(m0 + mA) * 256 + cA * 8;
        ra[0] = ((const float4*)p)[0]; ra[1] = ((const float4*)p)[1];
        const float* r = Bw + (size_t)kB * 256 + n0 + cB * 8;
        rb[0] = ((const float4*)r)[0]; rb[1] = ((const float4*)r)[1];
        const float* t = r + 16 * 256;
        rb[2] = ((const float4*)t)[0]; rb[3] = ((const float4*)t)[1];
    }

    uint32_t bo = 0;
#pragma unroll 1
    for (int s = 0; s < totalS; s++) {
        *(uint4*)(sm + bo + offA0) = cvt8_bf16(ra[0], ra[1]);
        *(uint4*)(sm + bo + offB0) = cvt8_bf16(rb[0], rb[1]);
        *(uint4*)(sm + bo + offB1) = cvt8_bf16(rb[2], rb[3]);
        __syncthreads();
        if (s < totalS - 1) {
            int sn = s + 1;
            const float* Aj = (sn >> 3) == 0 ? A0 : ((sn >> 3) == 1 ? A1 : A2);
            const float* p = Aj + (size_t)(m0 + mA) * 256 + ((sn & 7) * 32) + cA * 8;
            ra[0] = ((const float4*)p)[0]; ra[1] = ((const float4*)p)[1];
            const float* r = Bw + (size_t)(sn * 32 + kB) * 256 + n0 + cB * 8;
            rb[0] = ((const float4*)r)[0]; rb[1] = ((const float4*)r)[1];
            const float* t = r + 16 * 256;
            rb[2] = ((const float4*)t)[0]; rb[3] = ((const float4*)t)[1];
        }
#pragma unroll
        for (int k16 = 0; k16 < 2; k16++) {
            uint32_t afr[2][4];
#pragma unroll
            for (int mi = 0; mi < 2; mi++) {
                int row = arow_base + mi * 16;
                int c = k16 * 2 + lq;
                uint32_t addr = smBase + bo + (uint32_t)(row * 64 + ((c ^ ((row >> 1) & 3)) << 4));
                LDSM_X4(afr[mi][0], afr[mi][1], afr[mi][2], afr[mi][3], addr);
            }
            uint32_t bfr[2][4];
#pragma unroll
            for (int g = 0; g < 2; g++) {
                int rowk = k16 * 16 + brow_base;
                int c = wn * 4 + g * 2 + lq;
                uint32_t addr = smBase + bo + 4096u + (uint32_t)(rowk * 256 + ((c ^ (rowk & 7)) << 4));
                LDSM_X4_T(bfr[g][0], bfr[g][1], bfr[g][2], bfr[g][3], addr);
            }
#pragma unroll
            for (int mi = 0; mi < 2; mi++)
#pragma unroll
                for (int j = 0; j < 4; j++)
                    MMA16816(acc[mi][j], afr[mi], bfr[j >> 1][(j & 1) * 2], bfr[j >> 1][(j & 1) * 2 + 1]);
        }
        bo ^= 12288u;
        if (s < totalS - 1) __syncthreads();
    }
}

// ---------------- fused GEMM: C = epi( concat(A0..A_{nA-1}) @ Bw + bias [+pos] ) ----
// mode 0: C = t (+pos)   mode 1: r=sig(t); C = r*E0 + (1-r)*E1   mode 2: C = E0 + sig(t)*E1
// grid (2, M/64)
__global__ void __launch_bounds__(256, 2)
k_gemm_f(const float* __restrict__ A0, const float* __restrict__ A1,
         const float* __restrict__ A2, const float* __restrict__ Bw,
         const float* __restrict__ bias, const float* __restrict__ E0,
         const float* __restrict__ E1, const float* __restrict__ pos,
         float* __restrict__ C, int nA, int mode, int posRows) {
    __shared__ __align__(16) uint8_t sm[24576];
    uint32_t smBase = smem_u32(sm);
    int m0 = blockIdx.y * 64, n0 = blockIdx.x * 128;

    float acc[2][4][4] = {};
    mma_loop(A0, A1, A2, Bw, nA, m0, n0, sm, smBase, acc);

    int lane = threadIdx.x & 31, wid = threadIdx.x >> 5;
    int wm = wid >> 2, wn = wid & 3;
    int gid = lane >> 2, tig = lane & 3;
#pragma unroll
    for (int mi = 0; mi < 2; mi++) {
#pragma unroll
        for (int j = 0; j < 4; j++) {
            int row = m0 + wm * 32 + mi * 16 + gid;
            int col = n0 + wn * 32 + j * 8 + tig * 2;
            float t0 = acc[mi][j][0], t1 = acc[mi][j][1];
            float t2 = acc[mi][j][2], t3 = acc[mi][j][3];
            float bb0 = 0.f, bb1 = 0.f;
            if (bias) { bb0 = bias[col]; bb1 = bias[col + 1]; }
            t0 += bb0; t1 += bb1; t2 += bb0; t3 += bb1;
            size_t o0 = (size_t)row * 256 + col;
            size_t o1 = (size_t)(row + 8) * 256 + col;
            float v0, v1, v2, v3;
            if (mode == 0) {
                if (pos) {
                    const float* p0 = pos + (size_t)(row % posRows) * 256 + col;
                    const float* p1 = pos + (size_t)((row + 8) % posRows) * 256 + col;
                    t0 += p0[0]; t1 += p0[1]; t2 += p1[0]; t3 += p1[1];
                }
                v0 = t0; v1 = t1; v2 = t2; v3 = t3;
            } else {
                float e0 = E0[o0], e1 = E0[o0 + 1], e2 = E0[o1], e3 = E0[o1 + 1];
                float f0 = E1[o0], f1 = E1[o0 + 1], f2 = E1[o1], f3 = E1[o1 + 1];
                if (mode == 1) {
                    float r0 = sigf(t0), r1 = sigf(t1), r2 = sigf(t2), r3 = sigf(t3);
                    v0 = r0 * e0 + (1.f - r0) * f0; v1 = r1 * e1 + (1.f - r1) * f1;
                    v2 = r2 * e2 + (1.f - r2) * f2; v3 = r3 * e3 + (1.f - r3) * f3;
                } else {
                    v0 = e0 + sigf(t0) * f0; v1 = e1 + sigf(t1) * f1;
                    v2 = e2 + sigf(t2) * f2; v3 = e3 + sigf(t3) * f3;
                }
            }
            C[o0] = v0; C[o0 + 1] = v1;
            C[o1] = v2; C[o1 + 1] = v3;
        }
    }
}

// ---------------- fused gates GEMM: grid (6, M/64) ----------------
// C0 = sigmoid(-(A@W0 + G0)), C1 = sigmoid(A@W1 + G1), C2 = sigmoid(A@W2 + G2)
__global__ void __launch_bounds__(256, 2)
k_gates3(const float* __restrict__ A, const float* __restrict__ W0,
         const float* __restrict__ W1, const float* __restrict__ W2,
         const float* __restrict__ G0, const float* __restrict__ G1,
         const float* __restrict__ G2, float* __restrict__ C0,
         float* __restrict__ C1, float* __restrict__ C2, int rowsPerBatch) {
    __shared__ __align__(16) uint8_t sm[24576];
    uint32_t smBase = smem_u32(sm);
    int j3 = blockIdx.x >> 1;
    int n0 = (blockIdx.x & 1) * 128;
    int m0 = blockIdx.y * 64;
    const float* Bw = j3 == 0 ? W0 : (j3 == 1 ? W1 : W2);
    const float* Gb = j3 == 0 ? G0 : (j3 == 1 ? G1 : G2);
    float* C = j3 == 0 ? C0 : (j3 == 1 ? C1 : C2);

    float acc[2][4][4] = {};
    mma_loop(A, A, A, Bw, 1, m0, n0, sm, smBase, acc);

    int lane = threadIdx.x & 31, wid = threadIdx.x >> 5;
    int wm = wid >> 2, wn = wid & 3;
    int gid = lane >> 2, tig = lane & 3;
    int batch = m0 / rowsPerBatch;
    float sgn = (j3 == 0) ? -1.f : 1.f;
#pragma unroll
    for (int mi = 0; mi < 2; mi++) {
#pragma unroll
        for (int j = 0; j < 4; j++) {
            int row = m0 + wm * 32 + mi * 16 + gid;
            int col = n0 + wn * 32 + j * 8 + tig * 2;
            float bb0 = Gb[batch * 256 + col], bb1 = Gb[batch * 256 + col + 1];
            float v0 = sigf(sgn * (acc[mi][j][0] + bb0));
            float v1 = sigf(sgn * (acc[mi][j][1] + bb1));
            float v2 = sigf(sgn * (acc[mi][j][2] + bb0));
            float v3 = sigf(sgn * (acc[mi][j][3] + bb1));
            size_t o0 = (size_t)row * 256 + col;
            size_t o1 = (size_t)(row + 8) * 256 + col;
            C[o0] = v0; C[o0 + 1] = v1;
            C[o1] = v2; C[o1 + 1] = v3;
        }
    }
}

// ---------------- elementwise / scan kernels ----------------

__global__ void k_transpose(const float* __restrict__ in, float* __restrict__ out,
                            int CC, int NR) {
    __shared__ float tile[32][33];
    int b = blockIdx.z;
    int n0 = blockIdx.x * 32, c0 = blockIdx.y * 32;
    const float* ip = in + (size_t)b * CC * NR;
    float* op = out + (size_t)b * CC * NR;
    for (int i = threadIdx.y; i < 32; i += 8)
        tile[i][threadIdx.x] = ip[(size_t)(c0 + i) * NR + n0 + threadIdx.x];
    __syncthreads();
    for (int i = threadIdx.y; i < 32; i += 8)
        op[(size_t)(n0 + i) * CC + c0 + threadIdx.x] = tile[threadIdx.x][i];
}

__device__ __forceinline__ int resize_taps(int i, int IS, int OS, int* jj, float* ww) {
    float inv = (float)IS / (float)OS;
    float dil = inv > 1.f ? inv : 1.f;
    float s = (i + 0.5f) * inv - 0.5f;
    int lo = (int)floorf(s - dil);
    int hi = (int)ceilf(s + dil);
    int n = 0; float tot = 0.f;
    for (int j = lo; j <= hi; j++) {
        if (j < 0 || j >= IS) continue;
        float w = 1.f - fabsf(s - (float)j) / dil;
        if (w <= 0.f) continue;
        jj[n] = j; ww[n] = w; tot += w; n++;
    }
    float r = 1.f / tot;
    for (int t = 0; t < n; t++) ww[t] *= r;
    return n;
}

__global__ void k_pos_embed(const float* __restrict__ pos, float* __restrict__ out,
                            int OH, int OW) {
    int c = threadIdx.x;
    int n = blockIdx.x;
    int h = n / OW, w = n % OW;
    int jy[8], jx[8]; float wy[8], wx[8];
    int ny = resize_taps(h, 32, OH, jy, wy);
    int nx = resize_taps(w, 32, OW, jx, wx);
    float acc = 0.f;
    for (int a = 0; a < ny; a++)
        for (int b2 = 0; b2 < nx; b2++)
            acc += wy[a] * wx[b2] * pos[c * 1024 + jy[a] * 32 + jx[b2]];
    out[(size_t)n * CH + c] = acc;
}

__global__ void k_colsum(const float* __restrict__ u, float* __restrict__ part,
                         int rowsTotal, int rowsPerBlock, int nch) {
    int b = blockIdx.y, c = threadIdx.x, chn = blockIdx.x;
    const float* p = u + ((size_t)b * rowsTotal + (size_t)chn * rowsPerBlock) * CH + c;
    float s = 0.f;
    for (int r = 0; r < rowsPerBlock; r++) s += p[(size_t)r * CH];
    part[((size_t)b * nch + chn) * CH + c] = s;
}

__global__ void k_ln_ctx(const float* __restrict__ part, int nch, float invN,
                         const float* __restrict__ g, const float* __restrict__ be,
                         float* __restrict__ cbar) {
    __shared__ float red[256];
    int b = blockIdx.x, c = threadIdx.x;
    float v = 0.f;
    for (int chn = 0; chn < nch; chn++) v += part[((size_t)b * nch + chn) * CH + c];
    v *= invN;
    red[c] = v; __syncthreads();
    for (int s = 128; s > 0; s >>= 1) { if (c < s) red[c] += red[c + s]; __syncthreads(); }
    float m = red[0] / CH; __syncthreads();
    float d = v - m;
    red[c] = d * d; __syncthreads();
    for (int s = 128; s > 0; s >>= 1) { if (c < s) red[c] += red[c + s]; __syncthreads(); }
    float var = red[0] / CH;
    cbar[b * CH + c] = d * rsqrtf(var + 1e-5f) * g[c] + be[c];
}

__global__ void k_gate_bias(const float* __restrict__ cbar, const float* __restrict__ Wlow,
                            const float* __restrict__ bias, float* __restrict__ out) {
    __shared__ float cs[256];
    int b = blockIdx.x, j = threadIdx.x;
    cs[j] = cbar[b * CH + j];
    __syncthreads();
    float s = bias[j];
    for (int c = 0; c < CH; c++) s += cs[c] * Wlow[c * CH + j];
    out[b * CH + j] = s;
}

__global__ void k_scan_pass1(const float* __restrict__ GA, const float* __restrict__ GW,
                             const float* __restrict__ U,
                             float* __restrict__ AF, float* __restrict__ BF,
                             float* __restrict__ ABc, float* __restrict__ BBc,
                             int rows, int nchunk) {
    int b = blockIdx.y, chn = blockIdx.x, c = threadIdx.x;
    int L = rows / nchunk;
    size_t base = ((size_t)b * rows + (size_t)chn * L) * CH + c;
    float Af = 1.f, Bf = 0.f;
    for (int i = 0; i < L; i++) {
        size_t o = base + (size_t)i * CH;
        float a = GA[o];
        float bb = (1.f - a) * GW[o] * U[o];
        Af *= a; Bf = a * Bf + bb;
    }
    float Ab = 1.f, Bb = 0.f;
    for (int i = L - 1; i >= 0; i--) {
        size_t o = base + (size_t)i * CH;
        float a = GA[o];
        float bb = (1.f - a) * GW[o] * U[o];
        Ab *= a; Bb = a * Bb + bb;
    }
    size_t co = ((size_t)b * nchunk + chn) * CH + c;
    AF[co] = Af; BF[co] = Bf; ABc[co] = Ab; BBc[co] = Bb;
}

__global__ void k_scan_pass2(const float* __restrict__ AF, const float* __restrict__ BF,
                             const float* __restrict__ ABc, const float* __restrict__ BBc,
                             float* __restrict__ SF, float* __restrict__ SB, int nchunk) {
    int b = blockIdx.x, c = threadIdx.x;
    float s = 0.f;
    for (int chn = 0; chn < nchunk; chn++) {
        size_t o = ((size_t)b * nchunk + chn) * CH + c;
        SF[o] = s; s = AF[o] * s + BF[o];
    }
    float sb = 0.f;
    for (int chn = nchunk - 1; chn >= 0; chn--) {
        size_t o = ((size_t)b * nchunk + chn) * CH + c;
        SB[o] = sb; sb = ABc[o] * sb + BBc[o];
    }
}

__global__ void k_scan_pass3(const float* __restrict__ GA, const float* __restrict__ GW,
                             const float* __restrict__ GO, const float* __restrict__ U,
                             const float* __restrict__ SF, const float* __restrict__ SB,
                             float* __restrict__ YF, float* __restrict__ YB,
                             int rows, int nchunk) {
    int b = blockIdx.y, chn = blockIdx.x, c = threadIdx.x;
    int L = rows / nchunk;
    size_t base = ((size_t)b * rows + (size_t)chn * L) * CH + c;
    size_t co = ((size_t)b * nchunk + chn) * CH + c;
    float s = SF[co];
    for (int i = 0; i < L; i++) {
        size_t o = base + (size_t)i * CH;
        float a = GA[o], u = U[o], ov = GO[o];
        float bb = (1.f - a) * GW[o] * u;
        s = a * s + bb;
        YF[o] = ov * s + (1.f - ov) * u;
    }
    float sb = SB[co];
    for (int i = L - 1; i >= 0; i--) {
        size_t o = base + (size_t)i * CH;
        float a = GA[o], u = U[o], ov = GO[o];
        float bb = (1.f - a) * GW[o] * u;
        sb = a * sb + bb;
        YB[o] = ov * sb + (1.f - ov) * u;
    }
}

__global__ void k_pool(const float* __restrict__ x, float* __restrict__ xg) {
    int i = blockIdx.x * blockDim.x + threadIdx.x;
    if (i >= BSZ * CH * NG) return;
    int gx = i % GH; int gy = (i / GH) % GH; int bc = i / NG;
    const float* p = x + (size_t)bc * NN + (gy * 4) * 64 + gx * 4;
    float s = 0.f;
#pragma unroll
    for (int dy = 0; dy < 4; dy++)
#pragma unroll
        for (int dx = 0; dx < 4; dx++) s += p[dy * 64 + dx];
    xg[i] = s * 0.0625f;
}

__global__ void k_upsample(const float* __restrict__ yg, float* __restrict__ out) {
    int c = threadIdx.x;
    int n = blockIdx.x;
    int b = blockIdx.y;
    int h = n >> 6, w = n & 63;
    float sy = (h + 0.5f) * 0.25f - 0.5f;
    float sx = (w + 0.5f) * 0.25f - 0.5f;
    int y0 = (int)floorf(sy); float fy = sy - y0;
    int x0 = (int)floorf(sx); float fx = sx - x0;
    int y0c = min(max(y0, 0), 15), y1c = min(max(y0 + 1, 0), 15);
    int x0c = min(max(x0, 0), 15), x1c = min(max(x0 + 1, 0), 15);
    const float* p = yg + (size_t)b * NG * CH + c;
    float v00 = p[(size_t)(y0c * 16 + x0c) * CH];
    float v01 = p[(size_t)(y0c * 16 + x1c) * CH];
    float v10 = p[(size_t)(y1c * 16 + x0c) * CH];
    float v11 = p[(size_t)(y1c * 16 + x1c) * CH];
    out[((size_t)b * NN + n) * CH + c] =
        (1.f - fy) * ((1.f - fx) * v00 + fx * v01) + fy * ((1.f - fx) * v10 + fx * v11);
}

__global__ void k_dwconv(const float* __restrict__ x, const float* __restrict__ wt,
                         const float* __restrict__ bs, float* __restrict__ out) {
    int i = blockIdx.x * blockDim.x + threadIdx.x;
    if (i >= BSZ * CH * NN) return;
    int wp = i & 63;
    int h = (i >> 6) & 63;
    int cc = (i >> 12) & 255;
    const float* xp = x + (size_t)(i - wp - h * 64);
    const float* kp = wt + cc * 9;
    float s = bs[cc];
#pragma unroll
    for (int dy = -1; dy <= 1; dy++) {
        int yy = h + dy; if (yy < 0 || yy >= 64) continue;
#pragma unroll
        for (int dx = -1; dx <= 1; dx++) {
            int xx = wp + dx; if (xx < 0 || xx >= 64) continue;
            s += xp[yy * 64 + xx] * kp[(dy + 1) * 3 + (dx + 1)];
        }
    }
    out[i] = s;
}

__global__ void k_final(const float* __restrict__ x, const float* __restrict__ P,
                        float* __restrict__ out) {
    __shared__ float tile[32][33];
    int b = blockIdx.z;
    int n0 = blockIdx.x * 32, c0 = blockIdx.y * 32;
    const float* pp = P + (size_t)b * NN * CH;
    for (int i = threadIdx.y; i < 32; i += 8)
        tile[i][threadIdx.x] = pp[(size_t)(n0 + i) * CH + c0 + threadIdx.x];
    __syncthreads();
    const float* xp = x + (size_t)b * CH * NN;
    float* op = out + (size_t)b * CH * NN;
    for (int i = threadIdx.y; i < 32; i += 8)
        op[(size_t)(c0 + i) * NN + n0 + threadIdx.x] =
            xp[(size_t)(c0 + i) * NN + n0 + threadIdx.x] + tile[threadIdx.x][i];
}

// ---------------- host orchestration ----------------
static float* gsym(const void* sym) {
    void* p = nullptr;
    cudaGetSymbolAddress(&p, sym);
    return (float*)p;
}

extern "C" void kernel_launch(void* const* d_in, const int* in_sizes, int n_in,
                              void* d_out, int out_size) {
    const float* x    = (const float*)d_in[0];
    const float* Wt   = (const float*)d_in[1];
    const float* bt   = (const float*)d_in[2];
    const float* posf = (const float*)d_in[3];
    const float* posg = (const float*)d_in[4];
    const float* lng  = (const float*)d_in[5];
    const float* lnb  = (const float*)d_in[6];
    const float* Wf   = (const float*)d_in[7];
    const float* bf   = (const float*)d_in[8];
    const float* Ww_  = (const float*)d_in[9];
    const float* bw   = (const float*)d_in[10];
    const float* Wo   = (const float*)d_in[11];
    const float* bo   = (const float*)d_in[12];
    const float* Wr   = (const float*)d_in[13];
    const float* br   = (const float*)d_in[14];
    const float* Wgi  = (const float*)d_in[15];
    const float* bgi  = (const float*)d_in[16];
    const float* dww  = (const float*)d_in[17];
    const float* dwb  = (const float*)d_in[18];
    const float* Wl   = (const float*)d_in[19];
    const float* bl   = (const float*)d_in[20];
    const float* Wlf  = (const float*)d_in[21];
    const float* blf  = (const float*)d_in[22];
    const float* Wout = (const float*)d_in[23];
    const float* bout = (const float*)d_in[24];
    float* out = (float*)d_out;

    float *SEQ = gsym(d_SEQ), *U = gsym(d_U), *GA = gsym(d_GA), *GW = gsym(d_GB),
          *GO = gsym(d_GO), *YF = gsym(d_YF), *YB = gsym(d_YB), *Y = gsym(d_Y),
          *YG = gsym(d_YG), *T0 = gsym(d_T0);
    float *PF = gsym(d_PF), *PG = gsym(d_PG), *XG = gsym(d_XG), *SEQG = gsym(d_SEQG),
          *UG = gsym(d_UG), *AG = gsym(d_AG), *BG = gsym(d_BG), *OG = gsym(d_OG),
          *YGS = gsym(d_YGS), *YGB = gsym(d_YGB);
    float *PART = gsym(d_PART), *CBAR = gsym(d_CBAR), *GBF = gsym(d_GBF),
          *GBW = gsym(d_GBW), *GBO = gsym(d_GBO);
    float *AF = gsym(d_AF), *BF = gsym(d_BF), *ABc = gsym(d_ABc), *BBc = gsym(d_BBc),
          *SF = gsym(d_SF), *SB = gsym(d_SB);

    dim3 tb(32, 8);
    dim3 gF(2, M_FINE / 64);    // fine GEMM (1024 CTAs)
    dim3 gG(2, M_GLOB / 64);    // glob GEMM
    dim3 gF3(6, M_FINE / 64);   // fine gates
    dim3 gG3(6, M_GLOB / 64);   // glob gates

    // ---- fine sequence ----
    k_transpose<<<dim3(NN / 32, CH / 32, BSZ), tb>>>(x, SEQ, CH, NN);
    k_pos_embed<<<NN, 256>>>(posf, PF, HH, WW);
    k_pos_embed<<<NG, 256>>>(posg, PG, GH, GH);

    // u = seq @ Wt + bt + pos
    k_gemm_f<<<gF, 256>>>(SEQ, nullptr, nullptr, Wt, bt, nullptr, nullptr, PF, U, 1, 0, NN);

    // context + gate biases
    k_colsum<<<dim3(32, BSZ), 256>>>(U, PART, NN, 128, 32);
    k_ln_ctx<<<BSZ, 256>>>(PART, 32, 1.f / NN, lng, lnb, CBAR);
    k_gate_bias<<<BSZ, 256>>>(CBAR, Wf + 256 * 256, bf, GBF);
    k_gate_bias<<<BSZ, 256>>>(CBAR, Ww_ + 256 * 256, bw, GBW);
    k_gate_bias<<<BSZ, 256>>>(CBAR, Wo + 256 * 256, bo, GBO);

    // gates: a, g, o (b computed inline in scans)
    k_gates3<<<gF3, 256>>>(U, Wf, Ww_, Wo, GBF, GBW, GBO, GA, GW, GO, NN);

    // bidirectional chunked scan
    k_scan_pass1<<<dim3(NCHUNK, BSZ), 256>>>(GA, GW, U, AF, BF, ABc, BBc, NN, NCHUNK);
    k_scan_pass2<<<BSZ, 256>>>(AF, BF, ABc, BBc, SF, SB, NCHUNK);
    k_scan_pass3<<<dim3(NCHUNK, BSZ), 256>>>(GA, GW, GO, U, SF, SB, YF, YB, NN, NCHUNK);

    // rho mix fused: Y = sig(t)*YF + (1-sig)*YB, t = [U,YF,YB]@Wr + br
    k_gemm_f<<<gF, 256>>>(U, YF, YB, Wr, br, YF, YB, nullptr, Y, 3, 1, NN);

    // ---- global branch ----
    k_pool<<<(BSZ * CH * NG + 255) / 256, 256>>>(x, XG);
    k_transpose<<<dim3(NG / 32, CH / 32, BSZ), tb>>>(XG, SEQG, CH, NG);
    k_gemm_f<<<gG, 256>>>(SEQG, nullptr, nullptr, Wt, bt, nullptr, nullptr, PG, UG, 1, 0, NG);

    k_colsum<<<dim3(2, BSZ), 256>>>(UG, PART, NG, 128, 2);
    k_ln_ctx<<<BSZ, 256>>>(PART, 2, 1.f / NG, lng, lnb, CBAR);
    k_gate_bias<<<BSZ, 256>>>(CBAR, Wf + 256 * 256, bf, GBF);
    k_gate_bias<<<BSZ, 256>>>(CBAR, Ww_ + 256 * 256, bw, GBW);
    k_gate_bias<<<BSZ, 256>>>(CBAR, Wo + 256 * 256, bo, GBO);

    k_gates3<<<gG3, 256>>>(UG, Wf, Ww_, Wo, GBF, GBW, GBO, AG, BG, OG, NG);

    k_scan_pass1<<<dim3(NCHUNK_G, BSZ), 256>>>(AG, BG, UG, AF, BF, ABc, BBc, NG, NCHUNK_G);
    k_scan_pass2<<<BSZ, 256>>>(AF, BF, ABc, BBc, SF, SB, NCHUNK_G);
    k_scan_pass3<<<dim3(NCHUNK_G, BSZ), 256>>>(AG, BG, OG, UG, SF, SB, YGS, YGB, NG, NCHUNK_G);

    k_upsample<<<dim3(NN, BSZ), 256>>>(YGS, YG);

    // lam fused: T0 := z = Y + sig(t)*YG, t = [Y,YG,U]@Wgi + bgi
    k_gemm_f<<<gF, 256>>>(Y, YG, U, Wgi, bgi, Y, YG, nullptr, T0, 3, 2, NN);

    // ---- local depthwise conv branch ----
    k_dwconv<<<(BSZ * CH * NN + 255) / 256, 256>>>(x, dww, dwb, SEQ);
    k_transpose<<<dim3(NN / 32, CH / 32, BSZ), tb>>>(SEQ, YF, CH, NN);
    // v = convseq @ Wl + bl  -> GA
    k_gemm_f<<<gF, 256>>>(YF, nullptr, nullptr, Wl, bl, nullptr, nullptr, nullptr, GA, 1, 0, NN);
    // eta fused: u_out = sig(t)*v + (1-sig)*z, t = [v,z]@Wlf + blf  -> GW buffer
    k_gemm_f<<<gF, 256>>>(GA, T0, nullptr, Wlf, blf, GA, T0, nullptr, GW, 2, 1, NN);
    // out projection -> U (free), then residual transpose
    k_gemm_f<<<gF, 256>>>(GW, nullptr, nullptr, Wout, bout, nullptr, nullptr, nullptr, U, 1, 0, NN);
    k_final<<<dim3(NN / 32, CH / 32, BSZ), tb>>>(x, U, out);
}

// round 8
// speedup vs baseline: 3.8993x; 1.1834x over previous
#include <cuda_runtime.h>
#include <cuda_bf16.h>
#include <math.h>
#include <stdint.h>

#define BSZ 8
#define CH 256
#define HH 64
#define WW 64
#define NN 4096
#define GH 16
#define NG 256
#define M_FINE (BSZ*NN)  // 32768
#define M_GLOB (BSZ*NG)  // 2048
#define NCHUNK 64
#define NCHUNK_G 8

typedef __nv_bfloat16 bf16;

// ---------------- scratch ----------------
__device__ float d_SEQ [M_FINE*CH];   // also reused as conv map
__device__ float d_U   [M_FINE*CH];
__device__ float d_GA  [M_FINE*CH];
__device__ float d_GB  [M_FINE*CH];
__device__ float d_GO  [M_FINE*CH];
__device__ float d_YF  [M_FINE*CH];
__device__ float d_YB  [M_FINE*CH];
__device__ float d_Y   [M_FINE*CH];
__device__ float d_YG  [M_FINE*CH];
__device__ float d_T0  [M_FINE*CH];

__device__ bf16 d_SEQ16[M_FINE*CH];
__device__ bf16 d_U16  [M_FINE*CH];
__device__ bf16 d_YF16 [M_FINE*CH];
__device__ bf16 d_YB16 [M_FINE*CH];
__device__ bf16 d_Y16  [M_FINE*CH];
__device__ bf16 d_YG16 [M_FINE*CH];
__device__ bf16 d_V16  [M_FINE*CH];
__device__ bf16 d_Z16  [M_FINE*CH];
__device__ bf16 d_UO16 [M_FINE*CH];
__device__ bf16 d_CS16 [M_FINE*CH];   // conv-seq bf16
__device__ bf16 d_SEQG16[M_GLOB*CH];
__device__ bf16 d_UG16 [M_GLOB*CH];

__device__ float d_PF  [NN*CH];
__device__ float d_PG  [NG*CH];
__device__ float d_XG  [BSZ*CH*NG];
__device__ float d_UG  [M_GLOB*CH];
__device__ float d_AG  [M_GLOB*CH];
__device__ float d_BG  [M_GLOB*CH];
__device__ float d_OG  [M_GLOB*CH];
__device__ float d_YGS [M_GLOB*CH];
__device__ float d_YGB [M_GLOB*CH];

__device__ float d_PART[BSZ*32*CH];
__device__ float d_CBAR[BSZ*CH];
__device__ float d_GBF [BSZ*CH];
__device__ float d_GBW [BSZ*CH];
__device__ float d_GBO [BSZ*CH];

__device__ float d_AF [BSZ*NCHUNK*CH];
__device__ float d_BF [BSZ*NCHUNK*CH];
__device__ float d_ABc[BSZ*NCHUNK*CH];
__device__ float d_BBc[BSZ*NCHUNK*CH];
__device__ float d_SF [BSZ*NCHUNK*CH];
__device__ float d_SB [BSZ*NCHUNK*CH];

// bf16 weight cache (segments, in elements):
#define OW_Wt   0
#define OW_Wf   65536
#define OW_Ww   131072
#define OW_Wo   196608
#define OW_Wr   262144
#define OW_Wgi  458752
#define OW_Wl   655360
#define OW_Wlf  720896
#define OW_Wout 851968
#define OW_TOT  917504
__device__ bf16 d_W16[OW_TOT];

// ---------------- asm helpers ----------------
__device__ __forceinline__ uint32_t smem_u32(const void* p) {
    uint32_t a;
    asm("{ .reg .u64 t; cvta.to.shared.u64 t, %1; cvt.u32.u64 %0, t; }" : "=r"(a) : "l"(p));
    return a;
}
#define LDSM_X4(r0, r1, r2, r3, addr) \
    asm volatile("ldmatrix.sync.aligned.m8n8.x4.shared.b16 {%0,%1,%2,%3}, [%4];" \
                 : "=r"(r0), "=r"(r1), "=r"(r2), "=r"(r3) : "r"(addr))
#define LDSM_X4_T(r0, r1, r2, r3, addr) \
    asm volatile("ldmatrix.sync.aligned.m8n8.x4.trans.shared.b16 {%0,%1,%2,%3}, [%4];" \
                 : "=r"(r0), "=r"(r1), "=r"(r2), "=r"(r3) : "r"(addr))
#define MMA16816(d, a, b0, b1) \
    asm volatile("mma.sync.aligned.m16n8k16.row.col.f32.bf16.bf16.f32 " \
                 "{%0,%1,%2,%3}, {%4,%5,%6,%7}, {%8,%9}, {%0,%1,%2,%3};" \
                 : "+f"((d)[0]), "+f"((d)[1]), "+f"((d)[2]), "+f"((d)[3]) \
                 : "r"((a)[0]), "r"((a)[1]), "r"((a)[2]), "r"((a)[3]), "r"(b0), "r"(b1))
#define CPA16(dst, src) \
    asm volatile("cp.async.cg.shared.global [%0], [%1], 16;" :: "r"(dst), "l"(src))
#define CPA_COMMIT() asm volatile("cp.async.commit_group;" ::: "memory")
#define CPA_WAIT(n)  asm volatile("cp.async.wait_group %0;" :: "n"(n) : "memory")

__device__ __forceinline__ float sigf(float x) { return 1.f / (1.f + expf(-x)); }

// ---------------- cp.async HMMA mainloop (CTA tile 64x128, 4 stages) ----------------
// acc = sum_j A_j[64,256] @ Bseg[256,128]; A,B bf16.
// stage = 12KB: A 4KB (64x64B swz) @0, B 8KB (32x256B swz) @4096. 4 stages = 48KB.
__device__ __forceinline__ void mma_loop(
    const bf16* __restrict__ A0, const bf16* __restrict__ A1, const bf16* __restrict__ A2,
    const bf16* __restrict__ Bw, int nA, int m0, int n0,
    uint32_t smBase, float (*acc)[4][4]) {
    int tid = threadIdx.x;
    int wid = tid >> 5, lane = tid & 31;
    int wm = wid >> 2, wn = wid & 3;
    int mA = tid >> 2, cA = tid & 3;
    int kB = tid >> 4, cB = tid & 15;

    uint32_t offA  = (uint32_t)(mA * 64 + ((cA ^ ((mA >> 1) & 3)) << 4));
    uint32_t offB0 = 4096u + (uint32_t)(kB * 256 + ((cB ^ (kB & 7)) << 4));
    uint32_t offB1 = offB0 + 4096u;

    int lr = lane & 7, lh = (lane >> 3) & 1, lq = lane >> 4;
    int arow_base = wm * 32 + lh * 8 + lr;
    int brow_base = lh * 8 + lr;

    int totalS = nA * 8;

    const bf16* aSrc = A0 + (size_t)(m0 + mA) * 256 + cA * 8;
    const bf16* a1Src = A1 ? A1 + (size_t)(m0 + mA) * 256 + cA * 8 : nullptr;
    const bf16* a2Src = A2 ? A2 + (size_t)(m0 + mA) * 256 + cA * 8 : nullptr;
    const bf16* bSrc = Bw + (size_t)kB * 256 + n0 + cB * 8;

#define ISSUE(s) do { \
        uint32_t slot = smBase + ((uint32_t)(s) & 3u) * 12288u; \
        const bf16* pa = ((s) >> 3) == 0 ? aSrc : (((s) >> 3) == 1 ? a1Src : a2Src); \
        CPA16(slot + offA, pa + ((s) & 7) * 32); \
        const bf16* pb = bSrc + (size_t)(s) * 32 * 256; \
        CPA16(slot + offB0, pb); \
        CPA16(slot + offB1, pb + 16 * 256); \
        CPA_COMMIT(); \
    } while (0)

    ISSUE(0); ISSUE(1); ISSUE(2);

#pragma unroll 1
    for (int s = 0; s < totalS; s++) {
        if (s + 3 < totalS) ISSUE(s + 3);
        int rem = totalS - 1 - s;
        if (rem >= 3) CPA_WAIT(3);
        else if (rem == 2) CPA_WAIT(2);
        else if (rem == 1) CPA_WAIT(1);
        else CPA_WAIT(0);
        __syncthreads();
        uint32_t bo = smBase + ((uint32_t)s & 3u) * 12288u;
#pragma unroll
        for (int k16 = 0; k16 < 2; k16++) {
            uint32_t afr[2][4];
#pragma unroll
            for (int mi = 0; mi < 2; mi++) {
                int row = arow_base + mi * 16;
                int c = k16 * 2 + lq;
                uint32_t addr = bo + (uint32_t)(row * 64 + ((c ^ ((row >> 1) & 3)) << 4));
                LDSM_X4(afr[mi][0], afr[mi][1], afr[mi][2], afr[mi][3], addr);
            }
            uint32_t bfr[2][4];
#pragma unroll
            for (int g = 0; g < 2; g++) {
                int rowk = k16 * 16 + brow_base;
                int c = wn * 4 + g * 2 + lq;
                uint32_t addr = bo + 4096u + (uint32_t)(rowk * 256 + ((c ^ (rowk & 7)) << 4));
                LDSM_X4_T(bfr[g][0], bfr[g][1], bfr[g][2], bfr[g][3], addr);
            }
#pragma unroll
            for (int mi = 0; mi < 2; mi++)
#pragma unroll
                for (int j = 0; j < 4; j++)
                    MMA16816(acc[mi][j], afr[mi], bfr[j >> 1][(j & 1) * 2], bfr[j >> 1][(j & 1) * 2 + 1]);
        }
        __syncthreads();
    }
#undef ISSUE
}

// ---------------- fused GEMM ----------------
// mode 0: C = t (+pos)   mode 1: r=sig(t); C = r*E0+(1-r)*E1   mode 2: C = E0 + sig(t)*E1
// C16 (optional) gets bf16 copy of C. grid (2, M/64)
__global__ void __launch_bounds__(256, 2)
k_gemm_f(const bf16* __restrict__ A0, const bf16* __restrict__ A1,
         const bf16* __restrict__ A2, const bf16* __restrict__ Bw,
         const float* __restrict__ bias, const float* __restrict__ E0,
         const float* __restrict__ E1, const float* __restrict__ pos,
         float* __restrict__ C, bf16* __restrict__ C16,
         int nA, int mode, int posRows) {
    __shared__ __align__(16) uint8_t sm[49152];
    uint32_t smBase = smem_u32(sm);
    int m0 = blockIdx.y * 64, n0 = blockIdx.x * 128;

    float acc[2][4][4] = {};
    mma_loop(A0, A1, A2, Bw, nA, m0, n0, smBase, acc);

    int lane = threadIdx.x & 31, wid = threadIdx.x >> 5;
    int wm = wid >> 2, wn = wid & 3;
    int gid = lane >> 2, tig = lane & 3;
#pragma unroll
    for (int mi = 0; mi < 2; mi++) {
#pragma unroll
        for (int j = 0; j < 4; j++) {
            int row = m0 + wm * 32 + mi * 16 + gid;
            int col = n0 + wn * 32 + j * 8 + tig * 2;
            float t0 = acc[mi][j][0], t1 = acc[mi][j][1];
            float t2 = acc[mi][j][2], t3 = acc[mi][j][3];
            float bb0 = 0.f, bb1 = 0.f;
            if (bias) { bb0 = bias[col]; bb1 = bias[col + 1]; }
            t0 += bb0; t1 += bb1; t2 += bb0; t3 += bb1;
            size_t o0 = (size_t)row * 256 + col;
            size_t o1 = (size_t)(row + 8) * 256 + col;
            float v0, v1, v2, v3;
            if (mode == 0) {
                if (pos) {
                    const float* p0 = pos + (size_t)(row % posRows) * 256 + col;
                    const float* p1 = pos + (size_t)((row + 8) % posRows) * 256 + col;
                    t0 += p0[0]; t1 += p0[1]; t2 += p1[0]; t3 += p1[1];
                }
                v0 = t0; v1 = t1; v2 = t2; v3 = t3;
            } else {
                float e0 = E0[o0], e1 = E0[o0 + 1], e2 = E0[o1], e3 = E0[o1 + 1];
                float f0 = E1[o0], f1 = E1[o0 + 1], f2 = E1[o1], f3 = E1[o1 + 1];
                if (mode == 1) {
                    float r0 = sigf(t0), r1 = sigf(t1), r2 = sigf(t2), r3 = sigf(t3);
                    v0 = r0 * e0 + (1.f - r0) * f0; v1 = r1 * e1 + (1.f - r1) * f1;
                    v2 = r2 * e2 + (1.f - r2) * f2; v3 = r3 * e3 + (1.f - r3) * f3;
                } else {
                    v0 = e0 + sigf(t0) * f0; v1 = e1 + sigf(t1) * f1;
                    v2 = e2 + sigf(t2) * f2; v3 = e3 + sigf(t3) * f3;
                }
            }
            C[o0] = v0; C[o0 + 1] = v1;
            C[o1] = v2; C[o1 + 1] = v3;
            if (C16) {
                *(__nv_bfloat162*)(C16 + o0) = __floats2bfloat162_rn(v0, v1);
                *(__nv_bfloat162*)(C16 + o1) = __floats2bfloat162_rn(v2, v3);
            }
        }
    }
}

// ---------------- fused gates GEMM: grid (6, M/64) ----------------
__global__ void __launch_bounds__(256, 2)
k_gates3(const bf16* __restrict__ A, const bf16* __restrict__ Wall,
         const float* __restrict__ G0, const float* __restrict__ G1,
         const float* __restrict__ G2, float* __restrict__ C0,
         float* __restrict__ C1, float* __restrict__ C2, int rowsPerBatch) {
    __shared__ __align__(16) uint8_t sm[49152];
    uint32_t smBase = smem_u32(sm);
    int j3 = blockIdx.x >> 1;
    int n0 = (blockIdx.x & 1) * 128;
    int m0 = blockIdx.y * 64;
    const bf16* Bw = Wall + (size_t)j3 * 65536;   // Wf, Ww, Wo consecutive in d_W16
    const float* Gb = j3 == 0 ? G0 : (j3 == 1 ? G1 : G2);
    float* C = j3 == 0 ? C0 : (j3 == 1 ? C1 : C2);

    float acc[2][4][4] = {};
    mma_loop(A, A, A, Bw, 1, m0, n0, smBase, acc);

    int lane = threadIdx.x & 31, wid = threadIdx.x >> 5;
    int wm = wid >> 2, wn = wid & 3;
    int gid = lane >> 2, tig = lane & 3;
    int batch = m0 / rowsPerBatch;
    float sgn = (j3 == 0) ? -1.f : 1.f;
#pragma unroll
    for (int mi = 0; mi < 2; mi++) {
#pragma unroll
        for (int j = 0; j < 4; j++) {
            int row = m0 + wm * 32 + mi * 16 + gid;
            int col = n0 + wn * 32 + j * 8 + tig * 2;
            float bb0 = Gb[batch * 256 + col], bb1 = Gb[batch * 256 + col + 1];
            float v0 = sigf(sgn * (acc[mi][j][0] + bb0));
            float v1 = sigf(sgn * (acc[mi][j][1] + bb1));
            float v2 = sigf(sgn * (acc[mi][j][2] + bb0));
            float v3 = sigf(sgn * (acc[mi][j][3] + bb1));
            size_t o0 = (size_t)row * 256 + col;
            size_t o1 = (size_t)(row + 8) * 256 + col;
            C[o0] = v0; C[o0 + 1] = v1;
            C[o1] = v2; C[o1 + 1] = v3;
        }
    }
}

// ---------------- weight conversion ----------------
__global__ void k_wcvt(const float* __restrict__ s0, const float* __restrict__ s1,
                       const float* __restrict__ s2, const float* __restrict__ s3,
                       const float* __restrict__ s4, const float* __restrict__ s5,
                       const float* __restrict__ s6, const float* __restrict__ s7,
                       const float* __restrict__ s8, bf16* __restrict__ dst) {
    int i0 = blockIdx.x * 1024 + threadIdx.x * 4;
#pragma unroll
    for (int e = 0; e < 4; e++) {
        int idx = i0 + e;
        if (idx >= OW_TOT) return;
        float v;
        if (idx < OW_Wf)        v = s0[idx - OW_Wt];
        else if (idx < OW_Ww)   v = s1[idx - OW_Wf];
        else if (idx < OW_Wo)   v = s2[idx - OW_Ww];
        else if (idx < OW_Wr)   v = s3[idx - OW_Wo];
        else if (idx < OW_Wgi)  v = s4[idx - OW_Wr];
        else if (idx < OW_Wl)   v = s5[idx - OW_Wgi];
        else if (idx < OW_Wlf)  v = s6[idx - OW_Wl];
        else if (idx < OW_Wout) v = s7[idx - OW_Wlf];
        else                    v = s8[idx - OW_Wout];
        dst[idx] = __float2bfloat16_rn(v);
    }
}

// ---------------- elementwise / scan kernels ----------------

__global__ void k_transpose(const float* __restrict__ in, float* __restrict__ out,
                            int CC, int NR) {
    __shared__ float tile[32][33];
    int b = blockIdx.z;
    int n0 = blockIdx.x * 32, c0 = blockIdx.y * 32;
    const float* ip = in + (size_t)b * CC * NR;
    float* op = out + (size_t)b * CC * NR;
    for (int i = threadIdx.y; i < 32; i += 8)
        tile[i][threadIdx.x] = ip[(size_t)(c0 + i) * NR + n0 + threadIdx.x];
    __syncthreads();
    for (int i = threadIdx.y; i < 32; i += 8)
        op[(size_t)(n0 + i) * CC + c0 + threadIdx.x] = tile[threadIdx.x][i];
}

// transpose with bf16 output
__global__ void k_transpose16(const float* __restrict__ in, bf16* __restrict__ out,
                              int CC, int NR) {
    __shared__ float tile[32][33];
    int b = blockIdx.z;
    int n0 = blockIdx.x * 32, c0 = blockIdx.y * 32;
    const float* ip = in + (size_t)b * CC * NR;
    bf16* op = out + (size_t)b * CC * NR;
    for (int i = threadIdx.y; i < 32; i += 8)
        tile[i][threadIdx.x] = ip[(size_t)(c0 + i) * NR + n0 + threadIdx.x];
    __syncthreads();
    for (int i = threadIdx.y; i < 32; i += 8)
        op[(size_t)(n0 + i) * CC + c0 + threadIdx.x] =
            __float2bfloat16_rn(tile[threadIdx.x][i]);
}

__device__ __forceinline__ int resize_taps(int i, int IS, int OS, int* jj, float* ww) {
    float inv = (float)IS / (float)OS;
    float dil = inv > 1.f ? inv : 1.f;
    float s = (i + 0.5f) * inv - 0.5f;
    int lo = (int)floorf(s - dil);
    int hi = (int)ceilf(s + dil);
    int n = 0; float tot = 0.f;
    for (int j = lo; j <= hi; j++) {
        if (j < 0 || j >= IS) continue;
        float w = 1.f - fabsf(s - (float)j) / dil;
        if (w <= 0.f) continue;
        jj[n] = j; ww[n] = w; tot += w; n++;
    }
    float r = 1.f / tot;
    for (int t = 0; t < n; t++) ww[t] *= r;
    return n;
}

__global__ void k_pos_embed(const float* __restrict__ pos, float* __restrict__ out,
                            int OH, int OW) {
    int c = threadIdx.x;
    int n = blockIdx.x;
    int h = n / OW, w = n % OW;
    int jy[8], jx[8]; float wy[8], wx[8];
    int ny = resize_taps(h, 32, OH, jy, wy);
    int nx = resize_taps(w, 32, OW, jx, wx);
    float acc = 0.f;
    for (int a = 0; a < ny; a++)
        for (int b2 = 0; b2 < nx; b2++)
            acc += wy[a] * wx[b2] * pos[c * 1024 + jy[a] * 32 + jx[b2]];
    out[(size_t)n * CH + c] = acc;
}

__global__ void k_colsum(const float* __restrict__ u, float* __restrict__ part,
                         int rowsTotal, int rowsPerBlock, int nch) {
    int b = blockIdx.y, c = threadIdx.x, chn = blockIdx.x;
    const float* p = u + ((size_t)b * rowsTotal + (size_t)chn * rowsPerBlock) * CH + c;
    float s = 0.f;
    for (int r = 0; r < rowsPerBlock; r++) s += p[(size_t)r * CH];
    part[((size_t)b * nch + chn) * CH + c] = s;
}

__global__ void k_ln_ctx(const float* __restrict__ part, int nch, float invN,
                         const float* __restrict__ g, const float* __restrict__ be,
                         float* __restrict__ cbar) {
    __shared__ float red[256];
    int b = blockIdx.x, c = threadIdx.x;
    float v = 0.f;
    for (int chn = 0; chn < nch; chn++) v += part[((size_t)b * nch + chn) * CH + c];
    v *= invN;
    red[c] = v; __syncthreads();
    for (int s = 128; s > 0; s >>= 1) { if (c < s) red[c] += red[c + s]; __syncthreads(); }
    float m = red[0] / CH; __syncthreads();
    float d = v - m;
    red[c] = d * d; __syncthreads();
    for (int s = 128; s > 0; s >>= 1) { if (c < s) red[c] += red[c + s]; __syncthreads(); }
    float var = red[0] / CH;
    cbar[b * CH + c] = d * rsqrtf(var + 1e-5f) * g[c] + be[c];
}

__global__ void k_gate_bias(const float* __restrict__ cbar, const float* __restrict__ Wlow,
                            const float* __restrict__ bias, float* __restrict__ out) {
    __shared__ float cs[256];
    int b = blockIdx.x, j = threadIdx.x;
    cs[j] = cbar[b * CH + j];
    __syncthreads();
    float s = bias[j];
    for (int c = 0; c < CH; c++) s += cs[c] * Wlow[c * CH + j];
    out[b * CH + j] = s;
}

__global__ void k_scan_pass1(const float* __restrict__ GA, const float* __restrict__ GW,
                             const float* __restrict__ U,
                             float* __restrict__ AF, float* __restrict__ BF,
                             float* __restrict__ ABc, float* __restrict__ BBc,
                             int rows, int nchunk) {
    int b = blockIdx.y, chn = blockIdx.x, c = threadIdx.x;
    int L = rows / nchunk;
    size_t base = ((size_t)b * rows + (size_t)chn * L) * CH + c;
    float Af = 1.f, Bf = 0.f;
    for (int i = 0; i < L; i++) {
        size_t o = base + (size_t)i * CH;
        float a = GA[o];
        float bb = (1.f - a) * GW[o] * U[o];
        Af *= a; Bf = a * Bf + bb;
    }
    float Ab = 1.f, Bb = 0.f;
    for (int i = L - 1; i >= 0; i--) {
        size_t o = base + (size_t)i * CH;
        float a = GA[o];
        float bb = (1.f - a) * GW[o] * U[o];
        Ab *= a; Bb = a * Bb + bb;
    }
    size_t co = ((size_t)b * nchunk + chn) * CH + c;
    AF[co] = Af; BF[co] = Bf; ABc[co] = Ab; BBc[co] = Bb;
}

__global__ void k_scan_pass2(const float* __restrict__ AF, const float* __restrict__ BF,
                             const float* __restrict__ ABc, const float* __restrict__ BBc,
                             float* __restrict__ SF, float* __restrict__ SB, int nchunk) {
    int b = blockIdx.x, c = threadIdx.x;
    float s = 0.f;
    for (int chn = 0; chn < nchunk; chn++) {
        size_t o = ((size_t)b * nchunk + chn) * CH + c;
        SF[o] = s; s = AF[o] * s + BF[o];
    }
    float sb = 0.f;
    for (int chn = nchunk - 1; chn >= 0; chn--) {
        size_t o = ((size_t)b * nchunk + chn) * CH + c;
        SB[o] = sb; sb = ABc[o] * sb + BBc[o];
    }
}

__global__ void k_scan_pass3(const float* __restrict__ GA, const float* __restrict__ GW,
                             const float* __restrict__ GO, const float* __restrict__ U,
                             const float* __restrict__ SF, const float* __restrict__ SB,
                             float* __restrict__ YF, float* __restrict__ YB,
                             bf16* __restrict__ YF16, bf16* __restrict__ YB16,
                             int rows, int nchunk) {
    int b = blockIdx.y, chn = blockIdx.x, c = threadIdx.x;
    int L = rows / nchunk;
    size_t base = ((size_t)b * rows + (size_t)chn * L) * CH + c;
    size_t co = ((size_t)b * nchunk + chn) * CH + c;
    float s = SF[co];
    for (int i = 0; i < L; i++) {
        size_t o = base + (size_t)i * CH;
        float a = GA[o], u = U[o], ov = GO[o];
        float bb = (1.f - a) * GW[o] * u;
        s = a * s + bb;
        float y = ov * s + (1.f - ov) * u;
        YF[o] = y;
        if (YF16) YF16[o] = __float2bfloat16_rn(y);
    }
    float sb = SB[co];
    for (int i = L - 1; i >= 0; i--) {
        size_t o = base + (size_t)i * CH;
        float a = GA[o], u = U[o], ov = GO[o];
        float bb = (1.f - a) * GW[o] * u;
        sb = a * sb + bb;
        float y = ov * sb + (1.f - ov) * u;
        YB[o] = y;
        if (YB16) YB16[o] = __float2bfloat16_rn(y);
    }
}

__global__ void k_pool(const float* __restrict__ x, float* __restrict__ xg) {
    int i = blockIdx.x * blockDim.x + threadIdx.x;
    if (i >= BSZ * CH * NG) return;
    int gx = i % GH; int gy = (i / GH) % GH; int bc = i / NG;
    const float* p = x + (size_t)bc * NN + (gy * 4) * 64 + gx * 4;
    float s = 0.f;
#pragma unroll
    for (int dy = 0; dy < 4; dy++)
#pragma unroll
        for (int dx = 0; dx < 4; dx++) s += p[dy * 64 + dx];
    xg[i] = s * 0.0625f;
}

__global__ void k_upsample(const float* __restrict__ yg, float* __restrict__ out,
                           bf16* __restrict__ out16) {
    int c = threadIdx.x;
    int n = blockIdx.x;
    int b = blockIdx.y;
    int h = n >> 6, w = n & 63;
    float sy = (h + 0.5f) * 0.25f - 0.5f;
    float sx = (w + 0.5f) * 0.25f - 0.5f;
    int y0 = (int)floorf(sy); float fy = sy - y0;
    int x0 = (int)floorf(sx); float fx = sx - x0;
    int y0c = min(max(y0, 0), 15), y1c = min(max(y0 + 1, 0), 15);
    int x0c = min(max(x0, 0), 15), x1c = min(max(x0 + 1, 0), 15);
    const float* p = yg + (size_t)b * NG * CH + c;
    float v00 = p[(size_t)(y0c * 16 + x0c) * CH];
    float v01 = p[(size_t)(y0c * 16 + x1c) * CH];
    float v10 = p[(size_t)(y1c * 16 + x0c) * CH];
    float v11 = p[(size_t)(y1c * 16 + x1c) * CH];
    float v = (1.f - fy) * ((1.f - fx) * v00 + fx * v01) + fy * ((1.f - fx) * v10 + fx * v11);
    size_t o = ((size_t)b * NN + n) * CH + c;
    out[o] = v;
    out16[o] = __float2bfloat16_rn(v);
}

__global__ void k_dwconv(const float* __restrict__ x, const float* __restrict__ wt,
                         const float* __restrict__ bs, float* __restrict__ out) {
    int i = blockIdx.x * blockDim.x + threadIdx.x;
    if (i >= BSZ * CH * NN) return;
    int wp = i & 63;
    int h = (i >> 6) & 63;
    int cc = (i >> 12) & 255;
    const float* xp = x + (size_t)(i - wp - h * 64);
    const float* kp = wt + cc * 9;
    float s = bs[cc];
#pragma unroll
    for (int dy = -1; dy <= 1; dy++) {
        int yy = h + dy; if (yy < 0 || yy >= 64) continue;
#pragma unroll
        for (int dx = -1; dx <= 1; dx++) {
            int xx = wp + dx; if (xx < 0 || xx >= 64) continue;
            s += xp[yy * 64 + xx] * kp[(dy + 1) * 3 + (dx + 1)];
        }
    }
    out[i] = s;
}

__global__ void k_final(const float* __restrict__ x, const float* __restrict__ P,
                        float* __restrict__ out) {
    __shared__ float tile[32][33];
    int b = blockIdx.z;
    int n0 = blockIdx.x * 32, c0 = blockIdx.y * 32;
    const float* pp = P + (size_t)b * NN * CH;
    for (int i = threadIdx.y; i < 32; i += 8)
        tile[i][threadIdx.x] = pp[(size_t)(n0 + i) * CH + c0 + threadIdx.x];
    __syncthreads();
    const float* xp = x + (size_t)b * CH * NN;
    float* op = out + (size_t)b * CH * NN;
    for (int i = threadIdx.y; i < 32; i += 8)
        op[(size_t)(c0 + i) * NN + n0 + threadIdx.x] =
            xp[(size_t)(c0 + i) * NN + n0 + threadIdx.x] + tile[threadIdx.x][i];
}

// ---------------- host ----------------
static float* gsym(const void* sym) {
    void* p = nullptr;
    cudaGetSymbolAddress(&p, sym);
    return (float*)p;
}
static bf16* gsym16(const void* sym) {
    void* p = nullptr;
    cudaGetSymbolAddress(&p, sym);
    return (bf16*)p;
}

extern "C" void kernel_launch(void* const* d_in, const int* in_sizes, int n_in,
                              void* d_out, int out_size) {
    const float* x    = (const float*)d_in[0];
    const float* Wt   = (const float*)d_in[1];
    const float* bt   = (const float*)d_in[2];
    const float* posf = (const float*)d_in[3];
    const float* posg = (const float*)d_in[4];
    const float* lng  = (const float*)d_in[5];
    const float* lnb  = (const float*)d_in[6];
    const float* Wf   = (const float*)d_in[7];
    const float* bf   = (const float*)d_in[8];
    const float* Ww_  = (const float*)d_in[9];
    const float* bw   = (const float*)d_in[10];
    const float* Wo   = (const float*)d_in[11];
    const float* bo   = (const float*)d_in[12];
    const float* Wr   = (const float*)d_in[13];
    const float* br   = (const float*)d_in[14];
    const float* Wgi  = (const float*)d_in[15];
    const float* bgi  = (const float*)d_in[16];
    const float* dww  = (const float*)d_in[17];
    const float* dwb  = (const float*)d_in[18];
    const float* Wl   = (const float*)d_in[19];
    const float* bl   = (const float*)d_in[20];
    const float* Wlf  = (const float*)d_in[21];
    const float* blf  = (const float*)d_in[22];
    const float* Wout = (const float*)d_in[23];
    const float* bout = (const float*)d_in[24];
    float* out = (float*)d_out;

    float *SEQ = gsym(d_SEQ), *U = gsym(d_U), *GA = gsym(d_GA), *GW = gsym(d_GB),
          *GO = gsym(d_GO), *YF = gsym(d_YF), *YB = gsym(d_YB), *Y = gsym(d_Y),
          *YG = gsym(d_YG), *T0 = gsym(d_T0);
    float *PF = gsym(d_PF), *PG = gsym(d_PG), *XG = gsym(d_XG),
          *UG = gsym(d_UG), *AG = gsym(d_AG), *BG = gsym(d_BG), *OG = gsym(d_OG),
          *YGS = gsym(d_YGS), *YGB = gsym(d_YGB);
    float *PART = gsym(d_PART), *CBAR = gsym(d_CBAR), *GBF = gsym(d_GBF),
          *GBW = gsym(d_GBW), *GBO = gsym(d_GBO);
    float *AF = gsym(d_AF), *BF = gsym(d_BF), *ABc = gsym(d_ABc), *BBc = gsym(d_BBc),
          *SF = gsym(d_SF), *SB = gsym(d_SB);

    bf16 *SEQ16 = gsym16(d_SEQ16), *U16 = gsym16(d_U16), *YF16 = gsym16(d_YF16),
         *YB16 = gsym16(d_YB16), *Y16 = gsym16(d_Y16), *YG16 = gsym16(d_YG16),
         *V16 = gsym16(d_V16), *Z16 = gsym16(d_Z16), *UO16 = gsym16(d_UO16),
         *CS16 = gsym16(d_CS16), *SEQG16 = gsym16(d_SEQG16), *UG16 = gsym16(d_UG16);
    bf16 *W16 = gsym16(d_W16);

    dim3 tb(32, 8);
    dim3 gF(2, M_FINE / 64);
    dim3 gG(2, M_GLOB / 64);
    dim3 gF3(6, M_FINE / 64);
    dim3 gG3(6, M_GLOB / 64);

    // weights -> bf16 cache
    k_wcvt<<<(OW_TOT + 1023) / 1024, 256>>>(Wt, Wf, Ww_, Wo, Wr, Wgi, Wl, Wlf, Wout, W16);

    // ---- fine sequence ----
    k_transpose16<<<dim3(NN / 32, CH / 32, BSZ), tb>>>(x, SEQ16, CH, NN);
    k_pos_embed<<<NN, 256>>>(posf, PF, HH, WW);
    k_pos_embed<<<NG, 256>>>(posg, PG, GH, GH);

    // u = seq @ Wt + bt + pos  (fp32 + bf16)
    k_gemm_f<<<gF, 256>>>(SEQ16, nullptr, nullptr, W16 + OW_Wt, bt, nullptr, nullptr, PF,
                          U, U16, 1, 0, NN);

    // context + gate biases
    k_colsum<<<dim3(32, BSZ), 256>>>(U, PART, NN, 128, 32);
    k_ln_ctx<<<BSZ, 256>>>(PART, 32, 1.f / NN, lng, lnb, CBAR);
    k_gate_bias<<<BSZ, 256>>>(CBAR, Wf + 256 * 256, bf, GBF);
    k_gate_bias<<<BSZ, 256>>>(CBAR, Ww_ + 256 * 256, bw, GBW);
    k_gate_bias<<<BSZ, 256>>>(CBAR, Wo + 256 * 256, bo, GBO);

    // gates a, g, o
    k_gates3<<<gF3, 256>>>(U16, W16 + OW_Wf, GBF, GBW, GBO, GA, GW, GO, NN);

    // bidirectional chunked scan
    k_scan_pass1<<<dim3(NCHUNK, BSZ), 256>>>(GA, GW, U, AF, BF, ABc, BBc, NN, NCHUNK);
    k_scan_pass2<<<BSZ, 256>>>(AF, BF, ABc, BBc, SF, SB, NCHUNK);
    k_scan_pass3<<<dim3(NCHUNK, BSZ), 256>>>(GA, GW, GO, U, SF, SB, YF, YB, YF16, YB16, NN, NCHUNK);

    // rho mix
    k_gemm_f<<<gF, 256>>>(U16, YF16, YB16, W16 + OW_Wr, br, YF, YB, nullptr,
                          Y, Y16, 3, 1, NN);

    // ---- global branch ----
    k_pool<<<(BSZ * CH * NG + 255) / 256, 256>>>(x, XG);
    k_transpose16<<<dim3(NG / 32, CH / 32, BSZ), tb>>>(XG, SEQG16, CH, NG);
    k_gemm_f<<<gG, 256>>>(SEQG16, nullptr, nullptr, W16 + OW_Wt, bt, nullptr, nullptr, PG,
                          UG, UG16, 1, 0, NG);

    k_colsum<<<dim3(2, BSZ), 256>>>(UG, PART, NG, 128, 2);
    k_ln_ctx<<<BSZ, 256>>>(PART, 2, 1.f / NG, lng, lnb, CBAR);
    k_gate_bias<<<BSZ, 256>>>(CBAR, Wf + 256 * 256, bf, GBF);
    k_gate_bias<<<BSZ, 256>>>(CBAR, Ww_ + 256 * 256, bw, GBW);
    k_gate_bias<<<BSZ, 256>>>(CBAR, Wo + 256 * 256, bo, GBO);

    k_gates3<<<gG3, 256>>>(UG16, W16 + OW_Wf, GBF, GBW, GBO, AG, BG, OG, NG);

    k_scan_pass1<<<dim3(NCHUNK_G, BSZ), 256>>>(AG, BG, UG, AF, BF, ABc, BBc, NG, NCHUNK_G);
    k_scan_pass2<<<BSZ, 256>>>(AF, BF, ABc, BBc, SF, SB, NCHUNK_G);
    k_scan_pass3<<<dim3(NCHUNK_G, BSZ), 256>>>(AG, BG, OG, UG, SF, SB, YGS, YGB,
                                               nullptr, nullptr, NG, NCHUNK_G);

    k_upsample<<<dim3(NN, BSZ), 256>>>(YGS, YG, YG16);

    // lam: z = Y + sig(t)*YG
    k_gemm_f<<<gF, 256>>>(Y16, YG16, U16, W16 + OW_Wgi, bgi, Y, YG, nullptr,
                          T0, Z16, 3, 2, NN);

    // ---- local depthwise conv branch ----
    k_dwconv<<<(BSZ * CH * NN + 255) / 256, 256>>>(x, dww, dwb, SEQ);
    k_transpose16<<<dim3(NN / 32, CH / 32, BSZ), tb>>>(SEQ, CS16, CH, NN);
    // v
    k_gemm_f<<<gF, 256>>>(CS16, nullptr, nullptr, W16 + OW_Wl, bl, nullptr, nullptr, nullptr,
                          GA, V16, 1, 0, NN);
    // eta: u_out = sig(t)*v + (1-sig)*z
    k_gemm_f<<<gF, 256>>>(V16, Z16, nullptr, W16 + OW_Wlf, blf, GA, T0, nullptr,
                          GW, UO16, 2, 1, NN);
    // out projection -> U, residual
    k_gemm_f<<<gF, 256>>>(UO16, nullptr, nullptr, W16 + OW_Wout, bout, nullptr, nullptr, nullptr,
                          U, nullptr, 1, 0, NN);
    k_final<<<dim3(NN / 32, CH / 32, BSZ), tb>>>(x, U, out);
}

// round 9
// speedup vs baseline: 4.6132x; 1.1831x over previous
#include <cuda_runtime.h>
#include <cuda_bf16.h>
#include <math.h>
#include <stdint.h>

#define BSZ 8
#define CH 256
#define HH 64
#define WW 64
#define NN 4096
#define GH 16
#define NG 256
#define M_FINE (BSZ*NN)  // 32768
#define M_GLOB (BSZ*NG)  // 2048
#define NCHUNK 64
#define NCHUNK_G 8

typedef __nv_bfloat16 bf16;

// ---------------- scratch ----------------
__device__ float d_U   [M_FINE*CH];
__device__ float d_GA  [M_FINE*CH];
__device__ float d_GB  [M_FINE*CH];
__device__ float d_GO  [M_FINE*CH];

__device__ bf16 d_SEQ16[M_FINE*CH];
__device__ bf16 d_U16  [M_FINE*CH];
__device__ bf16 d_YF16 [M_FINE*CH];
__device__ bf16 d_YB16 [M_FINE*CH];
__device__ bf16 d_Y16  [M_FINE*CH];
__device__ bf16 d_YG16 [M_FINE*CH];
__device__ bf16 d_V16  [M_FINE*CH];
__device__ bf16 d_Z16  [M_FINE*CH];
__device__ bf16 d_UO16 [M_FINE*CH];
__device__ bf16 d_CS16 [M_FINE*CH];
__device__ bf16 d_SEQG16[M_GLOB*CH];
__device__ bf16 d_UG16 [M_GLOB*CH];

__device__ float d_PF  [NN*CH];
__device__ float d_PG  [NG*CH];
__device__ float d_XG  [BSZ*CH*NG];
__device__ float d_UG  [M_GLOB*CH];
__device__ float d_AG  [M_GLOB*CH];
__device__ float d_BG  [M_GLOB*CH];
__device__ float d_OG  [M_GLOB*CH];
__device__ float d_YGS [M_GLOB*CH];
__device__ float d_YGB [M_GLOB*CH];

__device__ float d_PART[BSZ*32*CH];
__device__ float d_CBAR[BSZ*CH];
__device__ float d_GBF [BSZ*CH];
__device__ float d_GBW [BSZ*CH];
__device__ float d_GBO [BSZ*CH];

__device__ float d_AF [BSZ*NCHUNK*CH];
__device__ float d_BF [BSZ*NCHUNK*CH];
__device__ float d_ABc[BSZ*NCHUNK*CH];
__device__ float d_BBc[BSZ*NCHUNK*CH];
__device__ float d_SF [BSZ*NCHUNK*CH];
__device__ float d_SB [BSZ*NCHUNK*CH];

// bf16 weight cache
#define OW_Wt   0
#define OW_Wf   65536
#define OW_Ww   131072
#define OW_Wo   196608
#define OW_Wr   262144
#define OW_Wgi  458752
#define OW_Wl   655360
#define OW_Wlf  720896
#define OW_Wout 851968
#define OW_TOT  917504
__device__ bf16 d_W16[OW_TOT];

// ---------------- asm helpers ----------------
__device__ __forceinline__ uint32_t smem_u32(const void* p) {
    uint32_t a;
    asm("{ .reg .u64 t; cvta.to.shared.u64 t, %1; cvt.u32.u64 %0, t; }" : "=r"(a) : "l"(p));
    return a;
}
#define LDSM_X4(r0, r1, r2, r3, addr) \
    asm volatile("ldmatrix.sync.aligned.m8n8.x4.shared.b16 {%0,%1,%2,%3}, [%4];" \
                 : "=r"(r0), "=r"(r1), "=r"(r2), "=r"(r3) : "r"(addr))
#define LDSM_X4_T(r0, r1, r2, r3, addr) \
    asm volatile("ldmatrix.sync.aligned.m8n8.x4.trans.shared.b16 {%0,%1,%2,%3}, [%4];" \
                 : "=r"(r0), "=r"(r1), "=r"(r2), "=r"(r3) : "r"(addr))
#define MMA16816(d, a, b0, b1) \
    asm volatile("mma.sync.aligned.m16n8k16.row.col.f32.bf16.bf16.f32 " \
                 "{%0,%1,%2,%3}, {%4,%5,%6,%7}, {%8,%9}, {%0,%1,%2,%3};" \
                 : "+f"((d)[0]), "+f"((d)[1]), "+f"((d)[2]), "+f"((d)[3]) \
                 : "r"((a)[0]), "r"((a)[1]), "r"((a)[2]), "r"((a)[3]), "r"(b0), "r"(b1))
#define CPA16(dst, src) \
    asm volatile("cp.async.cg.shared.global [%0], [%1], 16;" :: "r"(dst), "l"(src))
#define CPA_COMMIT() asm volatile("cp.async.commit_group;" ::: "memory")
#define CPA_WAIT(n)  asm volatile("cp.async.wait_group %0;" :: "n"(n) : "memory")

__device__ __forceinline__ float sigf(float x) { return 1.f / (1.f + expf(-x)); }

// ---------------- cp.async HMMA mainloop (CTA tile 64x128, 4 stages) ----------------
__device__ __forceinline__ void mma_loop(
    const bf16* __restrict__ A0, const bf16* __restrict__ A1, const bf16* __restrict__ A2,
    const bf16* __restrict__ Bw, int nA, int m0, int n0,
    uint32_t smBase, float (*acc)[4][4]) {
    int tid = threadIdx.x;
    int wid = tid >> 5, lane = tid & 31;
    int wm = wid >> 2, wn = wid & 3;
    int mA = tid >> 2, cA = tid & 3;
    int kB = tid >> 4, cB = tid & 15;

    uint32_t offA  = (uint32_t)(mA * 64 + ((cA ^ ((mA >> 1) & 3)) << 4));
    uint32_t offB0 = 4096u + (uint32_t)(kB * 256 + ((cB ^ (kB & 7)) << 4));
    uint32_t offB1 = offB0 + 4096u;

    int lr = lane & 7, lh = (lane >> 3) & 1, lq = lane >> 4;
    int arow_base = wm * 32 + lh * 8 + lr;
    int brow_base = lh * 8 + lr;

    int totalS = nA * 8;

    const bf16* aSrc = A0 + (size_t)(m0 + mA) * 256 + cA * 8;
    const bf16* a1Src = A1 ? A1 + (size_t)(m0 + mA) * 256 + cA * 8 : nullptr;
    const bf16* a2Src = A2 ? A2 + (size_t)(m0 + mA) * 256 + cA * 8 : nullptr;
    const bf16* bSrc = Bw + (size_t)kB * 256 + n0 + cB * 8;

#define ISSUE(s) do { \
        uint32_t slot = smBase + ((uint32_t)(s) & 3u) * 12288u; \
        const bf16* pa = ((s) >> 3) == 0 ? aSrc : (((s) >> 3) == 1 ? a1Src : a2Src); \
        CPA16(slot + offA, pa + ((s) & 7) * 32); \
        const bf16* pb = bSrc + (size_t)(s) * 32 * 256; \
        CPA16(slot + offB0, pb); \
        CPA16(slot + offB1, pb + 16 * 256); \
        CPA_COMMIT(); \
    } while (0)

    ISSUE(0); ISSUE(1); ISSUE(2);

#pragma unroll 1
    for (int s = 0; s < totalS; s++) {
        if (s + 3 < totalS) ISSUE(s + 3);
        int rem = totalS - 1 - s;
        if (rem >= 3) CPA_WAIT(3);
        else if (rem == 2) CPA_WAIT(2);
        else if (rem == 1) CPA_WAIT(1);
        else CPA_WAIT(0);
        __syncthreads();
        uint32_t bo = smBase + ((uint32_t)s & 3u) * 12288u;
#pragma unroll
        for (int k16 = 0; k16 < 2; k16++) {
            uint32_t afr[2][4];
#pragma unroll
            for (int mi = 0; mi < 2; mi++) {
                int row = arow_base + mi * 16;
                int c = k16 * 2 + lq;
                uint32_t addr = bo + (uint32_t)(row * 64 + ((c ^ ((row >> 1) & 3)) << 4));
                LDSM_X4(afr[mi][0], afr[mi][1], afr[mi][2], afr[mi][3], addr);
            }
            uint32_t bfr[2][4];
#pragma unroll
            for (int g = 0; g < 2; g++) {
                int rowk = k16 * 16 + brow_base;
                int c = wn * 4 + g * 2 + lq;
                uint32_t addr = bo + 4096u + (uint32_t)(rowk * 256 + ((c ^ (rowk & 7)) << 4));
                LDSM_X4_T(bfr[g][0], bfr[g][1], bfr[g][2], bfr[g][3], addr);
            }
#pragma unroll
            for (int mi = 0; mi < 2; mi++)
#pragma unroll
                for (int j = 0; j < 4; j++)
                    MMA16816(acc[mi][j], afr[mi], bfr[j >> 1][(j & 1) * 2], bfr[j >> 1][(j & 1) * 2 + 1]);
        }
        __syncthreads();
    }
#undef ISSUE
}

// ---------------- fused GEMM ----------------
// mode 0: t (+pos) -> C (fp32, opt) / C16 (opt)
// mode 1: r=sig(t); r*E0+(1-r)*E1 -> C/C16
// mode 2: E0 + sig(t)*E1 -> C/C16
// mode 3: outres[b][c][n] = xres + t  (smem transpose, residual)
__global__ void __launch_bounds__(256, 2)
k_gemm_f(const bf16* __restrict__ A0, const bf16* __restrict__ A1,
         const bf16* __restrict__ A2, const bf16* __restrict__ Bw,
         const float* __restrict__ bias, const bf16* __restrict__ E0,
         const bf16* __restrict__ E1, const float* __restrict__ pos,
         float* __restrict__ C, bf16* __restrict__ C16,
         const float* __restrict__ xres, float* __restrict__ outres,
         int nA, int mode, int posRows) {
    __shared__ __align__(16) uint8_t sm[49152];
    uint32_t smBase = smem_u32(sm);
    int m0 = blockIdx.y * 64, n0 = blockIdx.x * 128;

    float acc[2][4][4] = {};
    mma_loop(A0, A1, A2, Bw, nA, m0, n0, smBase, acc);

    int lane = threadIdx.x & 31, wid = threadIdx.x >> 5;
    int wm = wid >> 2, wn = wid & 3;
    int gid = lane >> 2, tig = lane & 3;

    if (mode == 3) {
        float* stage = (float*)sm;   // stage[c_l][row_l], stride 65
#pragma unroll
        for (int mi = 0; mi < 2; mi++) {
#pragma unroll
            for (int j = 0; j < 4; j++) {
                int row_l = wm * 32 + mi * 16 + gid;
                int col_l = wn * 32 + j * 8 + tig * 2;
                int col = n0 + col_l;
                float bb0 = bias ? bias[col] : 0.f;
                float bb1 = bias ? bias[col + 1] : 0.f;
                stage[col_l * 65 + row_l] = acc[mi][j][0] + bb0;
                stage[(col_l + 1) * 65 + row_l] = acc[mi][j][1] + bb1;
                stage[col_l * 65 + row_l + 8] = acc[mi][j][2] + bb0;
                stage[(col_l + 1) * 65 + row_l + 8] = acc[mi][j][3] + bb1;
            }
        }
        __syncthreads();
        int b = m0 >> 12;
        int ntok = m0 & 4095;
#pragma unroll
        for (int k = 0; k < 16; k++) {
            int c_l = wid * 16 + k;
            int c = n0 + c_l;
            size_t base = (((size_t)(b * 256 + c)) << 12) + ntok;
#pragma unroll
            for (int i = 0; i < 2; i++) {
                int nl = i * 32 + lane;
                outres[base + nl] = stage[c_l * 65 + nl] + xres[base + nl];
            }
        }
        return;
    }

#pragma unroll
    for (int mi = 0; mi < 2; mi++) {
#pragma unroll
        for (int j = 0; j < 4; j++) {
            int row = m0 + wm * 32 + mi * 16 + gid;
            int col = n0 + wn * 32 + j * 8 + tig * 2;
            float t0 = acc[mi][j][0], t1 = acc[mi][j][1];
            float t2 = acc[mi][j][2], t3 = acc[mi][j][3];
            float bb0 = 0.f, bb1 = 0.f;
            if (bias) { bb0 = bias[col]; bb1 = bias[col + 1]; }
            t0 += bb0; t1 += bb1; t2 += bb0; t3 += bb1;
            size_t o0 = (size_t)row * 256 + col;
            size_t o1 = (size_t)(row + 8) * 256 + col;
            float v0, v1, v2, v3;
            if (mode == 0) {
                if (pos) {
                    const float* p0 = pos + (size_t)(row % posRows) * 256 + col;
                    const float* p1 = pos + (size_t)((row + 8) % posRows) * 256 + col;
                    t0 += p0[0]; t1 += p0[1]; t2 += p1[0]; t3 += p1[1];
                }
                v0 = t0; v1 = t1; v2 = t2; v3 = t3;
            } else {
                float e0 = __bfloat162float(E0[o0]), e1 = __bfloat162float(E0[o0 + 1]);
                float e2 = __bfloat162float(E0[o1]), e3 = __bfloat162float(E0[o1 + 1]);
                float f0 = __bfloat162float(E1[o0]), f1 = __bfloat162float(E1[o0 + 1]);
                float f2 = __bfloat162float(E1[o1]), f3 = __bfloat162float(E1[o1 + 1]);
                if (mode == 1) {
                    float r0 = sigf(t0), r1 = sigf(t1), r2 = sigf(t2), r3 = sigf(t3);
                    v0 = r0 * e0 + (1.f - r0) * f0; v1 = r1 * e1 + (1.f - r1) * f1;
                    v2 = r2 * e2 + (1.f - r2) * f2; v3 = r3 * e3 + (1.f - r3) * f3;
                } else {
                    v0 = e0 + sigf(t0) * f0; v1 = e1 + sigf(t1) * f1;
                    v2 = e2 + sigf(t2) * f2; v3 = e3 + sigf(t3) * f3;
                }
            }
            if (C) {
                C[o0] = v0; C[o0 + 1] = v1;
                C[o1] = v2; C[o1 + 1] = v3;
            }
            if (C16) {
                *(__nv_bfloat162*)(C16 + o0) = __floats2bfloat162_rn(v0, v1);
                *(__nv_bfloat162*)(C16 + o1) = __floats2bfloat162_rn(v2, v3);
            }
        }
    }
}

// ---------------- fused gates GEMM: grid (6, M/64) ----------------
__global__ void __launch_bounds__(256, 2)
k_gates3(const bf16* __restrict__ A, const bf16* __restrict__ Wall,
         const float* __restrict__ G0, const float* __restrict__ G1,
         const float* __restrict__ G2, float* __restrict__ C0,
         float* __restrict__ C1, float* __restrict__ C2, int rowsPerBatch) {
    __shared__ __align__(16) uint8_t sm[49152];
    uint32_t smBase = smem_u32(sm);
    int j3 = blockIdx.x >> 1;
    int n0 = (blockIdx.x & 1) * 128;
    int m0 = blockIdx.y * 64;
    const bf16* Bw = Wall + (size_t)j3 * 65536;
    const float* Gb = j3 == 0 ? G0 : (j3 == 1 ? G1 : G2);
    float* C = j3 == 0 ? C0 : (j3 == 1 ? C1 : C2);

    float acc[2][4][4] = {};
    mma_loop(A, A, A, Bw, 1, m0, n0, smBase, acc);

    int lane = threadIdx.x & 31, wid = threadIdx.x >> 5;
    int wm = wid >> 2, wn = wid & 3;
    int gid = lane >> 2, tig = lane & 3;
    int batch = m0 / rowsPerBatch;
    float sgn = (j3 == 0) ? -1.f : 1.f;
#pragma unroll
    for (int mi = 0; mi < 2; mi++) {
#pragma unroll
        for (int j = 0; j < 4; j++) {
            int row = m0 + wm * 32 + mi * 16 + gid;
            int col = n0 + wn * 32 + j * 8 + tig * 2;
            float bb0 = Gb[batch * 256 + col], bb1 = Gb[batch * 256 + col + 1];
            float v0 = sigf(sgn * (acc[mi][j][0] + bb0));
            float v1 = sigf(sgn * (acc[mi][j][1] + bb1));
            float v2 = sigf(sgn * (acc[mi][j][2] + bb0));
            float v3 = sigf(sgn * (acc[mi][j][3] + bb1));
            size_t o0 = (size_t)row * 256 + col;
            size_t o1 = (size_t)(row + 8) * 256 + col;
            C[o0] = v0; C[o0 + 1] = v1;
            C[o1] = v2; C[o1 + 1] = v3;
        }
    }
}

// ---------------- weight conversion ----------------
__global__ void k_wcvt(const float* __restrict__ s0, const float* __restrict__ s1,
                       const float* __restrict__ s2, const float* __restrict__ s3,
                       const float* __restrict__ s4, const float* __restrict__ s5,
                       const float* __restrict__ s6, const float* __restrict__ s7,
                       const float* __restrict__ s8, bf16* __restrict__ dst) {
    int i0 = blockIdx.x * 1024 + threadIdx.x * 4;
#pragma unroll
    for (int e = 0; e < 4; e++) {
        int idx = i0 + e;
        if (idx >= OW_TOT) return;
        float v;
        if (idx < OW_Wf)        v = s0[idx - OW_Wt];
        else if (idx < OW_Ww)   v = s1[idx - OW_Wf];
        else if (idx < OW_Wo)   v = s2[idx - OW_Ww];
        else if (idx < OW_Wr)   v = s3[idx - OW_Wo];
        else if (idx < OW_Wgi)  v = s4[idx - OW_Wr];
        else if (idx < OW_Wl)   v = s5[idx - OW_Wgi];
        else if (idx < OW_Wlf)  v = s6[idx - OW_Wl];
        else if (idx < OW_Wout) v = s7[idx - OW_Wlf];
        else                    v = s8[idx - OW_Wout];
        dst[idx] = __float2bfloat16_rn(v);
    }
}

// ---------------- elementwise / scan kernels ----------------

// fp32 [b][CC][NR] -> bf16 [b][NR][CC]
__global__ void k_transpose16(const float* __restrict__ in, bf16* __restrict__ out,
                              int CC, int NR) {
    __shared__ float tile[32][33];
    int b = blockIdx.z;
    int n0 = blockIdx.x * 32, c0 = blockIdx.y * 32;
    const float* ip = in + (size_t)b * CC * NR;
    bf16* op = out + (size_t)b * CC * NR;
    for (int i = threadIdx.y; i < 32; i += 8)
        tile[i][threadIdx.x] = ip[(size_t)(c0 + i) * NR + n0 + threadIdx.x];
    __syncthreads();
    for (int i = threadIdx.y; i < 32; i += 8)
        op[(size_t)(n0 + i) * CC + c0 + threadIdx.x] =
            __float2bfloat16_rn(tile[threadIdx.x][i]);
}

__device__ __forceinline__ int resize_taps(int i, int IS, int OS, int* jj, float* ww) {
    float inv = (float)IS / (float)OS;
    float dil = inv > 1.f ? inv : 1.f;
    float s = (i + 0.5f) * inv - 0.5f;
    int lo = (int)floorf(s - dil);
    int hi = (int)ceilf(s + dil);
    int n = 0; float tot = 0.f;
    for (int j = lo; j <= hi; j++) {
        if (j < 0 || j >= IS) continue;
        float w = 1.f - fabsf(s - (float)j) / dil;
        if (w <= 0.f) continue;
        jj[n] = j; ww[n] = w; tot += w; n++;
    }
    float r = 1.f / tot;
    for (int t = 0; t < n; t++) ww[t] *= r;
    return n;
}

__global__ void k_pos_embed(const float* __restrict__ pos, float* __restrict__ out,
                            int OH, int OW) {
    __shared__ int sjy[8], sjx[8], sny, snx;
    __shared__ float swy[8], swx[8];
    int c = threadIdx.x;
    int n = blockIdx.x;
    int h = n / OW, w = n % OW;
    if (c == 0) {
        int jy[8]; float wy[8];
        int ny = resize_taps(h, 32, OH, jy, wy);
        sny = ny;
        for (int t = 0; t < ny; t++) { sjy[t] = jy[t]; swy[t] = wy[t]; }
    }
    if (c == 32) {
        int jx[8]; float wx[8];
        int nx = resize_taps(w, 32, OW, jx, wx);
        snx = nx;
        for (int t = 0; t < nx; t++) { sjx[t] = jx[t]; swx[t] = wx[t]; }
    }
    __syncthreads();
    int ny = sny, nx = snx;
    float acc = 0.f;
    for (int a = 0; a < ny; a++)
        for (int b2 = 0; b2 < nx; b2++)
            acc += swy[a] * swx[b2] * pos[c * 1024 + sjy[a] * 32 + sjx[b2]];
    out[(size_t)n * CH + c] = acc;
}

__global__ void k_colsum(const float* __restrict__ u, float* __restrict__ part,
                         int rowsTotal, int rowsPerBlock, int nch) {
    int b = blockIdx.y, c = threadIdx.x, chn = blockIdx.x;
    const float* p = u + ((size_t)b * rowsTotal + (size_t)chn * rowsPerBlock) * CH + c;
    float s = 0.f;
    for (int r = 0; r < rowsPerBlock; r++) s += p[(size_t)r * CH];
    part[((size_t)b * nch + chn) * CH + c] = s;
}

__global__ void k_ln_ctx(const float* __restrict__ part, int nch, float invN,
                         const float* __restrict__ g, const float* __restrict__ be,
                         float* __restrict__ cbar) {
    __shared__ float red[256];
    int b = blockIdx.x, c = threadIdx.x;
    float v = 0.f;
    for (int chn = 0; chn < nch; chn++) v += part[((size_t)b * nch + chn) * CH + c];
    v *= invN;
    red[c] = v; __syncthreads();
    for (int s = 128; s > 0; s >>= 1) { if (c < s) red[c] += red[c + s]; __syncthreads(); }
    float m = red[0] / CH; __syncthreads();
    float d = v - m;
    red[c] = d * d; __syncthreads();
    for (int s = 128; s > 0; s >>= 1) { if (c < s) red[c] += red[c + s]; __syncthreads(); }
    float var = red[0] / CH;
    cbar[b * CH + c] = d * rsqrtf(var + 1e-5f) * g[c] + be[c];
}

__global__ void k_gate_bias(const float* __restrict__ cbar, const float* __restrict__ Wlow,
                            const float* __restrict__ bias, float* __restrict__ out) {
    __shared__ float cs[256];
    int b = blockIdx.x, j = threadIdx.x;
    cs[j] = cbar[b * CH + j];
    __syncthreads();
    float s = bias[j];
    for (int c = 0; c < CH; c++) s += cs[c] * Wlow[c * CH + j];
    out[b * CH + j] = s;
}

__global__ void k_scan_pass1(const float* __restrict__ GA, const float* __restrict__ GW,
                             const float* __restrict__ U,
                             float* __restrict__ AF, float* __restrict__ BF,
                             float* __restrict__ ABc, float* __restrict__ BBc,
                             int rows, int nchunk) {
    int b = blockIdx.y, chn = blockIdx.x, c = threadIdx.x;
    int L = rows / nchunk;
    size_t base = ((size_t)b * rows + (size_t)chn * L) * CH + c;
    float Af = 1.f, Bf = 0.f;
    for (int i = 0; i < L; i++) {
        size_t o = base + (size_t)i * CH;
        float a = GA[o];
        float bb = (1.f - a) * GW[o] * U[o];
        Af *= a; Bf = a * Bf + bb;
    }
    float Ab = 1.f, Bb = 0.f;
    for (int i = L - 1; i >= 0; i--) {
        size_t o = base + (size_t)i * CH;
        float a = GA[o];
        float bb = (1.f - a) * GW[o] * U[o];
        Ab *= a; Bb = a * Bb + bb;
    }
    size_t co = ((size_t)b * nchunk + chn) * CH + c;
    AF[co] = Af; BF[co] = Bf; ABc[co] = Ab; BBc[co] = Bb;
}

__global__ void k_scan_pass2(const float* __restrict__ AF, const float* __restrict__ BF,
                             const float* __restrict__ ABc, const float* __restrict__ BBc,
                             float* __restrict__ SF, float* __restrict__ SB, int nchunk) {
    int b = blockIdx.x, c = threadIdx.x;
    float s = 0.f;
    for (int chn = 0; chn < nchunk; chn++) {
        size_t o = ((size_t)b * nchunk + chn) * CH + c;
        SF[o] = s; s = AF[o] * s + BF[o];
    }
    float sb = 0.f;
    for (int chn = nchunk - 1; chn >= 0; chn--) {
        size_t o = ((size_t)b * nchunk + chn) * CH + c;
        SB[o] = sb; sb = ABc[o] * sb + BBc[o];
    }
}

__global__ void k_scan_pass3(const float* __restrict__ GA, const float* __restrict__ GW,
                             const float* __restrict__ GO, const float* __restrict__ U,
                             const float* __restrict__ SF, const float* __restrict__ SB,
                             float* __restrict__ YFf, float* __restrict__ YBf,
                             bf16* __restrict__ YF16, bf16* __restrict__ YB16,
                             int rows, int nchunk) {
    int b = blockIdx.y, chn = blockIdx.x, c = threadIdx.x;
    int L = rows / nchunk;
    size_t base = ((size_t)b * rows + (size_t)chn * L) * CH + c;
    size_t co = ((size_t)b * nchunk + chn) * CH + c;
    float s = SF[co];
    for (int i = 0; i < L; i++) {
        size_t o = base + (size_t)i * CH;
        float a = GA[o], u = U[o], ov = GO[o];
        float bb = (1.f - a) * GW[o] * u;
        s = a * s + bb;
        float y = ov * s + (1.f - ov) * u;
        if (YFf) YFf[o] = y;
        if (YF16) YF16[o] = __float2bfloat16_rn(y);
    }
    float sb = SB[co];
    for (int i = L - 1; i >= 0; i--) {
        size_t o = base + (size_t)i * CH;
        float a = GA[o], u = U[o], ov = GO[o];
        float bb = (1.f - a) * GW[o] * u;
        sb = a * sb + bb;
        float y = ov * sb + (1.f - ov) * u;
        if (YBf) YBf[o] = y;
        if (YB16) YB16[o] = __float2bfloat16_rn(y);
    }
}

__global__ void k_pool(const float* __restrict__ x, float* __restrict__ xg) {
    int i = blockIdx.x * blockDim.x + threadIdx.x;
    if (i >= BSZ * CH * NG) return;
    int gx = i % GH; int gy = (i / GH) % GH; int bc = i / NG;
    const float* p = x + (size_t)bc * NN + (gy * 4) * 64 + gx * 4;
    float s = 0.f;
#pragma unroll
    for (int dy = 0; dy < 4; dy++)
#pragma unroll
        for (int dx = 0; dx < 4; dx++) s += p[dy * 64 + dx];
    xg[i] = s * 0.0625f;
}

__global__ void k_upsample(const float* __restrict__ yg, bf16* __restrict__ out16) {
    int c = threadIdx.x;
    int n = blockIdx.x;
    int b = blockIdx.y;
    int h = n >> 6, w = n & 63;
    float sy = (h + 0.5f) * 0.25f - 0.5f;
    float sx = (w + 0.5f) * 0.25f - 0.5f;
    int y0 = (int)floorf(sy); float fy = sy - y0;
    int x0 = (int)floorf(sx); float fx = sx - x0;
    int y0c = min(max(y0, 0), 15), y1c = min(max(y0 + 1, 0), 15);
    int x0c = min(max(x0, 0), 15), x1c = min(max(x0 + 1, 0), 15);
    const float* p = yg + (size_t)b * NG * CH + c;
    float v00 = p[(size_t)(y0c * 16 + x0c) * CH];
    float v01 = p[(size_t)(y0c * 16 + x1c) * CH];
    float v10 = p[(size_t)(y1c * 16 + x0c) * CH];
    float v11 = p[(size_t)(y1c * 16 + x1c) * CH];
    float v = (1.f - fy) * ((1.f - fx) * v00 + fx * v01) + fy * ((1.f - fx) * v10 + fx * v11);
    out16[((size_t)b * NN + n) * CH + c] = __float2bfloat16_rn(v);
}

// depthwise 3x3 SAME, fused transpose: x[b][c][64][64] -> out16[b][n][c] (bf16)
// grid (8 ctile, 64 h, 8 b), 256 threads.
__global__ void k_dwconv_t(const float* __restrict__ x, const float* __restrict__ wt,
                           const float* __restrict__ bs, bf16* __restrict__ out16) {
    __shared__ float xs[32][3][67];   // [c_local][row][w+1 padded]
    int c0 = blockIdx.x * 32;
    int h = blockIdx.y;
    int b = blockIdx.z;
    int tid = threadIdx.x;

    // zero halo columns (w=0 and w=65) + rows out of range handled below
    for (int idx = tid; idx < 32 * 3; idx += 256) {
        int cc = idx / 3, r = idx % 3;
        xs[cc][r][0] = 0.f;
        xs[cc][r][65] = 0.f;
        xs[cc][r][66] = 0.f;
    }
    __syncthreads();
    // fill interior
    for (int idx = tid; idx < 32 * 3 * 64; idx += 256) {
        int cc = idx / 192;
        int rem = idx - cc * 192;
        int r = rem >> 6, w = rem & 63;
        int hs = h - 1 + r;
        float v = 0.f;
        if (hs >= 0 && hs < 64)
            v = x[(((size_t)b * 256 + c0 + cc) << 12) + hs * 64 + w];
        xs[cc][r][w + 1] = v;
    }
    __syncthreads();

    int c_l = tid & 31;
    int w0 = (tid >> 5) * 8;
    float k0 = wt[(c0 + c_l) * 9 + 0], k1 = wt[(c0 + c_l) * 9 + 1], k2 = wt[(c0 + c_l) * 9 + 2];
    float k3 = wt[(c0 + c_l) * 9 + 3], k4 = wt[(c0 + c_l) * 9 + 4], k5 = wt[(c0 + c_l) * 9 + 5];
    float k6 = wt[(c0 + c_l) * 9 + 6], k7 = wt[(c0 + c_l) * 9 + 7], k8 = wt[(c0 + c_l) * 9 + 8];
    float bias = bs[c0 + c_l];
#pragma unroll
    for (int e = 0; e < 8; e++) {
        int w = w0 + e;
        float s = bias;
        s += xs[c_l][0][w] * k0 + xs[c_l][0][w + 1] * k1 + xs[c_l][0][w + 2] * k2;
        s += xs[c_l][1][w] * k3 + xs[c_l][1][w + 1] * k4 + xs[c_l][1][w + 2] * k5;
        s += xs[c_l][2][w] * k6 + xs[c_l][2][w + 1] * k7 + xs[c_l][2][w + 2] * k8;
        out16[(((size_t)b * 4096 + h * 64 + w) << 8) + c0 + c_l] = __float2bfloat16_rn(s);
    }
}

// ---------------- host ----------------
static float* gsym(const void* sym) {
    void* p = nullptr;
    cudaGetSymbolAddress(&p, sym);
    return (float*)p;
}
static bf16* gsym16(const void* sym) {
    void* p = nullptr;
    cudaGetSymbolAddress(&p, sym);
    return (bf16*)p;
}

extern "C" void kernel_launch(void* const* d_in, const int* in_sizes, int n_in,
                              void* d_out, int out_size) {
    const float* x    = (const float*)d_in[0];
    const float* Wt   = (const float*)d_in[1];
    const float* bt   = (const float*)d_in[2];
    const float* posf = (const float*)d_in[3];
    const float* posg = (const float*)d_in[4];
    const float* lng  = (const float*)d_in[5];
    const float* lnb  = (const float*)d_in[6];
    const float* Wf   = (const float*)d_in[7];
    const float* bf   = (const float*)d_in[8];
    const float* Ww_  = (const float*)d_in[9];
    const float* bw   = (const float*)d_in[10];
    const float* Wo   = (const float*)d_in[11];
    const float* bo   = (const float*)d_in[12];
    const float* Wr   = (const float*)d_in[13];
    const float* br   = (const float*)d_in[14];
    const float* Wgi  = (const float*)d_in[15];
    const float* bgi  = (const float*)d_in[16];
    const float* dww  = (const float*)d_in[17];
    const float* dwb  = (const float*)d_in[18];
    const float* Wl   = (const float*)d_in[19];
    const float* bl   = (const float*)d_in[20];
    const float* Wlf  = (const float*)d_in[21];
    const float* blf  = (const float*)d_in[22];
    const float* Wout = (const float*)d_in[23];
    const float* bout = (const float*)d_in[24];
    float* out = (float*)d_out;

    float *U = gsym(d_U), *GA = gsym(d_GA), *GW = gsym(d_GB), *GO = gsym(d_GO);
    float *PF = gsym(d_PF), *PG = gsym(d_PG), *XG = gsym(d_XG),
          *UG = gsym(d_UG), *AG = gsym(d_AG), *BG = gsym(d_BG), *OG = gsym(d_OG),
          *YGS = gsym(d_YGS), *YGB = gsym(d_YGB);
    float *PART = gsym(d_PART), *CBAR = gsym(d_CBAR), *GBF = gsym(d_GBF),
          *GBW = gsym(d_GBW), *GBO = gsym(d_GBO);
    float *AF = gsym(d_AF), *BF = gsym(d_BF), *ABc = gsym(d_ABc), *BBc = gsym(d_BBc),
          *SF = gsym(d_SF), *SB = gsym(d_SB);

    bf16 *SEQ16 = gsym16(d_SEQ16), *U16 = gsym16(d_U16), *YF16 = gsym16(d_YF16),
         *YB16 = gsym16(d_YB16), *Y16 = gsym16(d_Y16), *YG16 = gsym16(d_YG16),
         *V16 = gsym16(d_V16), *Z16 = gsym16(d_Z16), *UO16 = gsym16(d_UO16),
         *CS16 = gsym16(d_CS16), *SEQG16 = gsym16(d_SEQG16), *UG16 = gsym16(d_UG16);
    bf16 *W16 = gsym16(d_W16);

    dim3 tb(32, 8);
    dim3 gF(2, M_FINE / 64);
    dim3 gG(2, M_GLOB / 64);
    dim3 gF3(6, M_FINE / 64);
    dim3 gG3(6, M_GLOB / 64);

    k_wcvt<<<(OW_TOT + 1023) / 1024, 256>>>(Wt, Wf, Ww_, Wo, Wr, Wgi, Wl, Wlf, Wout, W16);

    // ---- fine sequence ----
    k_transpose16<<<dim3(NN / 32, CH / 32, BSZ), tb>>>(x, SEQ16, CH, NN);
    k_pos_embed<<<NN, 256>>>(posf, PF, HH, WW);
    k_pos_embed<<<NG, 256>>>(posg, PG, GH, GH);

    // u = seq @ Wt + bt + pos
    k_gemm_f<<<gF, 256>>>(SEQ16, nullptr, nullptr, W16 + OW_Wt, bt, nullptr, nullptr, PF,
                          U, U16, nullptr, nullptr, 1, 0, NN);

    k_colsum<<<dim3(32, BSZ), 256>>>(U, PART, NN, 128, 32);
    k_ln_ctx<<<BSZ, 256>>>(PART, 32, 1.f / NN, lng, lnb, CBAR);
    k_gate_bias<<<BSZ, 256>>>(CBAR, Wf + 256 * 256, bf, GBF);
    k_gate_bias<<<BSZ, 256>>>(CBAR, Ww_ + 256 * 256, bw, GBW);
    k_gate_bias<<<BSZ, 256>>>(CBAR, Wo + 256 * 256, bo, GBO);

    k_gates3<<<gF3, 256>>>(U16, W16 + OW_Wf, GBF, GBW, GBO, GA, GW, GO, NN);

    k_scan_pass1<<<dim3(NCHUNK, BSZ), 256>>>(GA, GW, U, AF, BF, ABc, BBc, NN, NCHUNK);
    k_scan_pass2<<<BSZ, 256>>>(AF, BF, ABc, BBc, SF, SB, NCHUNK);
    k_scan_pass3<<<dim3(NCHUNK, BSZ), 256>>>(GA, GW, GO, U, SF, SB,
                                             nullptr, nullptr, YF16, YB16, NN, NCHUNK);

    // rho: Y16 = sig(t)*YF + (1-sig)*YB
    k_gemm_f<<<gF, 256>>>(U16, YF16, YB16, W16 + OW_Wr, br, YF16, YB16, nullptr,
                          nullptr, Y16, nullptr, nullptr, 3, 1, NN);

    // ---- global branch ----
    k_pool<<<(BSZ * CH * NG + 255) / 256, 256>>>(x, XG);
    k_transpose16<<<dim3(NG / 32, CH / 32, BSZ), tb>>>(XG, SEQG16, CH, NG);
    k_gemm_f<<<gG, 256>>>(SEQG16, nullptr, nullptr, W16 + OW_Wt, bt, nullptr, nullptr, PG,
                          UG, UG16, nullptr, nullptr, 1, 0, NG);

    k_colsum<<<dim3(2, BSZ), 256>>>(UG, PART, NG, 128, 2);
    k_ln_ctx<<<BSZ, 256>>>(PART, 2, 1.f / NG, lng, lnb, CBAR);
    k_gate_bias<<<BSZ, 256>>>(CBAR, Wf + 256 * 256, bf, GBF);
    k_gate_bias<<<BSZ, 256>>>(CBAR, Ww_ + 256 * 256, bw, GBW);
    k_gate_bias<<<BSZ, 256>>>(CBAR, Wo + 256 * 256, bo, GBO);

    k_gates3<<<gG3, 256>>>(UG16, W16 + OW_Wf, GBF, GBW, GBO, AG, BG, OG, NG);

    k_scan_pass1<<<dim3(NCHUNK_G, BSZ), 256>>>(AG, BG, UG, AF, BF, ABc, BBc, NG, NCHUNK_G);
    k_scan_pass2<<<BSZ, 256>>>(AF, BF, ABc, BBc, SF, SB, NCHUNK_G);
    k_scan_pass3<<<dim3(NCHUNK_G, BSZ), 256>>>(AG, BG, OG, UG, SF, SB,
                                               YGS, YGB, nullptr, nullptr, NG, NCHUNK_G);

    k_upsample<<<dim3(NN, BSZ), 256>>>(YGS, YG16);

    // lam: Z16 = Y + sig(t)*YG
    k_gemm_f<<<gF, 256>>>(Y16, YG16, U16, W16 + OW_Wgi, bgi, Y16, YG16, nullptr,
                          nullptr, Z16, nullptr, nullptr, 3, 2, NN);

    // ---- local depthwise conv branch ----
    k_dwconv_t<<<dim3(8, 64, 8), 256>>>(x, dww, dwb, CS16);
    // v
    k_gemm_f<<<gF, 256>>>(CS16, nullptr, nullptr, W16 + OW_Wl, bl, nullptr, nullptr, nullptr,
                          nullptr, V16, nullptr, nullptr, 1, 0, NN);
    // eta: UO16 = sig(t)*v + (1-sig)*z
    k_gemm_f<<<gF, 256>>>(V16, Z16, nullptr, W16 + OW_Wlf, blf, V16, Z16, nullptr,
                          nullptr, UO16, nullptr, nullptr, 2, 1, NN);
    // out projection + residual, direct [b][c][n] write
    k_gemm_f<<<gF, 256>>>(UO16, nullptr, nullptr, W16 + OW_Wout, bout, nullptr, nullptr, nullptr,
                          nullptr, nullptr, x, out, 1, 3, NN);
}